// round 2
// baseline (speedup 1.0000x reference)
#include <cuda_runtime.h>
#include <math.h>

#define B_ROWS 16384
#define NSP 26
#define ND 13
#define VOCAB 100000
#define EMB_D 16
#define F0 29
#define H1 256
#define H2 128
#define H3 64
#define BN_EPS 1e-5f

// Scratch (no allocations allowed -> device globals)
__device__ float g_xbuf[B_ROWS * 32];   // [B][32]: cols 0..15 cross, 16..28 dense, 29..31 zero
__device__ float g_bnscale[32];
__device__ float g_bnshift[32];
__device__ int   g_idx64;

// ---------------------------------------------------------------------------
// Detect whether x_sparse is int64 or int32.
// If int64 (values in [0, 100000)), every odd 32-bit word (high half) is 0.
// If int32, odd words are uniform vocab ids; P(32 of them all zero) ~ 1e-160.
// ---------------------------------------------------------------------------
__global__ void detect_idx_kernel(const int* __restrict__ xs_i32) {
    if (threadIdx.x == 0) {
        int all0 = 1;
        for (int i = 1; i < 64; i += 2)
            if (xs_i32[i] != 0) { all0 = 0; break; }
        g_idx64 = all0;
    }
}

// ---------------------------------------------------------------------------
// Gather + FM cross. 4 threads per row; thread q owns 16B slice q of the 64B
// embedding row (lanes 0..3 of a quad coalesce into one 64B segment).
// ---------------------------------------------------------------------------
__global__ void gather_cross_kernel(const void* __restrict__ xsparse,
                                    const float* __restrict__ xdense,
                                    const float* __restrict__ emb) {
    int tid = blockIdx.x * blockDim.x + threadIdx.x;
    int r = tid >> 2;
    int q = tid & 3;
    if (r >= B_ROWS) return;

    const long long* xs64 = (const long long*)xsparse;
    const int*       xs32 = (const int*)xsparse;
    const bool is64 = (g_idx64 != 0);

    float s0 = 0.f, s1 = 0.f, s2 = 0.f, s3 = 0.f;
    float q0 = 0.f, q1 = 0.f, q2 = 0.f, q3 = 0.f;

#pragma unroll
    for (int f = 0; f < NSP; f++) {
        long long idx = is64 ? xs64[r * NSP + f] : (long long)xs32[r * NSP + f];
        const float4 v = *(const float4*)(emb +
            ((size_t)f * VOCAB + (size_t)idx) * EMB_D + q * 4);
        s0 += v.x; s1 += v.y; s2 += v.z; s3 += v.w;
        q0 += v.x * v.x; q1 += v.y * v.y; q2 += v.z * v.z; q3 += v.w * v.w;
    }

    float4 cr;
    cr.x = 0.5f * (s0 * s0 - q0);
    cr.y = 0.5f * (s1 * s1 - q1);
    cr.z = 0.5f * (s2 * s2 - q2);
    cr.w = 0.5f * (s3 * s3 - q3);
    *(float4*)&g_xbuf[r * 32 + q * 4] = cr;

    // dense cols 16..28, pad 29..31 with zeros. thread q fills cols 16+4q..19+4q
    int base = q * 4;  // dense index base
    float4 dv;
    dv.x = (base + 0 < ND) ? xdense[r * ND + base + 0] : 0.f;
    dv.y = (base + 1 < ND) ? xdense[r * ND + base + 1] : 0.f;
    dv.z = (base + 2 < ND) ? xdense[r * ND + base + 2] : 0.f;
    dv.w = (base + 3 < ND) ? xdense[r * ND + base + 3] : 0.f;
    *(float4*)&g_xbuf[r * 32 + 16 + q * 4] = dv;
}

// ---------------------------------------------------------------------------
// BatchNorm stats (training mode, biased var). One block per feature column.
// Fixed-order tree reduction -> deterministic.
// ---------------------------------------------------------------------------
__global__ void bn_stats_kernel(const float* __restrict__ gamma,
                                const float* __restrict__ beta) {
    int c = blockIdx.x;
    int t = threadIdx.x;
    float sum = 0.f, sq = 0.f;
    for (int r = t; r < B_ROWS; r += 256) {
        float v = g_xbuf[r * 32 + c];
        sum += v;
        sq += v * v;
    }
    __shared__ float ssum[256], ssq[256];
    ssum[t] = sum; ssq[t] = sq;
    __syncthreads();
    for (int s = 128; s > 0; s >>= 1) {
        if (t < s) { ssum[t] += ssum[t + s]; ssq[t] += ssq[t + s]; }
        __syncthreads();
    }
    if (t == 0) {
        float mean = ssum[0] * (1.0f / B_ROWS);
        float var  = ssq[0] * (1.0f / B_ROWS) - mean * mean;
        float sc   = gamma[c] * rsqrtf(var + BN_EPS);
        g_bnscale[c] = sc;
        g_bnshift[c] = beta[c] - mean * sc;
    }
}

// ---------------------------------------------------------------------------
// Fused BN + MLP. Persistent CTAs, all weights staged in SMEM, 8 rows per
// tile with per-thread accumulators (weight LDS amortized across rows).
// ---------------------------------------------------------------------------
// SMEM float layout:
#define OFF_W1   0                      // 32*256  (k padded 29->32, zeros)
#define OFF_B1   (OFF_W1 + 32 * 256)    // 256
#define OFF_W2   (OFF_B1 + 256)         // 256*128
#define OFF_B2   (OFF_W2 + 256 * 128)   // 128
#define OFF_W3   (OFF_B2 + 128)         // 128*64
#define OFF_B3   (OFF_W3 + 128 * 64)    // 64
#define OFF_WF   (OFF_B3 + 64)          // 64
#define OFF_SC   (OFF_WF + 64)          // 32
#define OFF_SH   (OFF_SC + 32)          // 32
#define OFF_XS   (OFF_SH + 32)          // 8*32
#define OFF_H1   (OFF_XS + 8 * 32)      // 8*256
#define OFF_H2   (OFF_H1 + 8 * 256)     // 8*128
#define OFF_H3   (OFF_H2 + 8 * 128)     // 8*64
#define SMEM_FLOATS (OFF_H3 + 8 * 64)
#define SMEM_BYTES  (SMEM_FLOATS * 4)

__global__ void __launch_bounds__(256, 1)
mlp_kernel(const float* __restrict__ W1, const float* __restrict__ b1,
           const float* __restrict__ W2, const float* __restrict__ b2,
           const float* __restrict__ W3, const float* __restrict__ b3,
           const float* __restrict__ Wf, const float* __restrict__ bf,
           float* __restrict__ out) {
    extern __shared__ float sm[];
    float* sW1 = sm + OFF_W1;
    float* sB1 = sm + OFF_B1;
    float* sW2 = sm + OFF_W2;
    float* sB2 = sm + OFF_B2;
    float* sW3 = sm + OFF_W3;
    float* sB3 = sm + OFF_B3;
    float* sWF = sm + OFF_WF;
    float* sSC = sm + OFF_SC;
    float* sSH = sm + OFF_SH;
    float* xs  = sm + OFF_XS;
    float* h1  = sm + OFF_H1;
    float* h2  = sm + OFF_H2;
    float* h3  = sm + OFF_H3;

    const int tid = threadIdx.x;

    // ---- stage weights ----
    for (int i = tid; i < 32 * 256; i += 256) {
        int k = i >> 8;
        sW1[i] = (k < F0) ? W1[k * 256 + (i & 255)] : 0.f;
    }
    sB1[tid] = b1[tid];
    for (int i = tid; i < 256 * 128; i += 256) sW2[i] = W2[i];
    if (tid < 128) sB2[tid] = b2[tid];
    for (int i = tid; i < 128 * 64; i += 256) sW3[i] = W3[i];
    if (tid < 64) sB3[tid] = b3[tid];
    if (tid < 64) sWF[tid] = Wf[tid];
    if (tid < 32) {
        sSC[tid] = (tid < F0) ? g_bnscale[tid] : 0.f;
        sSH[tid] = (tid < F0) ? g_bnshift[tid] : 0.f;
    }
    const float bfv = bf[0];
    __syncthreads();

    // ---- row tiles of 8 ----
    for (int t = blockIdx.x; t < B_ROWS / 8; t += gridDim.x) {
        const int r0 = t * 8;

        // load + BN-normalize 8 rows into xs[8][32]
        {
            int row = tid >> 5, col = tid & 31;
            float v = g_xbuf[(r0 + row) * 32 + col];
            xs[row * 32 + col] = (col < F0) ? (v * sSC[col] + sSH[col]) : 0.f;
        }
        __syncthreads();

        // layer 1: 256 neurons, 8 rows per thread
        {
            const int n = tid;
            float acc[8];
#pragma unroll
            for (int r = 0; r < 8; r++) acc[r] = sB1[n];
#pragma unroll
            for (int k = 0; k < 32; k += 4) {
                float w0 = sW1[(k + 0) * 256 + n];
                float w1 = sW1[(k + 1) * 256 + n];
                float w2 = sW1[(k + 2) * 256 + n];
                float w3 = sW1[(k + 3) * 256 + n];
#pragma unroll
                for (int r = 0; r < 8; r++) {
                    float4 xv = *(const float4*)&xs[r * 32 + k];
                    acc[r] += xv.x * w0 + xv.y * w1 + xv.z * w2 + xv.w * w3;
                }
            }
#pragma unroll
            for (int r = 0; r < 8; r++) h1[r * 256 + n] = fmaxf(acc[r], 0.f);
        }
        __syncthreads();

        // layer 2: 128 neurons x 2 row-groups of 4
        {
            const int n = tid & 127;
            const int g = tid >> 7;
            float acc[4];
#pragma unroll
            for (int r = 0; r < 4; r++) acc[r] = sB2[n];
            for (int k = 0; k < 256; k += 4) {
                float w0 = sW2[(k + 0) * 128 + n];
                float w1 = sW2[(k + 1) * 128 + n];
                float w2 = sW2[(k + 2) * 128 + n];
                float w3 = sW2[(k + 3) * 128 + n];
#pragma unroll
                for (int r = 0; r < 4; r++) {
                    float4 hv = *(const float4*)&h1[(g * 4 + r) * 256 + k];
                    acc[r] += hv.x * w0 + hv.y * w1 + hv.z * w2 + hv.w * w3;
                }
            }
#pragma unroll
            for (int r = 0; r < 4; r++)
                h2[(g * 4 + r) * 128 + n] = fmaxf(acc[r], 0.f);
        }
        __syncthreads();

        // layer 3: 64 neurons x 4 row-groups of 2
        {
            const int n = tid & 63;
            const int g = tid >> 6;
            float acc[2];
#pragma unroll
            for (int r = 0; r < 2; r++) acc[r] = sB3[n];
#pragma unroll
            for (int k = 0; k < 128; k += 4) {
                float w0 = sW3[(k + 0) * 64 + n];
                float w1 = sW3[(k + 1) * 64 + n];
                float w2 = sW3[(k + 2) * 64 + n];
                float w3 = sW3[(k + 3) * 64 + n];
#pragma unroll
                for (int r = 0; r < 2; r++) {
                    float4 hv = *(const float4*)&h2[(g * 2 + r) * 128 + k];
                    acc[r] += hv.x * w0 + hv.y * w1 + hv.z * w2 + hv.w * w3;
                }
            }
#pragma unroll
            for (int r = 0; r < 2; r++)
                h3[(g * 2 + r) * 64 + n] = fmaxf(acc[r], 0.f);
        }
        __syncthreads();

        // final: warp w reduces row w
        {
            const int w = tid >> 5, l = tid & 31;
            float p = h3[w * 64 + l] * sWF[l] + h3[w * 64 + 32 + l] * sWF[32 + l];
#pragma unroll
            for (int s = 16; s > 0; s >>= 1)
                p += __shfl_xor_sync(0xffffffffu, p, s);
            if (l == 0) {
                float z = p + bfv;
                out[r0 + w] = 1.f / (1.f + __expf(-z));
            }
        }
        __syncthreads();
    }
}

// ---------------------------------------------------------------------------
extern "C" void kernel_launch(void* const* d_in, const int* in_sizes, int n_in,
                              void* d_out, int out_size) {
    const float* x_dense = (const float*)d_in[0];
    const void*  x_sparse = d_in[1];
    const float* emb   = (const float*)d_in[2];
    const float* gamma = (const float*)d_in[3];
    const float* beta  = (const float*)d_in[4];
    const float* W1 = (const float*)d_in[5];
    const float* b1 = (const float*)d_in[6];
    const float* W2 = (const float*)d_in[7];
    const float* b2 = (const float*)d_in[8];
    const float* W3 = (const float*)d_in[9];
    const float* b3 = (const float*)d_in[10];
    const float* Wf = (const float*)d_in[11];
    const float* bf = (const float*)d_in[12];
    float* out = (float*)d_out;

    // One-time opt-in for >48KB dynamic SMEM (non-stream call; capture-safe).
    static bool s_attr_done = false;
    if (!s_attr_done) {
        cudaFuncSetAttribute(mlp_kernel,
                             cudaFuncAttributeMaxDynamicSharedMemorySize,
                             SMEM_BYTES);
        s_attr_done = true;
    }

    detect_idx_kernel<<<1, 32>>>((const int*)x_sparse);
    gather_cross_kernel<<<(B_ROWS * 4) / 256, 256>>>(x_sparse, x_dense, emb);
    bn_stats_kernel<<<F0, 256>>>(gamma, beta);
    mlp_kernel<<<148, 256, SMEM_BYTES>>>(W1, b1, W2, b2, W3, b3, Wf, bf, out);
}

// round 3
// speedup vs baseline: 1.1169x; 1.1169x over previous
#include <cuda_runtime.h>
#include <math.h>

#define B_ROWS 16384
#define NSP 26
#define ND 13
#define VOCAB 100000
#define EMB_D 16
#define F0 29
#define H1 256
#define H2 128
#define H3 64
#define BN_EPS 1e-5f

#define TILE 16            // rows per CTA tile
#define NTHR 512

// Scratch (no allocations allowed -> device globals)
__device__ float g_xbuf[B_ROWS * 32];   // [B][32]: 0..15 cross, 16..28 dense, 29..31 zero
__device__ float g_bnscale[32];
__device__ float g_bnshift[32];
__device__ int   g_idx64;

// ---------------------------------------------------------------------------
__global__ void detect_idx_kernel(const int* __restrict__ xs_i32) {
    if (threadIdx.x == 0) {
        int all0 = 1;
        for (int i = 1; i < 64; i += 2)
            if (xs_i32[i] != 0) { all0 = 0; break; }
        g_idx64 = all0;
    }
}

// ---------------------------------------------------------------------------
// Gather + FM cross. 4 threads per row; thread q owns 16B slice q of the 64B
// embedding row.
// ---------------------------------------------------------------------------
__global__ void gather_cross_kernel(const void* __restrict__ xsparse,
                                    const float* __restrict__ xdense,
                                    const float* __restrict__ emb) {
    int tid = blockIdx.x * blockDim.x + threadIdx.x;
    int r = tid >> 2;
    int q = tid & 3;
    if (r >= B_ROWS) return;

    const long long* xs64 = (const long long*)xsparse;
    const int*       xs32 = (const int*)xsparse;
    const bool is64 = (g_idx64 != 0);

    float s0 = 0.f, s1 = 0.f, s2 = 0.f, s3 = 0.f;
    float q0 = 0.f, q1 = 0.f, q2 = 0.f, q3 = 0.f;

#pragma unroll
    for (int f = 0; f < NSP; f++) {
        long long idx = is64 ? xs64[r * NSP + f] : (long long)xs32[r * NSP + f];
        const float4 v = *(const float4*)(emb +
            ((size_t)f * VOCAB + (size_t)idx) * EMB_D + q * 4);
        s0 += v.x; s1 += v.y; s2 += v.z; s3 += v.w;
        q0 += v.x * v.x; q1 += v.y * v.y; q2 += v.z * v.z; q3 += v.w * v.w;
    }

    float4 cr;
    cr.x = 0.5f * (s0 * s0 - q0);
    cr.y = 0.5f * (s1 * s1 - q1);
    cr.z = 0.5f * (s2 * s2 - q2);
    cr.w = 0.5f * (s3 * s3 - q3);
    *(float4*)&g_xbuf[r * 32 + q * 4] = cr;

    int base = q * 4;
    float4 dv;
    dv.x = (base + 0 < ND) ? xdense[r * ND + base + 0] : 0.f;
    dv.y = (base + 1 < ND) ? xdense[r * ND + base + 1] : 0.f;
    dv.z = (base + 2 < ND) ? xdense[r * ND + base + 2] : 0.f;
    dv.w = (base + 3 < ND) ? xdense[r * ND + base + 3] : 0.f;
    *(float4*)&g_xbuf[r * 32 + 16 + q * 4] = dv;
}

// ---------------------------------------------------------------------------
__global__ void bn_stats_kernel(const float* __restrict__ gamma,
                                const float* __restrict__ beta) {
    int c = blockIdx.x;
    int t = threadIdx.x;
    float sum = 0.f, sq = 0.f;
    for (int r = t; r < B_ROWS; r += 256) {
        float v = g_xbuf[r * 32 + c];
        sum += v;
        sq += v * v;
    }
    __shared__ float ssum[256], ssq[256];
    ssum[t] = sum; ssq[t] = sq;
    __syncthreads();
    for (int s = 128; s > 0; s >>= 1) {
        if (t < s) { ssum[t] += ssum[t + s]; ssq[t] += ssq[t + s]; }
        __syncthreads();
    }
    if (t == 0) {
        float mean = ssum[0] * (1.0f / B_ROWS);
        float var  = ssq[0] * (1.0f / B_ROWS) - mean * mean;
        float sc   = gamma[c] * rsqrtf(var + BN_EPS);
        g_bnscale[c] = sc;
        g_bnshift[c] = beta[c] - mean * sc;
    }
}

// ---------------------------------------------------------------------------
// Fused BN + MLP. 512 thr, 16-row tiles. W1/b1 live in registers (one layer-1
// neuron per thread). W2/W3 staged in SMEM in [k/4][n][4] layout so each
// 4-k weight chunk is one conflict-free LDS.128.
// ---------------------------------------------------------------------------
// SMEM float layout:
#define OFF_W2   0                        // 64*128*4 = 32768  ([kc][n][4])
#define OFF_W3   (OFF_W2 + 32768)         // 32*64*4  = 8192   ([kc][n][4])
#define OFF_B2   (OFF_W3 + 8192)          // 128
#define OFF_B3   (OFF_B2 + 128)           // 64
#define OFF_WF   (OFF_B3 + 64)            // 64
#define OFF_SC   (OFF_WF + 64)            // 32
#define OFF_SH   (OFF_SC + 32)            // 32
#define OFF_XS   (OFF_SH + 32)            // TILE*32  = 512
#define OFF_H1   (OFF_XS + TILE * 32)     // TILE*256 = 4096
#define OFF_H2   (OFF_H1 + TILE * 256)    // TILE*128 = 2048
#define OFF_H3   (OFF_H2 + TILE * 128)    // TILE*64  = 1024
#define SMEM_FLOATS (OFF_H3 + TILE * 64)
#define SMEM_BYTES  (SMEM_FLOATS * 4)

__global__ void __launch_bounds__(NTHR, 1)
mlp_kernel(const float* __restrict__ W1, const float* __restrict__ b1,
           const float* __restrict__ W2, const float* __restrict__ b2,
           const float* __restrict__ W3, const float* __restrict__ b3,
           const float* __restrict__ Wf, const float* __restrict__ bf,
           float* __restrict__ out) {
    extern __shared__ float sm[];
    float* sW2 = sm + OFF_W2;
    float* sW3 = sm + OFF_W3;
    float* sB2 = sm + OFF_B2;
    float* sB3 = sm + OFF_B3;
    float* sWF = sm + OFF_WF;
    float* sSC = sm + OFF_SC;
    float* sSH = sm + OFF_SH;
    float* xs  = sm + OFF_XS;
    float* h1  = sm + OFF_H1;
    float* h2  = sm + OFF_H2;
    float* h3  = sm + OFF_H3;

    const int tid = threadIdx.x;

    // ---- stage W2/W3 into vectorizable layout ----
    for (int i = tid; i < 256 * 128; i += NTHR) {
        int k = i >> 7, n = i & 127;
        sW2[(k >> 2) * 512 + n * 4 + (k & 3)] = W2[i];
    }
    for (int i = tid; i < 128 * 64; i += NTHR) {
        int k = i >> 6, n = i & 63;
        sW3[(k >> 2) * 256 + n * 4 + (k & 3)] = W3[i];
    }
    if (tid < 128) sB2[tid] = b2[tid];
    if (tid < 64)  sB3[tid] = b3[tid];
    if (tid < 64)  sWF[tid] = Wf[tid];
    if (tid < 32) {
        sSC[tid] = (tid < F0) ? g_bnscale[tid] : 0.f;
        sSH[tid] = (tid < F0) ? g_bnshift[tid] : 0.f;
    }
    const float bfv = bf[0];

    // ---- W1 column for this thread's layer-1 neuron -> registers ----
    const int n1 = tid & 255;                 // layer-1 neuron
    float4 w1v[8];
#pragma unroll
    for (int kc = 0; kc < 8; kc++) {
        w1v[kc].x = (4 * kc + 0 < F0) ? W1[(4 * kc + 0) * 256 + n1] : 0.f;
        w1v[kc].y = (4 * kc + 1 < F0) ? W1[(4 * kc + 1) * 256 + n1] : 0.f;
        w1v[kc].z = (4 * kc + 2 < F0) ? W1[(4 * kc + 2) * 256 + n1] : 0.f;
        w1v[kc].w = (4 * kc + 3 < F0) ? W1[(4 * kc + 3) * 256 + n1] : 0.f;
    }
    const float b1r = b1[n1];
    __syncthreads();

    // ---- row tiles of 16 ----
    for (int t = blockIdx.x; t < B_ROWS / TILE; t += gridDim.x) {
        const int r0 = t * TILE;

        // load + BN-normalize 16 rows into xs[16][32] (1 elem/thread)
        {
            int row = tid >> 5, col = tid & 31;
            float v = g_xbuf[(r0 + row) * 32 + col];
            xs[row * 32 + col] = (col < F0) ? (v * sSC[col] + sSH[col]) : 0.f;
        }
        __syncthreads();

        // layer 1: 2 groups x 256 neurons, 8 rows each; weights in regs
        {
            const int g = tid >> 8;          // 0..1
            const float* xbase = xs + g * 8 * 32;
            float acc[8];
#pragma unroll
            for (int r = 0; r < 8; r++) acc[r] = b1r;
#pragma unroll
            for (int kc = 0; kc < 8; kc++) {
                const float4 w = w1v[kc];
#pragma unroll
                for (int r = 0; r < 8; r++) {
                    float4 xv = *(const float4*)&xbase[r * 32 + kc * 4];
                    acc[r] += xv.x * w.x + xv.y * w.y + xv.z * w.z + xv.w * w.w;
                }
            }
#pragma unroll
            for (int r = 0; r < 8; r++)
                h1[(g * 8 + r) * 256 + n1] = fmaxf(acc[r], 0.f);
        }
        __syncthreads();

        // layer 2: 4 groups x 128 neurons, 4 rows each; float4 weight loads
        {
            const int n = tid & 127;
            const int g = tid >> 7;          // 0..3
            const float* hbase = h1 + g * 4 * 256;
            float acc[4];
#pragma unroll
            for (int r = 0; r < 4; r++) acc[r] = sB2[n];
#pragma unroll 8
            for (int kc = 0; kc < 64; kc++) {
                float4 w = *(const float4*)&sW2[kc * 512 + n * 4];
#pragma unroll
                for (int r = 0; r < 4; r++) {
                    float4 hv = *(const float4*)&hbase[r * 256 + kc * 4];
                    acc[r] += hv.x * w.x + hv.y * w.y + hv.z * w.z + hv.w * w.w;
                }
            }
#pragma unroll
            for (int r = 0; r < 4; r++)
                h2[(g * 4 + r) * 128 + n] = fmaxf(acc[r], 0.f);
        }
        __syncthreads();

        // layer 3: 8 groups x 64 neurons, 2 rows each
        {
            const int n = tid & 63;
            const int g = tid >> 6;          // 0..7
            const float* hbase = h2 + g * 2 * 128;
            float acc[2];
#pragma unroll
            for (int r = 0; r < 2; r++) acc[r] = sB3[n];
#pragma unroll 8
            for (int kc = 0; kc < 32; kc++) {
                float4 w = *(const float4*)&sW3[kc * 256 + n * 4];
#pragma unroll
                for (int r = 0; r < 2; r++) {
                    float4 hv = *(const float4*)&hbase[r * 128 + kc * 4];
                    acc[r] += hv.x * w.x + hv.y * w.y + hv.z * w.z + hv.w * w.w;
                }
            }
#pragma unroll
            for (int r = 0; r < 2; r++)
                h3[(g * 2 + r) * 64 + n] = fmaxf(acc[r], 0.f);
        }
        __syncthreads();

        // final: warp w reduces row w (16 warps x 16 rows)
        {
            const int w = tid >> 5, l = tid & 31;
            float p = h3[w * 64 + l] * sWF[l] + h3[w * 64 + 32 + l] * sWF[32 + l];
#pragma unroll
            for (int s = 16; s > 0; s >>= 1)
                p += __shfl_xor_sync(0xffffffffu, p, s);
            if (l == 0) {
                float z = p + bfv;
                out[r0 + w] = 1.f / (1.f + __expf(-z));
            }
        }
        __syncthreads();
    }
}

// ---------------------------------------------------------------------------
extern "C" void kernel_launch(void* const* d_in, const int* in_sizes, int n_in,
                              void* d_out, int out_size) {
    const float* x_dense = (const float*)d_in[0];
    const void*  x_sparse = d_in[1];
    const float* emb   = (const float*)d_in[2];
    const float* gamma = (const float*)d_in[3];
    const float* beta  = (const float*)d_in[4];
    const float* W1 = (const float*)d_in[5];
    const float* b1 = (const float*)d_in[6];
    const float* W2 = (const float*)d_in[7];
    const float* b2 = (const float*)d_in[8];
    const float* W3 = (const float*)d_in[9];
    const float* b3 = (const float*)d_in[10];
    const float* Wf = (const float*)d_in[11];
    const float* bf = (const float*)d_in[12];
    float* out = (float*)d_out;

    static bool s_attr_done = false;
    if (!s_attr_done) {
        cudaFuncSetAttribute(mlp_kernel,
                             cudaFuncAttributeMaxDynamicSharedMemorySize,
                             SMEM_BYTES);
        s_attr_done = true;
    }

    detect_idx_kernel<<<1, 32>>>((const int*)x_sparse);
    gather_cross_kernel<<<(B_ROWS * 4) / 256, 256>>>(x_sparse, x_dense, emb);
    bn_stats_kernel<<<F0, 256>>>(gamma, beta);
    mlp_kernel<<<148, NTHR, SMEM_BYTES>>>(W1, b1, W2, b2, W3, b3, Wf, bf, out);
}

// round 6
// speedup vs baseline: 1.5620x; 1.3985x over previous
#include <cuda_runtime.h>
#include <cuda_bf16.h>
#include <math.h>
#include <stdint.h>

#define B_ROWS 16384
#define NSP 26
#define ND 13
#define VOCAB 100000
#define EMB_D 16
#define F0 29
#define BN_EPS 1e-5f

// ---------------------------------------------------------------------------
// Device scratch
// ---------------------------------------------------------------------------
__device__ float g_xbuf[B_ROWS * 32];   // [B][32]: 0..15 cross, 16..28 dense, 29..31 zero
__device__ float g_bnscale[32];         // cols 29..31 stay 0
__device__ float g_bnshift[32];
__device__ int   g_idx64;

// Fragment-ordered bf16x2-packed weights (built by prep kernel):
// wf1: [s(6)][nt(32)][lane(32)][reg(2)]   s: (Ahi,Whi k0),(Ahi,Whi k1),(Ahi,Wlo k0),(Ahi,Wlo k1),(Alo,Whi k0),(Alo,Whi k1)
// wf2: [cs(48)=chunk*6+s][nt(16)][lane][reg]
// wf3: [s(24)=pass*8+kt][nt(8)][lane][reg]
__device__ uint32_t g_wf1[12288];
__device__ uint32_t g_wf2[49152];
__device__ uint32_t g_wf3[12288];

// Intermediate activations, bf16 hi/lo parts
__device__ __nv_bfloat16 g_h1hi[B_ROWS * 256];
__device__ __nv_bfloat16 g_h1lo[B_ROWS * 256];
__device__ __nv_bfloat16 g_h2hi[B_ROWS * 128];
__device__ __nv_bfloat16 g_h2lo[B_ROWS * 128];

// ---------------------------------------------------------------------------
__device__ __forceinline__ void mma_bf16(float* c, uint32_t a0, uint32_t a1,
                                         uint32_t a2, uint32_t a3,
                                         uint32_t b0, uint32_t b1) {
    asm volatile(
        "mma.sync.aligned.m16n8k16.row.col.f32.bf16.bf16.f32 "
        "{%0,%1,%2,%3}, {%4,%5,%6,%7}, {%8,%9}, {%0,%1,%2,%3};"
        : "+f"(c[0]), "+f"(c[1]), "+f"(c[2]), "+f"(c[3])
        : "r"(a0), "r"(a1), "r"(a2), "r"(a3), "r"(b0), "r"(b1));
}

__device__ __forceinline__ void split_pack(float h0, float h1,
                                           uint32_t& hi, uint32_t& lo) {
    __nv_bfloat16 b0 = __float2bfloat16(h0);
    __nv_bfloat16 b1 = __float2bfloat16(h1);
    float r0 = h0 - __bfloat162float(b0);
    float r1 = h1 - __bfloat162float(b1);
    __nv_bfloat16 c0 = __float2bfloat16(r0);
    __nv_bfloat16 c1 = __float2bfloat16(r1);
    hi = ((uint32_t)__bfloat16_as_ushort(b1) << 16) | (uint32_t)__bfloat16_as_ushort(b0);
    lo = ((uint32_t)__bfloat16_as_ushort(c1) << 16) | (uint32_t)__bfloat16_as_ushort(c0);
}

__device__ __forceinline__ unsigned short wpart_bf16(float w, bool lo_part) {
    __nv_bfloat16 h = __float2bfloat16(w);
    if (!lo_part) return __bfloat16_as_ushort(h);
    return __bfloat16_as_ushort(__float2bfloat16(w - __bfloat162float(h)));
}

// ---------------------------------------------------------------------------
__global__ void detect_idx_kernel(const int* __restrict__ xs_i32) {
    if (threadIdx.x == 0) {
        int all0 = 1;
        for (int i = 1; i < 64; i += 2)
            if (xs_i32[i] != 0) { all0 = 0; break; }
        g_idx64 = all0;
    }
}

// ---------------------------------------------------------------------------
// prep: build fragment-ordered split weights.
// mma B frag: reg r holds B[k0][n], B[k0+1][n]; k0 = ktile*16 + (lane&3)*2 + r*8,
// n = ntile*8 + (lane>>2). Packed low = k0.
// ---------------------------------------------------------------------------
__global__ void prep_weights_kernel(const float* __restrict__ W1,
                                    const float* __restrict__ W2,
                                    const float* __restrict__ W3) {
    int e = blockIdx.x * blockDim.x + threadIdx.x;
    if (e >= 73728) return;
    if (e < 12288) {                       // layer 1: K=32(pad from 29), N=256
        int r = e & 1, lane = (e >> 1) & 31, nt = (e >> 6) & 31, s = e >> 11;
        bool wlo = (s == 2 || s == 3);
        int kt = s & 1;
        int k = kt * 16 + (lane & 3) * 2 + r * 8;
        int n = nt * 8 + (lane >> 2);
        float w0 = (k < F0)     ? W1[k * 256 + n]       : 0.f;
        float w1 = (k + 1 < F0) ? W1[(k + 1) * 256 + n] : 0.f;
        g_wf1[e] = ((uint32_t)wpart_bf16(w1, wlo) << 16) | wpart_bf16(w0, wlo);
    } else if (e < 61440) {                // layer 2: K=256, N=128
        int e2 = e - 12288;
        int r = e2 & 1, lane = (e2 >> 1) & 31, nt = (e2 >> 6) & 15, cs = e2 >> 10;
        int chunk = cs / 6, s = cs % 6;
        bool wlo = (s == 2 || s == 3);
        int kt = s & 1;
        int k = chunk * 32 + kt * 16 + (lane & 3) * 2 + r * 8;
        int n = nt * 8 + (lane >> 2);
        float w0 = W2[k * 128 + n];
        float w1 = W2[(k + 1) * 128 + n];
        g_wf2[e2] = ((uint32_t)wpart_bf16(w1, wlo) << 16) | wpart_bf16(w0, wlo);
    } else {                               // layer 3: K=128, N=64
        int e3 = e - 61440;
        int r = e3 & 1, lane = (e3 >> 1) & 31, nt = (e3 >> 6) & 7, s = e3 >> 9;
        int pass = s >> 3, kt = s & 7;
        bool wlo = (pass == 1);
        int k = kt * 16 + (lane & 3) * 2 + r * 8;
        int n = nt * 8 + (lane >> 2);
        float w0 = W3[k * 64 + n];
        float w1 = W3[(k + 1) * 64 + n];
        g_wf3[e3] = ((uint32_t)wpart_bf16(w1, wlo) << 16) | wpart_bf16(w0, wlo);
    }
}

// ---------------------------------------------------------------------------
// Gather + FM cross (unchanged)
// ---------------------------------------------------------------------------
__global__ void gather_cross_kernel(const void* __restrict__ xsparse,
                                    const float* __restrict__ xdense,
                                    const float* __restrict__ emb) {
    int tid = blockIdx.x * blockDim.x + threadIdx.x;
    int r = tid >> 2;
    int q = tid & 3;
    if (r >= B_ROWS) return;

    const long long* xs64 = (const long long*)xsparse;
    const int*       xs32 = (const int*)xsparse;
    const bool is64 = (g_idx64 != 0);

    float s0 = 0.f, s1 = 0.f, s2 = 0.f, s3 = 0.f;
    float q0 = 0.f, q1 = 0.f, q2 = 0.f, q3 = 0.f;

#pragma unroll
    for (int f = 0; f < NSP; f++) {
        long long idx = is64 ? xs64[r * NSP + f] : (long long)xs32[r * NSP + f];
        const float4 v = *(const float4*)(emb +
            ((size_t)f * VOCAB + (size_t)idx) * EMB_D + q * 4);
        s0 += v.x; s1 += v.y; s2 += v.z; s3 += v.w;
        q0 += v.x * v.x; q1 += v.y * v.y; q2 += v.z * v.z; q3 += v.w * v.w;
    }

    float4 cr;
    cr.x = 0.5f * (s0 * s0 - q0);
    cr.y = 0.5f * (s1 * s1 - q1);
    cr.z = 0.5f * (s2 * s2 - q2);
    cr.w = 0.5f * (s3 * s3 - q3);
    *(float4*)&g_xbuf[r * 32 + q * 4] = cr;

    int base = q * 4;
    float4 dv;
    dv.x = (base + 0 < ND) ? xdense[r * ND + base + 0] : 0.f;
    dv.y = (base + 1 < ND) ? xdense[r * ND + base + 1] : 0.f;
    dv.z = (base + 2 < ND) ? xdense[r * ND + base + 2] : 0.f;
    dv.w = (base + 3 < ND) ? xdense[r * ND + base + 3] : 0.f;
    *(float4*)&g_xbuf[r * 32 + 16 + q * 4] = dv;
}

// ---------------------------------------------------------------------------
__global__ void bn_stats_kernel(const float* __restrict__ gamma,
                                const float* __restrict__ beta) {
    int c = blockIdx.x;
    int t = threadIdx.x;
    float sum = 0.f, sq = 0.f;
    for (int r = t; r < B_ROWS; r += 256) {
        float v = g_xbuf[r * 32 + c];
        sum += v;
        sq += v * v;
    }
    __shared__ float ssum[256], ssq[256];
    ssum[t] = sum; ssq[t] = sq;
    __syncthreads();
    for (int s = 128; s > 0; s >>= 1) {
        if (t < s) { ssum[t] += ssum[t + s]; ssq[t] += ssq[t + s]; }
        __syncthreads();
    }
    if (t == 0) {
        float mean = ssum[0] * (1.0f / B_ROWS);
        float var  = ssq[0] * (1.0f / B_ROWS) - mean * mean;
        float sc   = gamma[c] * rsqrtf(var + BN_EPS);
        g_bnscale[c] = sc;
        g_bnshift[c] = beta[c] - mean * sc;
    }
}

// ---------------------------------------------------------------------------
// gemm1: H1 = relu( BN(X)[128-tile, 32] * W1[32,256] + b1 ), split -> hi/lo.
// 512 threads = 16 warps: mg = wid&3 (32 rows, 2 mtiles), ng = wid>>2 (64 cols).
// ---------------------------------------------------------------------------
#define G1_SM_WF   0
#define G1_SM_XHI  49152
#define G1_SM_XLO  59392
#define G1_SM_B1   69632
#define G1_SMEM    70656

__global__ void __launch_bounds__(512, 1)
gemm1_kernel(const float* __restrict__ b1) {
    extern __shared__ char sm[];
    uint32_t* swf = (uint32_t*)(sm + G1_SM_WF);
    char* xhi = sm + G1_SM_XHI;
    char* xlo = sm + G1_SM_XLO;
    float* sb1 = (float*)(sm + G1_SM_B1);

    const int tid = threadIdx.x;
    const int r0 = blockIdx.x * 128;

    for (int i = tid; i < 3072; i += 512)
        ((uint4*)swf)[i] = ((const uint4*)g_wf1)[i];
    for (int i = tid; i < 256; i += 512) sb1[i] = b1[i];

    // stage X tile: BN + split (scale/shift read from global; no extra sync)
    {
        int r = tid >> 2, q = tid & 3;
        float4 v0 = *(const float4*)&g_xbuf[(r0 + r) * 32 + q * 8];
        float4 v1 = *(const float4*)&g_xbuf[(r0 + r) * 32 + q * 8 + 4];
        float4 sc0 = *(const float4*)&g_bnscale[q * 8];
        float4 sc1 = *(const float4*)&g_bnscale[q * 8 + 4];
        float4 sh0 = *(const float4*)&g_bnshift[q * 8];
        float4 sh1 = *(const float4*)&g_bnshift[q * 8 + 4];
        float x0 = v0.x * sc0.x + sh0.x, x1 = v0.y * sc0.y + sh0.y;
        float x2 = v0.z * sc0.z + sh0.z, x3 = v0.w * sc0.w + sh0.w;
        float x4 = v1.x * sc1.x + sh1.x, x5 = v1.y * sc1.y + sh1.y;
        float x6 = v1.z * sc1.z + sh1.z, x7 = v1.w * sc1.w + sh1.w;
        uint4 uh, ul;
        split_pack(x0, x1, uh.x, ul.x);
        split_pack(x2, x3, uh.y, ul.y);
        split_pack(x4, x5, uh.z, ul.z);
        split_pack(x6, x7, uh.w, ul.w);
        *(uint4*)(xhi + r * 80 + q * 16) = uh;
        *(uint4*)(xlo + r * 80 + q * 16) = ul;
    }
    __syncthreads();

    const int wid = tid >> 5, lane = tid & 31;
    const int mg = wid & 3, ng = wid >> 2;

    float acc[2][8][4];
#pragma unroll
    for (int m = 0; m < 2; m++)
#pragma unroll
        for (int n = 0; n < 8; n++)
#pragma unroll
            for (int j = 0; j < 4; j++) acc[m][n][j] = 0.f;

#pragma unroll
    for (int s = 0; s < 6; s++) {
        const char* ab = (s >= 4) ? xlo : xhi;
        int kb = (s & 1) * 32 + (lane & 3) * 4;
        uint32_t a[2][4];
#pragma unroll
        for (int mt = 0; mt < 2; mt++) {
            int rA = mg * 32 + mt * 16 + (lane >> 2);
            a[mt][0] = *(const uint32_t*)(ab + rA * 80 + kb);
            a[mt][1] = *(const uint32_t*)(ab + (rA + 8) * 80 + kb);
            a[mt][2] = *(const uint32_t*)(ab + rA * 80 + kb + 16);
            a[mt][3] = *(const uint32_t*)(ab + (rA + 8) * 80 + kb + 16);
        }
#pragma unroll
        for (int n = 0; n < 8; n++) {
            int idx = ((s * 32 + ng * 8 + n) * 32 + lane) * 2;
            uint32_t b0 = swf[idx], bv1 = swf[idx + 1];
            mma_bf16(acc[0][n], a[0][0], a[0][1], a[0][2], a[0][3], b0, bv1);
            mma_bf16(acc[1][n], a[1][0], a[1][1], a[1][2], a[1][3], b0, bv1);
        }
    }

    // epilogue: relu(+b1), split, store
#pragma unroll
    for (int mt = 0; mt < 2; mt++) {
        int row = r0 + mg * 32 + mt * 16 + (lane >> 2);
#pragma unroll
        for (int n = 0; n < 8; n++) {
            int col0 = ng * 64 + n * 8 + (lane & 3) * 2;
            float2 bb = *(const float2*)&sb1[col0];
            uint32_t hi, lo;
            float h0 = fmaxf(acc[mt][n][0] + bb.x, 0.f);
            float h1 = fmaxf(acc[mt][n][1] + bb.y, 0.f);
            split_pack(h0, h1, hi, lo);
            *(uint32_t*)&g_h1hi[row * 256 + col0] = hi;
            *(uint32_t*)&g_h1lo[row * 256 + col0] = lo;
            float h2 = fmaxf(acc[mt][n][2] + bb.x, 0.f);
            float h3 = fmaxf(acc[mt][n][3] + bb.y, 0.f);
            split_pack(h2, h3, hi, lo);
            *(uint32_t*)&g_h1hi[(row + 8) * 256 + col0] = hi;
            *(uint32_t*)&g_h1lo[(row + 8) * 256 + col0] = lo;
        }
    }
}

// ---------------------------------------------------------------------------
// gemm2: H2 = relu(H1 * W2 + b2), K=256 in 8 chunks of 32.
// 256 threads = 8 warps: mg = wid&3 (32 rows), ng = wid>>2 (64 cols).
// ---------------------------------------------------------------------------
#define G2_SM_WF   0
#define G2_SM_AHI  196608
#define G2_SM_ALO  206848
#define G2_SM_B2   217088
#define G2_SMEM    217600

__global__ void __launch_bounds__(256, 1)
gemm2_kernel(const float* __restrict__ b2) {
    extern __shared__ char sm[];
    uint32_t* swf = (uint32_t*)(sm + G2_SM_WF);
    char* ahi = sm + G2_SM_AHI;
    char* alo = sm + G2_SM_ALO;
    float* sb2 = (float*)(sm + G2_SM_B2);

    const int tid = threadIdx.x;
    const int r0 = blockIdx.x * 128;

    for (int i = tid; i < 12288; i += 256)
        ((uint4*)swf)[i] = ((const uint4*)g_wf2)[i];
    if (tid < 128) sb2[tid] = b2[tid];

    const int wid = tid >> 5, lane = tid & 31;
    const int mg = wid & 3, ng = wid >> 2;

    float acc[2][8][4];
#pragma unroll
    for (int m = 0; m < 2; m++)
#pragma unroll
        for (int n = 0; n < 8; n++)
#pragma unroll
            for (int j = 0; j < 4; j++) acc[m][n][j] = 0.f;

    for (int chunk = 0; chunk < 8; chunk++) {
        __syncthreads();   // previous chunk consumed (also covers wf staging on first iter)
        for (int i = tid; i < 512; i += 256) {
            int r = i >> 2, q = i & 3;
            *(uint4*)(ahi + r * 80 + q * 16) =
                *(const uint4*)&g_h1hi[(r0 + r) * 256 + chunk * 32 + q * 8];
            *(uint4*)(alo + r * 80 + q * 16) =
                *(const uint4*)&g_h1lo[(r0 + r) * 256 + chunk * 32 + q * 8];
        }
        __syncthreads();

#pragma unroll
        for (int s = 0; s < 6; s++) {
            const char* ab = (s >= 4) ? alo : ahi;
            int kb = (s & 1) * 32 + (lane & 3) * 4;
            uint32_t a[2][4];
#pragma unroll
            for (int mt = 0; mt < 2; mt++) {
                int rA = mg * 32 + mt * 16 + (lane >> 2);
                a[mt][0] = *(const uint32_t*)(ab + rA * 80 + kb);
                a[mt][1] = *(const uint32_t*)(ab + (rA + 8) * 80 + kb);
                a[mt][2] = *(const uint32_t*)(ab + rA * 80 + kb + 16);
                a[mt][3] = *(const uint32_t*)(ab + (rA + 8) * 80 + kb + 16);
            }
#pragma unroll
            for (int n = 0; n < 8; n++) {
                int idx = (((chunk * 6 + s) * 16 + ng * 8 + n) * 32 + lane) * 2;
                uint32_t b0 = swf[idx], bv1 = swf[idx + 1];
                mma_bf16(acc[0][n], a[0][0], a[0][1], a[0][2], a[0][3], b0, bv1);
                mma_bf16(acc[1][n], a[1][0], a[1][1], a[1][2], a[1][3], b0, bv1);
            }
        }
    }

#pragma unroll
    for (int mt = 0; mt < 2; mt++) {
        int row = r0 + mg * 32 + mt * 16 + (lane >> 2);
#pragma unroll
        for (int n = 0; n < 8; n++) {
            int col0 = ng * 64 + n * 8 + (lane & 3) * 2;
            float2 bb = *(const float2*)&sb2[col0];
            uint32_t hi, lo;
            float h0 = fmaxf(acc[mt][n][0] + bb.x, 0.f);
            float h1 = fmaxf(acc[mt][n][1] + bb.y, 0.f);
            split_pack(h0, h1, hi, lo);
            *(uint32_t*)&g_h2hi[row * 128 + col0] = hi;
            *(uint32_t*)&g_h2lo[row * 128 + col0] = lo;
            float h2 = fmaxf(acc[mt][n][2] + bb.x, 0.f);
            float h3 = fmaxf(acc[mt][n][3] + bb.y, 0.f);
            split_pack(h2, h3, hi, lo);
            *(uint32_t*)&g_h2hi[(row + 8) * 128 + col0] = hi;
            *(uint32_t*)&g_h2lo[(row + 8) * 128 + col0] = lo;
        }
    }
}

// ---------------------------------------------------------------------------
// gemm3: H3 = relu(H2 * W3 + b3); out = sigmoid(H3 . wf + bf).
// 256 threads = 8 warps: mg = wid (16 rows each), all 64 cols per warp.
// ---------------------------------------------------------------------------
#define G3_SM_WF   0
#define G3_SM_HHI  49152
#define G3_SM_HLO  83968
#define G3_SM_B3   118784
#define G3_SM_WFV  119040
#define G3_SM_BF   119296
#define G3_SMEM    119312

__global__ void __launch_bounds__(256, 1)
gemm3_kernel(const float* __restrict__ b3, const float* __restrict__ Wf,
             const float* __restrict__ bf, float* __restrict__ out) {
    extern __shared__ char sm[];
    uint32_t* swf = (uint32_t*)(sm + G3_SM_WF);
    char* hhi = sm + G3_SM_HHI;
    char* hlo = sm + G3_SM_HLO;
    float* sb3 = (float*)(sm + G3_SM_B3);
    float* swv = (float*)(sm + G3_SM_WFV);
    float* sbf = (float*)(sm + G3_SM_BF);

    const int tid = threadIdx.x;
    const int r0 = blockIdx.x * 128;

    for (int i = tid; i < 3072; i += 256)
        ((uint4*)swf)[i] = ((const uint4*)g_wf3)[i];
    if (tid < 64) { sb3[tid] = b3[tid]; swv[tid] = Wf[tid]; }
    if (tid == 0) sbf[0] = bf[0];

    for (int i = tid; i < 2048; i += 256) {
        int r = i >> 4, q = i & 15;
        *(uint4*)(hhi + r * 272 + q * 16) =
            *(const uint4*)&g_h2hi[(r0 + r) * 128 + q * 8];
        *(uint4*)(hlo + r * 272 + q * 16) =
            *(const uint4*)&g_h2lo[(r0 + r) * 128 + q * 8];
    }
    __syncthreads();

    const int wid = tid >> 5, lane = tid & 31;
    const int mg = wid;

    float acc[8][4];
#pragma unroll
    for (int n = 0; n < 8; n++)
#pragma unroll
        for (int j = 0; j < 4; j++) acc[n][j] = 0.f;

#pragma unroll
    for (int s = 0; s < 24; s++) {
        int pass = s >> 3, kt = s & 7;
        const char* ab = (pass == 2) ? hlo : hhi;
        int kb = kt * 32 + (lane & 3) * 4;
        int rA = mg * 16 + (lane >> 2);
        uint32_t a0 = *(const uint32_t*)(ab + rA * 272 + kb);
        uint32_t a1 = *(const uint32_t*)(ab + (rA + 8) * 272 + kb);
        uint32_t a2 = *(const uint32_t*)(ab + rA * 272 + kb + 16);
        uint32_t a3 = *(const uint32_t*)(ab + (rA + 8) * 272 + kb + 16);
#pragma unroll
        for (int n = 0; n < 8; n++) {
            int idx = ((s * 8 + n) * 32 + lane) * 2;
            mma_bf16(acc[n], a0, a1, a2, a3, swf[idx], swf[idx + 1]);
        }
    }

    // final dot + sigmoid
    float sum0 = 0.f, sum1 = 0.f;
#pragma unroll
    for (int n = 0; n < 8; n++) {
        int col0 = n * 8 + (lane & 3) * 2;
        float2 bb = *(const float2*)&sb3[col0];
        float2 wv = *(const float2*)&swv[col0];
        sum0 += fmaxf(acc[n][0] + bb.x, 0.f) * wv.x
              + fmaxf(acc[n][1] + bb.y, 0.f) * wv.y;
        sum1 += fmaxf(acc[n][2] + bb.x, 0.f) * wv.x
              + fmaxf(acc[n][3] + bb.y, 0.f) * wv.y;
    }
    sum0 += __shfl_xor_sync(0xffffffffu, sum0, 1);
    sum0 += __shfl_xor_sync(0xffffffffu, sum0, 2);
    sum1 += __shfl_xor_sync(0xffffffffu, sum1, 1);
    sum1 += __shfl_xor_sync(0xffffffffu, sum1, 2);
    if ((lane & 3) == 0) {
        int row = r0 + mg * 16 + (lane >> 2);
        float bfv = sbf[0];
        out[row]     = 1.f / (1.f + __expf(-(sum0 + bfv)));
        out[row + 8] = 1.f / (1.f + __expf(-(sum1 + bfv)));
    }
}

// ---------------------------------------------------------------------------
extern "C" void kernel_launch(void* const* d_in, const int* in_sizes, int n_in,
                              void* d_out, int out_size) {
    const float* x_dense = (const float*)d_in[0];
    const void*  x_sparse = d_in[1];
    const float* emb   = (const float*)d_in[2];
    const float* gamma = (const float*)d_in[3];
    const float* beta  = (const float*)d_in[4];
    const float* W1 = (const float*)d_in[5];
    const float* b1 = (const float*)d_in[6];
    const float* W2 = (const float*)d_in[7];
    const float* b2 = (const float*)d_in[8];
    const float* W3 = (const float*)d_in[9];
    const float* b3 = (const float*)d_in[10];
    const float* Wf = (const float*)d_in[11];
    const float* bf = (const float*)d_in[12];
    float* out = (float*)d_out;

    static bool s_attr_done = false;
    if (!s_attr_done) {
        cudaFuncSetAttribute(gemm1_kernel,
                             cudaFuncAttributeMaxDynamicSharedMemorySize, G1_SMEM);
        cudaFuncSetAttribute(gemm2_kernel,
                             cudaFuncAttributeMaxDynamicSharedMemorySize, G2_SMEM);
        cudaFuncSetAttribute(gemm3_kernel,
                             cudaFuncAttributeMaxDynamicSharedMemorySize, G3_SMEM);
        s_attr_done = true;
    }

    detect_idx_kernel<<<1, 32>>>((const int*)x_sparse);
    prep_weights_kernel<<<288, 256>>>(W1, W2, W3);
    gather_cross_kernel<<<(B_ROWS * 4) / 256, 256>>>(x_sparse, x_dense, emb);
    bn_stats_kernel<<<F0, 256>>>(gamma, beta);
    gemm1_kernel<<<B_ROWS / 128, 512, G1_SMEM>>>(b1);
    gemm2_kernel<<<B_ROWS / 128, 256, G2_SMEM>>>(b2);
    gemm3_kernel<<<B_ROWS / 128, 256, G3_SMEM>>>(b3, Wf, bf, out);
}

// round 7
// speedup vs baseline: 1.6927x; 1.0836x over previous
#include <cuda_runtime.h>
#include <cuda_bf16.h>
#include <math.h>
#include <stdint.h>

#define B_ROWS 16384
#define NSP 26
#define ND 13
#define VOCAB 100000
#define EMB_D 16
#define F0 29
#define BN_EPS 1e-5f

// ---------------------------------------------------------------------------
// Device scratch
// ---------------------------------------------------------------------------
__device__ float g_xbuf[B_ROWS * 32];   // [B][32]: 0..15 cross, 16..28 dense, 29..31 zero
__device__ float g_bnscale[32];
__device__ float g_bnshift[32];
__device__ int   g_idx64;
__device__ float g_part[256][64];       // per-block BN partials: [0..31] sums, [32..63] sumsq

// Fragment-ordered bf16x2-packed weights (built by prep kernel):
__device__ uint32_t g_wf1[12288];
__device__ uint32_t g_wf2[49152];
__device__ uint32_t g_wf3[12288];

// Intermediate activations, bf16 hi/lo parts
__device__ __nv_bfloat16 g_h1hi[B_ROWS * 256];
__device__ __nv_bfloat16 g_h1lo[B_ROWS * 256];
__device__ __nv_bfloat16 g_h2hi[B_ROWS * 128];
__device__ __nv_bfloat16 g_h2lo[B_ROWS * 128];

// ---------------------------------------------------------------------------
__device__ __forceinline__ void mma_bf16(float* c, uint32_t a0, uint32_t a1,
                                         uint32_t a2, uint32_t a3,
                                         uint32_t b0, uint32_t b1) {
    asm volatile(
        "mma.sync.aligned.m16n8k16.row.col.f32.bf16.bf16.f32 "
        "{%0,%1,%2,%3}, {%4,%5,%6,%7}, {%8,%9}, {%0,%1,%2,%3};"
        : "+f"(c[0]), "+f"(c[1]), "+f"(c[2]), "+f"(c[3])
        : "r"(a0), "r"(a1), "r"(a2), "r"(a3), "r"(b0), "r"(b1));
}

__device__ __forceinline__ void split_pack(float h0, float h1,
                                           uint32_t& hi, uint32_t& lo) {
    __nv_bfloat16 b0 = __float2bfloat16(h0);
    __nv_bfloat16 b1 = __float2bfloat16(h1);
    float r0 = h0 - __bfloat162float(b0);
    float r1 = h1 - __bfloat162float(b1);
    __nv_bfloat16 c0 = __float2bfloat16(r0);
    __nv_bfloat16 c1 = __float2bfloat16(r1);
    hi = ((uint32_t)__bfloat16_as_ushort(b1) << 16) | (uint32_t)__bfloat16_as_ushort(b0);
    lo = ((uint32_t)__bfloat16_as_ushort(c1) << 16) | (uint32_t)__bfloat16_as_ushort(c0);
}

__device__ __forceinline__ unsigned short wpart_bf16(float w, bool lo_part) {
    __nv_bfloat16 h = __float2bfloat16(w);
    if (!lo_part) return __bfloat16_as_ushort(h);
    return __bfloat16_as_ushort(__float2bfloat16(w - __bfloat162float(h)));
}

// ---------------------------------------------------------------------------
__global__ void detect_idx_kernel(const int* __restrict__ xs_i32) {
    if (threadIdx.x == 0) {
        int all0 = 1;
        for (int i = 1; i < 64; i += 2)
            if (xs_i32[i] != 0) { all0 = 0; break; }
        g_idx64 = all0;
    }
}

// ---------------------------------------------------------------------------
// prep: build fragment-ordered split weights.
// ---------------------------------------------------------------------------
__global__ void prep_weights_kernel(const float* __restrict__ W1,
                                    const float* __restrict__ W2,
                                    const float* __restrict__ W3) {
    int e = blockIdx.x * blockDim.x + threadIdx.x;
    if (e >= 73728) return;
    if (e < 12288) {                       // layer 1: K=32(pad from 29), N=256
        int r = e & 1, lane = (e >> 1) & 31, nt = (e >> 6) & 31, s = e >> 11;
        bool wlo = (s == 2 || s == 3);
        int kt = s & 1;
        int k = kt * 16 + (lane & 3) * 2 + r * 8;
        int n = nt * 8 + (lane >> 2);
        float w0 = (k < F0)     ? W1[k * 256 + n]       : 0.f;
        float w1 = (k + 1 < F0) ? W1[(k + 1) * 256 + n] : 0.f;
        g_wf1[e] = ((uint32_t)wpart_bf16(w1, wlo) << 16) | wpart_bf16(w0, wlo);
    } else if (e < 61440) {                // layer 2: K=256, N=128
        int e2 = e - 12288;
        int r = e2 & 1, lane = (e2 >> 1) & 31, nt = (e2 >> 6) & 15, cs = e2 >> 10;
        int chunk = cs / 6, s = cs % 6;
        bool wlo = (s == 2 || s == 3);
        int kt = s & 1;
        int k = chunk * 32 + kt * 16 + (lane & 3) * 2 + r * 8;
        int n = nt * 8 + (lane >> 2);
        float w0 = W2[k * 128 + n];
        float w1 = W2[(k + 1) * 128 + n];
        g_wf2[e2] = ((uint32_t)wpart_bf16(w1, wlo) << 16) | wpart_bf16(w0, wlo);
    } else {                               // layer 3: K=128, N=64
        int e3 = e - 61440;
        int r = e3 & 1, lane = (e3 >> 1) & 31, nt = (e3 >> 6) & 7, s = e3 >> 9;
        int pass = s >> 3, kt = s & 7;
        bool wlo = (pass == 1);
        int k = kt * 16 + (lane & 3) * 2 + r * 8;
        int n = nt * 8 + (lane >> 2);
        float w0 = W3[k * 64 + n];
        float w1 = W3[(k + 1) * 64 + n];
        g_wf3[e3] = ((uint32_t)wpart_bf16(w1, wlo) << 16) | wpart_bf16(w0, wlo);
    }
}

// ---------------------------------------------------------------------------
// Gather + FM cross + fused BN partial statistics.
// 4 threads per row; thread q owns 16B slice q. Per-block partial sums/sumsq
// for all 32 x-columns via warp shuffles + shared reduce -> g_part[block].
// ---------------------------------------------------------------------------
__global__ void gather_cross_kernel(const void* __restrict__ xsparse,
                                    const float* __restrict__ xdense,
                                    const float* __restrict__ emb) {
    __shared__ float swarp[8][4][16];
    int tid = blockIdx.x * blockDim.x + threadIdx.x;
    int r = tid >> 2;
    int q = tid & 3;

    const long long* xs64 = (const long long*)xsparse;
    const int*       xs32 = (const int*)xsparse;
    const bool is64 = (g_idx64 != 0);

    float s0 = 0.f, s1 = 0.f, s2 = 0.f, s3 = 0.f;
    float q0 = 0.f, q1 = 0.f, q2 = 0.f, q3 = 0.f;

#pragma unroll
    for (int f = 0; f < NSP; f++) {
        long long idx = is64 ? xs64[r * NSP + f] : (long long)xs32[r * NSP + f];
        const float4 v = *(const float4*)(emb +
            ((size_t)f * VOCAB + (size_t)idx) * EMB_D + q * 4);
        s0 += v.x; s1 += v.y; s2 += v.z; s3 += v.w;
        q0 += v.x * v.x; q1 += v.y * v.y; q2 += v.z * v.z; q3 += v.w * v.w;
    }

    float4 cr;
    cr.x = 0.5f * (s0 * s0 - q0);
    cr.y = 0.5f * (s1 * s1 - q1);
    cr.z = 0.5f * (s2 * s2 - q2);
    cr.w = 0.5f * (s3 * s3 - q3);
    *(float4*)&g_xbuf[r * 32 + q * 4] = cr;

    int base = q * 4;
    float4 dv;
    dv.x = (base + 0 < ND) ? xdense[r * ND + base + 0] : 0.f;
    dv.y = (base + 1 < ND) ? xdense[r * ND + base + 1] : 0.f;
    dv.z = (base + 2 < ND) ? xdense[r * ND + base + 2] : 0.f;
    dv.w = (base + 3 < ND) ? xdense[r * ND + base + 3] : 0.f;
    *(float4*)&g_xbuf[r * 32 + 16 + q * 4] = dv;

    // ---- fused BN partials ----
    float st[16];
    st[0] = cr.x; st[1] = cr.y; st[2] = cr.z; st[3] = cr.w;
    st[4] = cr.x * cr.x; st[5] = cr.y * cr.y; st[6] = cr.z * cr.z; st[7] = cr.w * cr.w;
    st[8] = dv.x; st[9] = dv.y; st[10] = dv.z; st[11] = dv.w;
    st[12] = dv.x * dv.x; st[13] = dv.y * dv.y; st[14] = dv.z * dv.z; st[15] = dv.w * dv.w;
#pragma unroll
    for (int j = 0; j < 16; j++) {
        st[j] += __shfl_xor_sync(0xffffffffu, st[j], 4);
        st[j] += __shfl_xor_sync(0xffffffffu, st[j], 8);
        st[j] += __shfl_xor_sync(0xffffffffu, st[j], 16);
    }
    int lt = threadIdx.x;
    int wid = lt >> 5, lane = lt & 31;
    if (lane < 4) {
#pragma unroll
        for (int j = 0; j < 16; j++) swarp[wid][lane][j] = st[j];
    }
    __syncthreads();
    if (lt < 64) {
        int qq = lt >> 4, j = lt & 15;
        float acc = 0.f;
#pragma unroll
        for (int w = 0; w < 8; w++) acc += swarp[w][qq][j];
        int col, slot;
        if (j < 4)       { col = qq * 4 + j;          slot = col; }
        else if (j < 8)  { col = qq * 4 + (j - 4);    slot = 32 + col; }
        else if (j < 12) { col = 16 + qq * 4 + (j - 8);  slot = col; }
        else             { col = 16 + qq * 4 + (j - 12); slot = 32 + col; }
        g_part[blockIdx.x][slot] = acc;
    }
}

// ---------------------------------------------------------------------------
// Finalize BN: reduce 256 block-partials (fixed order) -> scale/shift.
// ---------------------------------------------------------------------------
__global__ void bn_finalize_kernel(const float* __restrict__ gamma,
                                   const float* __restrict__ beta) {
    __shared__ float ssum[8][32], ssq[8][32];
    int t = threadIdx.x;
    int col = t & 31, chunk = t >> 5;
    float sum = 0.f, sq = 0.f;
    for (int b = chunk * 32; b < chunk * 32 + 32; b++) {
        sum += g_part[b][col];
        sq  += g_part[b][32 + col];
    }
    ssum[chunk][col] = sum;
    ssq[chunk][col]  = sq;
    __syncthreads();
    if (t < 32) {
        float s = 0.f, s2 = 0.f;
#pragma unroll
        for (int c = 0; c < 8; c++) { s += ssum[c][t]; s2 += ssq[c][t]; }
        float mean = s * (1.0f / B_ROWS);
        float var  = s2 * (1.0f / B_ROWS) - mean * mean;
        if (t < F0) {
            float sc = gamma[t] * rsqrtf(var + BN_EPS);
            g_bnscale[t] = sc;
            g_bnshift[t] = beta[t] - mean * sc;
        } else {
            g_bnscale[t] = 0.f;
            g_bnshift[t] = 0.f;
        }
    }
}

// ---------------------------------------------------------------------------
// gemm1: H1 = relu( BN(X)[128-tile, 32] * W1[32,256] + b1 ), split -> hi/lo.
// ---------------------------------------------------------------------------
#define G1_SM_WF   0
#define G1_SM_XHI  49152
#define G1_SM_XLO  59392
#define G1_SM_B1   69632
#define G1_SMEM    70656

__global__ void __launch_bounds__(512, 1)
gemm1_kernel(const float* __restrict__ b1) {
    extern __shared__ char sm[];
    uint32_t* swf = (uint32_t*)(sm + G1_SM_WF);
    char* xhi = sm + G1_SM_XHI;
    char* xlo = sm + G1_SM_XLO;
    float* sb1 = (float*)(sm + G1_SM_B1);

    const int tid = threadIdx.x;
    const int r0 = blockIdx.x * 128;

    for (int i = tid; i < 3072; i += 512)
        ((uint4*)swf)[i] = ((const uint4*)g_wf1)[i];
    for (int i = tid; i < 256; i += 512) sb1[i] = b1[i];

    {
        int r = tid >> 2, q = tid & 3;
        float4 v0 = *(const float4*)&g_xbuf[(r0 + r) * 32 + q * 8];
        float4 v1 = *(const float4*)&g_xbuf[(r0 + r) * 32 + q * 8 + 4];
        float4 sc0 = *(const float4*)&g_bnscale[q * 8];
        float4 sc1 = *(const float4*)&g_bnscale[q * 8 + 4];
        float4 sh0 = *(const float4*)&g_bnshift[q * 8];
        float4 sh1 = *(const float4*)&g_bnshift[q * 8 + 4];
        float x0 = v0.x * sc0.x + sh0.x, x1 = v0.y * sc0.y + sh0.y;
        float x2 = v0.z * sc0.z + sh0.z, x3 = v0.w * sc0.w + sh0.w;
        float x4 = v1.x * sc1.x + sh1.x, x5 = v1.y * sc1.y + sh1.y;
        float x6 = v1.z * sc1.z + sh1.z, x7 = v1.w * sc1.w + sh1.w;
        uint4 uh, ul;
        split_pack(x0, x1, uh.x, ul.x);
        split_pack(x2, x3, uh.y, ul.y);
        split_pack(x4, x5, uh.z, ul.z);
        split_pack(x6, x7, uh.w, ul.w);
        *(uint4*)(xhi + r * 80 + q * 16) = uh;
        *(uint4*)(xlo + r * 80 + q * 16) = ul;
    }
    __syncthreads();

    const int wid = tid >> 5, lane = tid & 31;
    const int mg = wid & 3, ng = wid >> 2;

    float acc[2][8][4];
#pragma unroll
    for (int m = 0; m < 2; m++)
#pragma unroll
        for (int n = 0; n < 8; n++)
#pragma unroll
            for (int j = 0; j < 4; j++) acc[m][n][j] = 0.f;

#pragma unroll
    for (int s = 0; s < 6; s++) {
        const char* ab = (s >= 4) ? xlo : xhi;
        int kb = (s & 1) * 32 + (lane & 3) * 4;
        uint32_t a[2][4];
#pragma unroll
        for (int mt = 0; mt < 2; mt++) {
            int rA = mg * 32 + mt * 16 + (lane >> 2);
            a[mt][0] = *(const uint32_t*)(ab + rA * 80 + kb);
            a[mt][1] = *(const uint32_t*)(ab + (rA + 8) * 80 + kb);
            a[mt][2] = *(const uint32_t*)(ab + rA * 80 + kb + 16);
            a[mt][3] = *(const uint32_t*)(ab + (rA + 8) * 80 + kb + 16);
        }
#pragma unroll
        for (int n = 0; n < 8; n++) {
            int idx = ((s * 32 + ng * 8 + n) * 32 + lane) * 2;
            uint32_t b0 = swf[idx], bv1 = swf[idx + 1];
            mma_bf16(acc[0][n], a[0][0], a[0][1], a[0][2], a[0][3], b0, bv1);
            mma_bf16(acc[1][n], a[1][0], a[1][1], a[1][2], a[1][3], b0, bv1);
        }
    }

#pragma unroll
    for (int mt = 0; mt < 2; mt++) {
        int row = r0 + mg * 32 + mt * 16 + (lane >> 2);
#pragma unroll
        for (int n = 0; n < 8; n++) {
            int col0 = ng * 64 + n * 8 + (lane & 3) * 2;
            float2 bb = *(const float2*)&sb1[col0];
            uint32_t hi, lo;
            float h0 = fmaxf(acc[mt][n][0] + bb.x, 0.f);
            float h1 = fmaxf(acc[mt][n][1] + bb.y, 0.f);
            split_pack(h0, h1, hi, lo);
            *(uint32_t*)&g_h1hi[row * 256 + col0] = hi;
            *(uint32_t*)&g_h1lo[row * 256 + col0] = lo;
            float h2 = fmaxf(acc[mt][n][2] + bb.x, 0.f);
            float h3 = fmaxf(acc[mt][n][3] + bb.y, 0.f);
            split_pack(h2, h3, hi, lo);
            *(uint32_t*)&g_h1hi[(row + 8) * 256 + col0] = hi;
            *(uint32_t*)&g_h1lo[(row + 8) * 256 + col0] = lo;
        }
    }
}

// ---------------------------------------------------------------------------
// gemm2: H2 = relu(H1 * W2 + b2), K=256 in 8 chunks of 32.
// ---------------------------------------------------------------------------
#define G2_SM_WF   0
#define G2_SM_AHI  196608
#define G2_SM_ALO  206848
#define G2_SM_B2   217088
#define G2_SMEM    217600

__global__ void __launch_bounds__(256, 1)
gemm2_kernel(const float* __restrict__ b2) {
    extern __shared__ char sm[];
    uint32_t* swf = (uint32_t*)(sm + G2_SM_WF);
    char* ahi = sm + G2_SM_AHI;
    char* alo = sm + G2_SM_ALO;
    float* sb2 = (float*)(sm + G2_SM_B2);

    const int tid = threadIdx.x;
    const int r0 = blockIdx.x * 128;

    for (int i = tid; i < 12288; i += 256)
        ((uint4*)swf)[i] = ((const uint4*)g_wf2)[i];
    if (tid < 128) sb2[tid] = b2[tid];

    const int wid = tid >> 5, lane = tid & 31;
    const int mg = wid & 3, ng = wid >> 2;

    float acc[2][8][4];
#pragma unroll
    for (int m = 0; m < 2; m++)
#pragma unroll
        for (int n = 0; n < 8; n++)
#pragma unroll
            for (int j = 0; j < 4; j++) acc[m][n][j] = 0.f;

    for (int chunk = 0; chunk < 8; chunk++) {
        __syncthreads();
        for (int i = tid; i < 512; i += 256) {
            int r = i >> 2, q = i & 3;
            *(uint4*)(ahi + r * 80 + q * 16) =
                *(const uint4*)&g_h1hi[(r0 + r) * 256 + chunk * 32 + q * 8];
            *(uint4*)(alo + r * 80 + q * 16) =
                *(const uint4*)&g_h1lo[(r0 + r) * 256 + chunk * 32 + q * 8];
        }
        __syncthreads();

#pragma unroll
        for (int s = 0; s < 6; s++) {
            const char* ab = (s >= 4) ? alo : ahi;
            int kb = (s & 1) * 32 + (lane & 3) * 4;
            uint32_t a[2][4];
#pragma unroll
            for (int mt = 0; mt < 2; mt++) {
                int rA = mg * 32 + mt * 16 + (lane >> 2);
                a[mt][0] = *(const uint32_t*)(ab + rA * 80 + kb);
                a[mt][1] = *(const uint32_t*)(ab + (rA + 8) * 80 + kb);
                a[mt][2] = *(const uint32_t*)(ab + rA * 80 + kb + 16);
                a[mt][3] = *(const uint32_t*)(ab + (rA + 8) * 80 + kb + 16);
            }
#pragma unroll
            for (int n = 0; n < 8; n++) {
                int idx = (((chunk * 6 + s) * 16 + ng * 8 + n) * 32 + lane) * 2;
                uint32_t b0 = swf[idx], bv1 = swf[idx + 1];
                mma_bf16(acc[0][n], a[0][0], a[0][1], a[0][2], a[0][3], b0, bv1);
                mma_bf16(acc[1][n], a[1][0], a[1][1], a[1][2], a[1][3], b0, bv1);
            }
        }
    }

#pragma unroll
    for (int mt = 0; mt < 2; mt++) {
        int row = r0 + mg * 32 + mt * 16 + (lane >> 2);
#pragma unroll
        for (int n = 0; n < 8; n++) {
            int col0 = ng * 64 + n * 8 + (lane & 3) * 2;
            float2 bb = *(const float2*)&sb2[col0];
            uint32_t hi, lo;
            float h0 = fmaxf(acc[mt][n][0] + bb.x, 0.f);
            float h1 = fmaxf(acc[mt][n][1] + bb.y, 0.f);
            split_pack(h0, h1, hi, lo);
            *(uint32_t*)&g_h2hi[row * 128 + col0] = hi;
            *(uint32_t*)&g_h2lo[row * 128 + col0] = lo;
            float h2 = fmaxf(acc[mt][n][2] + bb.x, 0.f);
            float h3 = fmaxf(acc[mt][n][3] + bb.y, 0.f);
            split_pack(h2, h3, hi, lo);
            *(uint32_t*)&g_h2hi[(row + 8) * 128 + col0] = hi;
            *(uint32_t*)&g_h2lo[(row + 8) * 128 + col0] = lo;
        }
    }
}

// ---------------------------------------------------------------------------
// gemm3: H3 = relu(H2 * W3 + b3); out = sigmoid(H3 . wf + bf).
// ---------------------------------------------------------------------------
#define G3_SM_WF   0
#define G3_SM_HHI  49152
#define G3_SM_HLO  83968
#define G3_SM_B3   118784
#define G3_SM_WFV  119040
#define G3_SM_BF   119296
#define G3_SMEM    119312

__global__ void __launch_bounds__(256, 1)
gemm3_kernel(const float* __restrict__ b3, const float* __restrict__ Wf,
             const float* __restrict__ bf, float* __restrict__ out) {
    extern __shared__ char sm[];
    uint32_t* swf = (uint32_t*)(sm + G3_SM_WF);
    char* hhi = sm + G3_SM_HHI;
    char* hlo = sm + G3_SM_HLO;
    float* sb3 = (float*)(sm + G3_SM_B3);
    float* swv = (float*)(sm + G3_SM_WFV);
    float* sbf = (float*)(sm + G3_SM_BF);

    const int tid = threadIdx.x;
    const int r0 = blockIdx.x * 128;

    for (int i = tid; i < 3072; i += 256)
        ((uint4*)swf)[i] = ((const uint4*)g_wf3)[i];
    if (tid < 64) { sb3[tid] = b3[tid]; swv[tid] = Wf[tid]; }
    if (tid == 0) sbf[0] = bf[0];

    for (int i = tid; i < 2048; i += 256) {
        int r = i >> 4, q = i & 15;
        *(uint4*)(hhi + r * 272 + q * 16) =
            *(const uint4*)&g_h2hi[(r0 + r) * 128 + q * 8];
        *(uint4*)(hlo + r * 272 + q * 16) =
            *(const uint4*)&g_h2lo[(r0 + r) * 128 + q * 8];
    }
    __syncthreads();

    const int wid = tid >> 5, lane = tid & 31;
    const int mg = wid;

    float acc[8][4];
#pragma unroll
    for (int n = 0; n < 8; n++)
#pragma unroll
        for (int j = 0; j < 4; j++) acc[n][j] = 0.f;

#pragma unroll
    for (int s = 0; s < 24; s++) {
        int pass = s >> 3, kt = s & 7;
        const char* ab = (pass == 2) ? hlo : hhi;
        int kb = kt * 32 + (lane & 3) * 4;
        int rA = mg * 16 + (lane >> 2);
        uint32_t a0 = *(const uint32_t*)(ab + rA * 272 + kb);
        uint32_t a1 = *(const uint32_t*)(ab + (rA + 8) * 272 + kb);
        uint32_t a2 = *(const uint32_t*)(ab + rA * 272 + kb + 16);
        uint32_t a3 = *(const uint32_t*)(ab + (rA + 8) * 272 + kb + 16);
#pragma unroll
        for (int n = 0; n < 8; n++) {
            int idx = ((s * 8 + n) * 32 + lane) * 2;
            mma_bf16(acc[n], a0, a1, a2, a3, swf[idx], swf[idx + 1]);
        }
    }

    float sum0 = 0.f, sum1 = 0.f;
#pragma unroll
    for (int n = 0; n < 8; n++) {
        int col0 = n * 8 + (lane & 3) * 2;
        float2 bb = *(const float2*)&sb3[col0];
        float2 wv = *(const float2*)&swv[col0];
        sum0 += fmaxf(acc[n][0] + bb.x, 0.f) * wv.x
              + fmaxf(acc[n][1] + bb.y, 0.f) * wv.y;
        sum1 += fmaxf(acc[n][2] + bb.x, 0.f) * wv.x
              + fmaxf(acc[n][3] + bb.y, 0.f) * wv.y;
    }
    sum0 += __shfl_xor_sync(0xffffffffu, sum0, 1);
    sum0 += __shfl_xor_sync(0xffffffffu, sum0, 2);
    sum1 += __shfl_xor_sync(0xffffffffu, sum1, 1);
    sum1 += __shfl_xor_sync(0xffffffffu, sum1, 2);
    if ((lane & 3) == 0) {
        int row = r0 + mg * 16 + (lane >> 2);
        float bfv = sbf[0];
        out[row]     = 1.f / (1.f + __expf(-(sum0 + bfv)));
        out[row + 8] = 1.f / (1.f + __expf(-(sum1 + bfv)));
    }
}

// ---------------------------------------------------------------------------
extern "C" void kernel_launch(void* const* d_in, const int* in_sizes, int n_in,
                              void* d_out, int out_size) {
    const float* x_dense = (const float*)d_in[0];
    const void*  x_sparse = d_in[1];
    const float* emb   = (const float*)d_in[2];
    const float* gamma = (const float*)d_in[3];
    const float* beta  = (const float*)d_in[4];
    const float* W1 = (const float*)d_in[5];
    const float* b1 = (const float*)d_in[6];
    const float* W2 = (const float*)d_in[7];
    const float* b2 = (const float*)d_in[8];
    const float* W3 = (const float*)d_in[9];
    const float* b3 = (const float*)d_in[10];
    const float* Wf = (const float*)d_in[11];
    const float* bf = (const float*)d_in[12];
    float* out = (float*)d_out;

    static bool s_attr_done = false;
    if (!s_attr_done) {
        cudaFuncSetAttribute(gemm1_kernel,
                             cudaFuncAttributeMaxDynamicSharedMemorySize, G1_SMEM);
        cudaFuncSetAttribute(gemm2_kernel,
                             cudaFuncAttributeMaxDynamicSharedMemorySize, G2_SMEM);
        cudaFuncSetAttribute(gemm3_kernel,
                             cudaFuncAttributeMaxDynamicSharedMemorySize, G3_SMEM);
        s_attr_done = true;
    }

    detect_idx_kernel<<<1, 32>>>((const int*)x_sparse);
    prep_weights_kernel<<<288, 256>>>(W1, W2, W3);
    gather_cross_kernel<<<(B_ROWS * 4) / 256, 256>>>(x_sparse, x_dense, emb);
    bn_finalize_kernel<<<1, 256>>>(gamma, beta);
    gemm1_kernel<<<B_ROWS / 128, 512, G1_SMEM>>>(b1);
    gemm2_kernel<<<B_ROWS / 128, 256, G2_SMEM>>>(b2);
    gemm3_kernel<<<B_ROWS / 128, 256, G3_SMEM>>>(b3, Wf, bf, out);
}

// round 8
// speedup vs baseline: 3.2775x; 1.9363x over previous
#include <cuda_runtime.h>
#include <cuda_bf16.h>
#include <math.h>
#include <stdint.h>

#define B_ROWS 16384
#define NSP 26
#define ND 13
#define VOCAB 100000
#define EMB_D 16
#define F0 29
#define BN_EPS 1e-5f

// ---------------------------------------------------------------------------
// Device scratch
// ---------------------------------------------------------------------------
__device__ float g_xbuf[B_ROWS * 32];
__device__ float g_bnpart[256][64];     // gather-block partials: [0..31] sum, [32..63] sumsq
__device__ int   g_idx64;

// Fragment-ordered bf16x2-packed weights
__device__ uint32_t g_wf1[12288];
__device__ uint32_t g_wf2[49152];
__device__ uint32_t g_wf3[12288];

// ---------------------------------------------------------------------------
__device__ __forceinline__ void mma_bf16(float* c, uint32_t a0, uint32_t a1,
                                         uint32_t a2, uint32_t a3,
                                         uint32_t b0, uint32_t b1) {
    asm volatile(
        "mma.sync.aligned.m16n8k16.row.col.f32.bf16.bf16.f32 "
        "{%0,%1,%2,%3}, {%4,%5,%6,%7}, {%8,%9}, {%0,%1,%2,%3};"
        : "+f"(c[0]), "+f"(c[1]), "+f"(c[2]), "+f"(c[3])
        : "r"(a0), "r"(a1), "r"(a2), "r"(a3), "r"(b0), "r"(b1));
}

__device__ __forceinline__ void split_pack(float h0, float h1,
                                           uint32_t& hi, uint32_t& lo) {
    __nv_bfloat16 b0 = __float2bfloat16(h0);
    __nv_bfloat16 b1 = __float2bfloat16(h1);
    float r0 = h0 - __bfloat162float(b0);
    float r1 = h1 - __bfloat162float(b1);
    __nv_bfloat16 c0 = __float2bfloat16(r0);
    __nv_bfloat16 c1 = __float2bfloat16(r1);
    hi = ((uint32_t)__bfloat16_as_ushort(b1) << 16) | (uint32_t)__bfloat16_as_ushort(b0);
    lo = ((uint32_t)__bfloat16_as_ushort(c1) << 16) | (uint32_t)__bfloat16_as_ushort(c0);
}

__device__ __forceinline__ unsigned short wpart_bf16(float w, bool lo_part) {
    __nv_bfloat16 h = __float2bfloat16(w);
    if (!lo_part) return __bfloat16_as_ushort(h);
    return __bfloat16_as_ushort(__float2bfloat16(w - __bfloat162float(h)));
}

// ---------------------------------------------------------------------------
// prep (+ idx-width detect): build fragment-ordered split weights.
// ---------------------------------------------------------------------------
__global__ void prep_weights_kernel(const float* __restrict__ W1,
                                    const float* __restrict__ W2,
                                    const float* __restrict__ W3,
                                    const int* __restrict__ xs_i32) {
    int e = blockIdx.x * blockDim.x + threadIdx.x;
    if (e == 0) {
        int all0 = 1;
        for (int i = 1; i < 64; i += 2)
            if (xs_i32[i] != 0) { all0 = 0; break; }
        g_idx64 = all0;
    }
    if (e >= 73728) return;
    if (e < 12288) {                       // layer 1: K=32(pad), N=256
        int r = e & 1, lane = (e >> 1) & 31, nt = (e >> 6) & 31, s = e >> 11;
        bool wlo = (s == 2 || s == 3);
        int kt = s & 1;
        int k = kt * 16 + (lane & 3) * 2 + r * 8;
        int n = nt * 8 + (lane >> 2);
        float w0 = (k < F0)     ? W1[k * 256 + n]       : 0.f;
        float w1 = (k + 1 < F0) ? W1[(k + 1) * 256 + n] : 0.f;
        g_wf1[e] = ((uint32_t)wpart_bf16(w1, wlo) << 16) | wpart_bf16(w0, wlo);
    } else if (e < 61440) {                // layer 2: K=256, N=128
        int e2 = e - 12288;
        int r = e2 & 1, lane = (e2 >> 1) & 31, nt = (e2 >> 6) & 15, cs = e2 >> 10;
        int chunk = cs / 6, s = cs % 6;
        bool wlo = (s == 2 || s == 3);
        int kt = s & 1;
        int k = chunk * 32 + kt * 16 + (lane & 3) * 2 + r * 8;
        int n = nt * 8 + (lane >> 2);
        float w0 = W2[k * 128 + n];
        float w1 = W2[(k + 1) * 128 + n];
        g_wf2[e2] = ((uint32_t)wpart_bf16(w1, wlo) << 16) | wpart_bf16(w0, wlo);
    } else {                               // layer 3: K=128, N=64
        int e3 = e - 61440;
        int r = e3 & 1, lane = (e3 >> 1) & 31, nt = (e3 >> 6) & 7, s = e3 >> 9;
        int pass = s >> 3, kt = s & 7;
        bool wlo = (pass == 1);
        int k = kt * 16 + (lane & 3) * 2 + r * 8;
        int n = nt * 8 + (lane >> 2);
        float w0 = W3[k * 64 + n];
        float w1 = W3[(k + 1) * 64 + n];
        g_wf3[e3] = ((uint32_t)wpart_bf16(w1, wlo) << 16) | wpart_bf16(w0, wlo);
    }
}

// ---------------------------------------------------------------------------
// Gather + FM cross + fused BN partial statistics (unchanged from R7).
// ---------------------------------------------------------------------------
__global__ void gather_cross_kernel(const void* __restrict__ xsparse,
                                    const float* __restrict__ xdense,
                                    const float* __restrict__ emb) {
    __shared__ float swarp[8][4][16];
    int tid = blockIdx.x * blockDim.x + threadIdx.x;
    int r = tid >> 2;
    int q = tid & 3;

    const long long* xs64 = (const long long*)xsparse;
    const int*       xs32 = (const int*)xsparse;
    const bool is64 = (g_idx64 != 0);

    float s0 = 0.f, s1 = 0.f, s2 = 0.f, s3 = 0.f;
    float q0 = 0.f, q1 = 0.f, q2 = 0.f, q3 = 0.f;

#pragma unroll
    for (int f = 0; f < NSP; f++) {
        long long idx = is64 ? xs64[r * NSP + f] : (long long)xs32[r * NSP + f];
        const float4 v = *(const float4*)(emb +
            ((size_t)f * VOCAB + (size_t)idx) * EMB_D + q * 4);
        s0 += v.x; s1 += v.y; s2 += v.z; s3 += v.w;
        q0 += v.x * v.x; q1 += v.y * v.y; q2 += v.z * v.z; q3 += v.w * v.w;
    }

    float4 cr;
    cr.x = 0.5f * (s0 * s0 - q0);
    cr.y = 0.5f * (s1 * s1 - q1);
    cr.z = 0.5f * (s2 * s2 - q2);
    cr.w = 0.5f * (s3 * s3 - q3);
    *(float4*)&g_xbuf[r * 32 + q * 4] = cr;

    int base = q * 4;
    float4 dv;
    dv.x = (base + 0 < ND) ? xdense[r * ND + base + 0] : 0.f;
    dv.y = (base + 1 < ND) ? xdense[r * ND + base + 1] : 0.f;
    dv.z = (base + 2 < ND) ? xdense[r * ND + base + 2] : 0.f;
    dv.w = (base + 3 < ND) ? xdense[r * ND + base + 3] : 0.f;
    *(float4*)&g_xbuf[r * 32 + 16 + q * 4] = dv;

    float st[16];
    st[0] = cr.x; st[1] = cr.y; st[2] = cr.z; st[3] = cr.w;
    st[4] = cr.x * cr.x; st[5] = cr.y * cr.y; st[6] = cr.z * cr.z; st[7] = cr.w * cr.w;
    st[8] = dv.x; st[9] = dv.y; st[10] = dv.z; st[11] = dv.w;
    st[12] = dv.x * dv.x; st[13] = dv.y * dv.y; st[14] = dv.z * dv.z; st[15] = dv.w * dv.w;
#pragma unroll
    for (int j = 0; j < 16; j++) {
        st[j] += __shfl_xor_sync(0xffffffffu, st[j], 4);
        st[j] += __shfl_xor_sync(0xffffffffu, st[j], 8);
        st[j] += __shfl_xor_sync(0xffffffffu, st[j], 16);
    }
    int lt = threadIdx.x;
    int wid = lt >> 5, lane = lt & 31;
    if (lane < 4) {
#pragma unroll
        for (int j = 0; j < 16; j++) swarp[wid][lane][j] = st[j];
    }
    __syncthreads();
    if (lt < 64) {
        int qq = lt >> 4, j = lt & 15;
        float acc = 0.f;
#pragma unroll
        for (int w = 0; w < 8; w++) acc += swarp[w][qq][j];
        int col, slot;
        if (j < 4)       { col = qq * 4 + j;          slot = col; }
        else if (j < 8)  { col = qq * 4 + (j - 4);    slot = 32 + col; }
        else if (j < 12) { col = 16 + qq * 4 + (j - 8);  slot = col; }
        else             { col = 16 + qq * 4 + (j - 12); slot = 32 + col; }
        g_bnpart[blockIdx.x][slot] = acc;
    }
}

// ---------------------------------------------------------------------------
// Fused MLP: one CTA per 128 rows, 512 threads. BN finalize in prologue,
// H1/H2 resident in SMEM, weights read from L2.
// ---------------------------------------------------------------------------
// SMEM byte map (X region aliased by H2 after layer 1):
#define FM_H1HI  0            // 128*528 = 67584
#define FM_H1LO  67584        // 67584   -> ends 135168
#define FM_XHI   135168       // 10240
#define FM_XLO   145408       // 10240   -> ends 155648 (dead after gemm1)
#define FM_H2HI  135168       // 34816 (aliases X)
#define FM_H2LO  169984       // 34816   -> ends 204800
#define FM_BIAS  204800       // floats: b1[256] b2[128] b3[64] wf[64] bf[1]
#define FM_SC    207232       // 32 floats
#define FM_SH    207360       // 32 floats
#define FM_RED   207488       // 8*64 floats = 2048
#define FM_SMEM  209536

__global__ void __launch_bounds__(512, 1)
fused_mlp_kernel(const float* __restrict__ gamma, const float* __restrict__ beta,
                 const float* __restrict__ b1, const float* __restrict__ b2,
                 const float* __restrict__ b3, const float* __restrict__ Wf,
                 const float* __restrict__ bf, float* __restrict__ out) {
    extern __shared__ char sm[];
    float* sb1 = (float*)(sm + FM_BIAS);
    float* sb2 = sb1 + 256;
    float* sb3 = sb2 + 128;
    float* swv = sb3 + 64;
    float* sbf = swv + 64;
    float* sSC = (float*)(sm + FM_SC);
    float* sSH = (float*)(sm + FM_SH);
    float* sred = (float*)(sm + FM_RED);   // [8][64]

    const int tid = threadIdx.x;
    const int r0 = blockIdx.x * 128;

    // ---- biases ----
    if (tid < 256) sb1[tid] = b1[tid];
    else if (tid < 384) sb2[tid - 256] = b2[tid - 256];
    else if (tid < 448) sb3[tid - 384] = b3[tid - 384];
    else if (tid < 512) swv[tid - 448] = Wf[tid - 448];
    if (tid == 0) sbf[0] = bf[0];

    // ---- BN finalize (per-CTA redundant; fixed order -> deterministic) ----
    {
        int slot = tid & 63, seg = tid >> 6;
        float acc = 0.f;
        for (int b = seg * 32; b < seg * 32 + 32; b++)
            acc += g_bnpart[b][slot];
        sred[seg * 64 + slot] = acc;
    }
    __syncthreads();
    if (tid < 32) {
        float s = 0.f, s2 = 0.f;
#pragma unroll
        for (int c = 0; c < 8; c++) { s += sred[c * 64 + tid]; s2 += sred[c * 64 + 32 + tid]; }
        float mean = s * (1.0f / B_ROWS);
        float var  = s2 * (1.0f / B_ROWS) - mean * mean;
        if (tid < F0) {
            float sc = gamma[tid] * rsqrtf(var + BN_EPS);
            sSC[tid] = sc;
            sSH[tid] = beta[tid] - mean * sc;
        } else { sSC[tid] = 0.f; sSH[tid] = 0.f; }
    }
    __syncthreads();

    // ---- stage X tile: BN + bf16 split ----
    {
        int r = tid >> 2, q = tid & 3;
        float4 v0 = *(const float4*)&g_xbuf[(r0 + r) * 32 + q * 8];
        float4 v1 = *(const float4*)&g_xbuf[(r0 + r) * 32 + q * 8 + 4];
        float4 sc0 = *(const float4*)&sSC[q * 8];
        float4 sc1 = *(const float4*)&sSC[q * 8 + 4];
        float4 sh0 = *(const float4*)&sSH[q * 8];
        float4 sh1 = *(const float4*)&sSH[q * 8 + 4];
        float x0 = v0.x * sc0.x + sh0.x, x1 = v0.y * sc0.y + sh0.y;
        float x2 = v0.z * sc0.z + sh0.z, x3 = v0.w * sc0.w + sh0.w;
        float x4 = v1.x * sc1.x + sh1.x, x5 = v1.y * sc1.y + sh1.y;
        float x6 = v1.z * sc1.z + sh1.z, x7 = v1.w * sc1.w + sh1.w;
        uint4 uh, ul;
        split_pack(x0, x1, uh.x, ul.x);
        split_pack(x2, x3, uh.y, ul.y);
        split_pack(x4, x5, uh.z, ul.z);
        split_pack(x6, x7, uh.w, ul.w);
        *(uint4*)(sm + FM_XHI + r * 80 + q * 16) = uh;
        *(uint4*)(sm + FM_XLO + r * 80 + q * 16) = ul;
    }
    __syncthreads();

    const int wid = tid >> 5, lane = tid & 31;

    // ================= layer 1: [128x32] x [32x256] =================
    {
        const int mg = wid & 3, ng = wid >> 2;     // 4 x 4 warp grid
        float acc[2][8][4];
#pragma unroll
        for (int m = 0; m < 2; m++)
#pragma unroll
            for (int n = 0; n < 8; n++)
#pragma unroll
                for (int j = 0; j < 4; j++) acc[m][n][j] = 0.f;

#pragma unroll
        for (int s = 0; s < 6; s++) {
            const char* ab = sm + ((s >= 4) ? FM_XLO : FM_XHI);
            int kb = (s & 1) * 32 + (lane & 3) * 4;
            uint32_t a[2][4];
#pragma unroll
            for (int mt = 0; mt < 2; mt++) {
                int rA = mg * 32 + mt * 16 + (lane >> 2);
                a[mt][0] = *(const uint32_t*)(ab + rA * 80 + kb);
                a[mt][1] = *(const uint32_t*)(ab + (rA + 8) * 80 + kb);
                a[mt][2] = *(const uint32_t*)(ab + rA * 80 + kb + 16);
                a[mt][3] = *(const uint32_t*)(ab + (rA + 8) * 80 + kb + 16);
            }
#pragma unroll
            for (int n = 0; n < 8; n++) {
                uint2 w = __ldg((const uint2*)&g_wf1[((s * 32 + ng * 8 + n) * 32 + lane) * 2]);
                mma_bf16(acc[0][n], a[0][0], a[0][1], a[0][2], a[0][3], w.x, w.y);
                mma_bf16(acc[1][n], a[1][0], a[1][1], a[1][2], a[1][3], w.x, w.y);
            }
        }

        // epilogue -> sH1 (stride 528 B)
#pragma unroll
        for (int mt = 0; mt < 2; mt++) {
            int rr = mg * 32 + mt * 16 + (lane >> 2);
#pragma unroll
            for (int n = 0; n < 8; n++) {
                int cb = (ng * 64 + n * 8 + (lane & 3) * 2) * 2;   // byte offset
                float2 bb = *(const float2*)&sb1[ng * 64 + n * 8 + (lane & 3) * 2];
                uint32_t hi, lo;
                float h0 = fmaxf(acc[mt][n][0] + bb.x, 0.f);
                float h1 = fmaxf(acc[mt][n][1] + bb.y, 0.f);
                split_pack(h0, h1, hi, lo);
                *(uint32_t*)(sm + FM_H1HI + rr * 528 + cb) = hi;
                *(uint32_t*)(sm + FM_H1LO + rr * 528 + cb) = lo;
                float h2 = fmaxf(acc[mt][n][2] + bb.x, 0.f);
                float h3 = fmaxf(acc[mt][n][3] + bb.y, 0.f);
                split_pack(h2, h3, hi, lo);
                *(uint32_t*)(sm + FM_H1HI + (rr + 8) * 528 + cb) = hi;
                *(uint32_t*)(sm + FM_H1LO + (rr + 8) * 528 + cb) = lo;
            }
        }
    }
    __syncthreads();

    // ================= layer 2: [128x256] x [256x128] =================
    {
        const int mg = wid & 3, ng = wid >> 2;     // mg: 2 mtiles, ng: 4 ntiles (32 cols)
        float acc[2][4][4];
#pragma unroll
        for (int m = 0; m < 2; m++)
#pragma unroll
            for (int n = 0; n < 4; n++)
#pragma unroll
                for (int j = 0; j < 4; j++) acc[m][n][j] = 0.f;

#pragma unroll 6
        for (int cs = 0; cs < 48; cs++) {
            int chunk = cs / 6, s = cs % 6;
            const char* ab = sm + ((s >= 4) ? FM_H1LO : FM_H1HI);
            int kb = chunk * 64 + (s & 1) * 32 + (lane & 3) * 4;
            uint32_t a[2][4];
#pragma unroll
            for (int mt = 0; mt < 2; mt++) {
                int rA = mg * 32 + mt * 16 + (lane >> 2);
                a[mt][0] = *(const uint32_t*)(ab + rA * 528 + kb);
                a[mt][1] = *(const uint32_t*)(ab + (rA + 8) * 528 + kb);
                a[mt][2] = *(const uint32_t*)(ab + rA * 528 + kb + 16);
                a[mt][3] = *(const uint32_t*)(ab + (rA + 8) * 528 + kb + 16);
            }
#pragma unroll
            for (int n = 0; n < 4; n++) {
                uint2 w = __ldg((const uint2*)&g_wf2[((cs * 16 + ng * 4 + n) * 32 + lane) * 2]);
                mma_bf16(acc[0][n], a[0][0], a[0][1], a[0][2], a[0][3], w.x, w.y);
                mma_bf16(acc[1][n], a[1][0], a[1][1], a[1][2], a[1][3], w.x, w.y);
            }
        }

        // epilogue -> sH2 (stride 272 B)
#pragma unroll
        for (int mt = 0; mt < 2; mt++) {
            int rr = mg * 32 + mt * 16 + (lane >> 2);
#pragma unroll
            for (int n = 0; n < 4; n++) {
                int col0 = ng * 32 + n * 8 + (lane & 3) * 2;
                float2 bb = *(const float2*)&sb2[col0];
                uint32_t hi, lo;
                float h0 = fmaxf(acc[mt][n][0] + bb.x, 0.f);
                float h1 = fmaxf(acc[mt][n][1] + bb.y, 0.f);
                split_pack(h0, h1, hi, lo);
                *(uint32_t*)(sm + FM_H2HI + rr * 272 + col0 * 2) = hi;
                *(uint32_t*)(sm + FM_H2LO + rr * 272 + col0 * 2) = lo;
                float h2 = fmaxf(acc[mt][n][2] + bb.x, 0.f);
                float h3 = fmaxf(acc[mt][n][3] + bb.y, 0.f);
                split_pack(h2, h3, hi, lo);
                *(uint32_t*)(sm + FM_H2HI + (rr + 8) * 272 + col0 * 2) = hi;
                *(uint32_t*)(sm + FM_H2LO + (rr + 8) * 272 + col0 * 2) = lo;
            }
        }
    }
    __syncthreads();

    // ================= layer 3 + head: warps 0..7 =================
    if (wid < 8) {
        const int mg = wid;
        float acc[8][4];
#pragma unroll
        for (int n = 0; n < 8; n++)
#pragma unroll
            for (int j = 0; j < 4; j++) acc[n][j] = 0.f;

#pragma unroll
        for (int s = 0; s < 24; s++) {
            int pass = s >> 3, kt = s & 7;
            const char* ab = sm + ((pass == 2) ? FM_H2LO : FM_H2HI);
            int kb = kt * 32 + (lane & 3) * 4;
            int rA = mg * 16 + (lane >> 2);
            uint32_t a0 = *(const uint32_t*)(ab + rA * 272 + kb);
            uint32_t a1 = *(const uint32_t*)(ab + (rA + 8) * 272 + kb);
            uint32_t a2 = *(const uint32_t*)(ab + rA * 272 + kb + 16);
            uint32_t a3 = *(const uint32_t*)(ab + (rA + 8) * 272 + kb + 16);
#pragma unroll
            for (int n = 0; n < 8; n++) {
                uint2 w = __ldg((const uint2*)&g_wf3[((s * 8 + n) * 32 + lane) * 2]);
                mma_bf16(acc[n], a0, a1, a2, a3, w.x, w.y);
            }
        }

        float sum0 = 0.f, sum1 = 0.f;
#pragma unroll
        for (int n = 0; n < 8; n++) {
            int col0 = n * 8 + (lane & 3) * 2;
            float2 bb = *(const float2*)&sb3[col0];
            float2 wv = *(const float2*)&swv[col0];
            sum0 += fmaxf(acc[n][0] + bb.x, 0.f) * wv.x
                  + fmaxf(acc[n][1] + bb.y, 0.f) * wv.y;
            sum1 += fmaxf(acc[n][2] + bb.x, 0.f) * wv.x
                  + fmaxf(acc[n][3] + bb.y, 0.f) * wv.y;
        }
        sum0 += __shfl_xor_sync(0xffffffffu, sum0, 1);
        sum0 += __shfl_xor_sync(0xffffffffu, sum0, 2);
        sum1 += __shfl_xor_sync(0xffffffffu, sum1, 1);
        sum1 += __shfl_xor_sync(0xffffffffu, sum1, 2);
        if ((lane & 3) == 0) {
            int row = r0 + mg * 16 + (lane >> 2);
            float bfv = sbf[0];
            out[row]     = 1.f / (1.f + __expf(-(sum0 + bfv)));
            out[row + 8] = 1.f / (1.f + __expf(-(sum1 + bfv)));
        }
    }
}

// ---------------------------------------------------------------------------
extern "C" void kernel_launch(void* const* d_in, const int* in_sizes, int n_in,
                              void* d_out, int out_size) {
    const float* x_dense = (const float*)d_in[0];
    const void*  x_sparse = d_in[1];
    const float* emb   = (const float*)d_in[2];
    const float* gamma = (const float*)d_in[3];
    const float* beta  = (const float*)d_in[4];
    const float* W1 = (const float*)d_in[5];
    const float* b1 = (const float*)d_in[6];
    const float* W2 = (const float*)d_in[7];
    const float* b2 = (const float*)d_in[8];
    const float* W3 = (const float*)d_in[9];
    const float* b3 = (const float*)d_in[10];
    const float* Wf = (const float*)d_in[11];
    const float* bf = (const float*)d_in[12];
    float* out = (float*)d_out;

    static bool s_attr_done = false;
    if (!s_attr_done) {
        cudaFuncSetAttribute(fused_mlp_kernel,
                             cudaFuncAttributeMaxDynamicSharedMemorySize, FM_SMEM);
        s_attr_done = true;
    }

    prep_weights_kernel<<<288, 256>>>(W1, W2, W3, (const int*)x_sparse);
    gather_cross_kernel<<<(B_ROWS * 4) / 256, 256>>>(x_sparse, x_dense, emb);
    fused_mlp_kernel<<<B_ROWS / 128, 512, FM_SMEM>>>(gamma, beta, b1, b2, b3,
                                                     Wf, bf, out);
}

// round 9
// speedup vs baseline: 3.4768x; 1.0608x over previous
#include <cuda_runtime.h>
#include <cuda_bf16.h>
#include <math.h>
#include <stdint.h>

#define B_ROWS 16384
#define NSP 26
#define ND 13
#define VOCAB 100000
#define EMB_D 16
#define F0 29
#define BN_EPS 1e-5f

// ---------------------------------------------------------------------------
// Device scratch
// ---------------------------------------------------------------------------
__device__ float g_xbuf[B_ROWS * 32];
__device__ float g_bnpart[256][64];     // gather-block partials: [0..31] sum, [32..63] sumsq

// Fragment-ordered bf16x2-packed weights
__device__ uint32_t g_wf1[12288];
__device__ uint32_t g_wf2[49152];
__device__ uint32_t g_wf3[12288];

// ---------------------------------------------------------------------------
__device__ __forceinline__ void mma_bf16(float* c, uint32_t a0, uint32_t a1,
                                         uint32_t a2, uint32_t a3,
                                         uint32_t b0, uint32_t b1) {
    asm volatile(
        "mma.sync.aligned.m16n8k16.row.col.f32.bf16.bf16.f32 "
        "{%0,%1,%2,%3}, {%4,%5,%6,%7}, {%8,%9}, {%0,%1,%2,%3};"
        : "+f"(c[0]), "+f"(c[1]), "+f"(c[2]), "+f"(c[3])
        : "r"(a0), "r"(a1), "r"(a2), "r"(a3), "r"(b0), "r"(b1));
}

__device__ __forceinline__ void ldsm_x4(uint32_t* r, uint32_t addr) {
    asm volatile("ldmatrix.sync.aligned.m8n8.x4.shared.b16 {%0,%1,%2,%3}, [%4];"
                 : "=r"(r[0]), "=r"(r[1]), "=r"(r[2]), "=r"(r[3]) : "r"(addr));
}

__device__ __forceinline__ uint32_t smem_u32(const void* p) {
    uint32_t a;
    asm("{ .reg .u64 t; cvta.to.shared.u64 t, %1; cvt.u32.u64 %0, t; }"
        : "=r"(a) : "l"(p));
    return a;
}

__device__ __forceinline__ void split_pack(float h0, float h1,
                                           uint32_t& hi, uint32_t& lo) {
    __nv_bfloat16 b0 = __float2bfloat16(h0);
    __nv_bfloat16 b1 = __float2bfloat16(h1);
    float r0 = h0 - __bfloat162float(b0);
    float r1 = h1 - __bfloat162float(b1);
    __nv_bfloat16 c0 = __float2bfloat16(r0);
    __nv_bfloat16 c1 = __float2bfloat16(r1);
    hi = ((uint32_t)__bfloat16_as_ushort(b1) << 16) | (uint32_t)__bfloat16_as_ushort(b0);
    lo = ((uint32_t)__bfloat16_as_ushort(c1) << 16) | (uint32_t)__bfloat16_as_ushort(c0);
}

__device__ __forceinline__ unsigned short wpart_bf16(float w, bool lo_part) {
    __nv_bfloat16 h = __float2bfloat16(w);
    if (!lo_part) return __bfloat16_as_ushort(h);
    return __bfloat16_as_ushort(__float2bfloat16(w - __bfloat162float(h)));
}

// ---------------------------------------------------------------------------
__device__ __forceinline__ void prep_one(int e, const float* __restrict__ W1,
                                         const float* __restrict__ W2,
                                         const float* __restrict__ W3) {
    if (e < 12288) {                       // layer 1: K=32(pad), N=256
        int r = e & 1, lane = (e >> 1) & 31, nt = (e >> 6) & 31, s = e >> 11;
        bool wlo = (s == 2 || s == 3);
        int kt = s & 1;
        int k = kt * 16 + (lane & 3) * 2 + r * 8;
        int n = nt * 8 + (lane >> 2);
        float w0 = (k < F0)     ? W1[k * 256 + n]       : 0.f;
        float w1 = (k + 1 < F0) ? W1[(k + 1) * 256 + n] : 0.f;
        g_wf1[e] = ((uint32_t)wpart_bf16(w1, wlo) << 16) | wpart_bf16(w0, wlo);
    } else if (e < 61440) {                // layer 2: K=256, N=128
        int e2 = e - 12288;
        int r = e2 & 1, lane = (e2 >> 1) & 31, nt = (e2 >> 6) & 15, cs = e2 >> 10;
        int chunk = cs / 6, s = cs % 6;
        bool wlo = (s == 2 || s == 3);
        int kt = s & 1;
        int k = chunk * 32 + kt * 16 + (lane & 3) * 2 + r * 8;
        int n = nt * 8 + (lane >> 2);
        float w0 = W2[k * 128 + n];
        float w1 = W2[(k + 1) * 128 + n];
        g_wf2[e2] = ((uint32_t)wpart_bf16(w1, wlo) << 16) | wpart_bf16(w0, wlo);
    } else {                               // layer 3: K=128, N=64
        int e3 = e - 61440;
        int r = e3 & 1, lane = (e3 >> 1) & 31, nt = (e3 >> 6) & 7, s = e3 >> 9;
        int pass = s >> 3, kt = s & 7;
        bool wlo = (pass == 1);
        int k = kt * 16 + (lane & 3) * 2 + r * 8;
        int n = nt * 8 + (lane >> 2);
        float w0 = W3[k * 64 + n];
        float w1 = W3[(k + 1) * 64 + n];
        g_wf3[e3] = ((uint32_t)wpart_bf16(w1, wlo) << 16) | wpart_bf16(w0, wlo);
    }
}

// ---------------------------------------------------------------------------
// front: blocks 0..255 do gather+cross+BN-partials; blocks 256..327 do
// weight prep (72 blocks x 1024 elements).
// ---------------------------------------------------------------------------
__global__ void front_kernel(const void* __restrict__ xsparse,
                             const float* __restrict__ xdense,
                             const float* __restrict__ emb,
                             const float* __restrict__ W1,
                             const float* __restrict__ W2,
                             const float* __restrict__ W3) {
    if (blockIdx.x >= 256) {
        int bb = blockIdx.x - 256;
#pragma unroll
        for (int i = 0; i < 4; i++)
            prep_one(bb * 1024 + i * 256 + threadIdx.x, W1, W2, W3);
        return;
    }

    __shared__ float swarp[8][4][16];
    __shared__ int s_is64;
    const int lt = threadIdx.x;
    const int* xs_i32 = (const int*)xsparse;

    // inline idx-width detect: high halves of first 32 entries all zero -> i64
    if (lt < 32) {
        unsigned m = __ballot_sync(0xffffffffu, xs_i32[2 * lt + 1] != 0);
        if (lt == 0) s_is64 = (m == 0);
    }
    __syncthreads();
    const bool is64 = (s_is64 != 0);

    int tid = blockIdx.x * blockDim.x + lt;
    int r = tid >> 2;
    int q = tid & 3;

    const long long* xs64 = (const long long*)xsparse;

    float s0 = 0.f, s1 = 0.f, s2 = 0.f, s3 = 0.f;
    float q0 = 0.f, q1 = 0.f, q2 = 0.f, q3 = 0.f;

#pragma unroll
    for (int f = 0; f < NSP; f++) {
        long long idx = is64 ? xs64[r * NSP + f] : (long long)xs_i32[r * NSP + f];
        const float4 v = *(const float4*)(emb +
            ((size_t)f * VOCAB + (size_t)idx) * EMB_D + q * 4);
        s0 += v.x; s1 += v.y; s2 += v.z; s3 += v.w;
        q0 += v.x * v.x; q1 += v.y * v.y; q2 += v.z * v.z; q3 += v.w * v.w;
    }

    float4 cr;
    cr.x = 0.5f * (s0 * s0 - q0);
    cr.y = 0.5f * (s1 * s1 - q1);
    cr.z = 0.5f * (s2 * s2 - q2);
    cr.w = 0.5f * (s3 * s3 - q3);
    *(float4*)&g_xbuf[r * 32 + q * 4] = cr;

    int base = q * 4;
    float4 dv;
    dv.x = (base + 0 < ND) ? xdense[r * ND + base + 0] : 0.f;
    dv.y = (base + 1 < ND) ? xdense[r * ND + base + 1] : 0.f;
    dv.z = (base + 2 < ND) ? xdense[r * ND + base + 2] : 0.f;
    dv.w = (base + 3 < ND) ? xdense[r * ND + base + 3] : 0.f;
    *(float4*)&g_xbuf[r * 32 + 16 + q * 4] = dv;

    float st[16];
    st[0] = cr.x; st[1] = cr.y; st[2] = cr.z; st[3] = cr.w;
    st[4] = cr.x * cr.x; st[5] = cr.y * cr.y; st[6] = cr.z * cr.z; st[7] = cr.w * cr.w;
    st[8] = dv.x; st[9] = dv.y; st[10] = dv.z; st[11] = dv.w;
    st[12] = dv.x * dv.x; st[13] = dv.y * dv.y; st[14] = dv.z * dv.z; st[15] = dv.w * dv.w;
#pragma unroll
    for (int j = 0; j < 16; j++) {
        st[j] += __shfl_xor_sync(0xffffffffu, st[j], 4);
        st[j] += __shfl_xor_sync(0xffffffffu, st[j], 8);
        st[j] += __shfl_xor_sync(0xffffffffu, st[j], 16);
    }
    int wid = lt >> 5, lane = lt & 31;
    if (lane < 4) {
#pragma unroll
        for (int j = 0; j < 16; j++) swarp[wid][lane][j] = st[j];
    }
    __syncthreads();
    if (lt < 64) {
        int qq = lt >> 4, j = lt & 15;
        float acc = 0.f;
#pragma unroll
        for (int w = 0; w < 8; w++) acc += swarp[w][qq][j];
        int col, slot;
        if (j < 4)       { col = qq * 4 + j;          slot = col; }
        else if (j < 8)  { col = qq * 4 + (j - 4);    slot = 32 + col; }
        else if (j < 12) { col = 16 + qq * 4 + (j - 8);  slot = col; }
        else             { col = 16 + qq * 4 + (j - 12); slot = 32 + col; }
        g_bnpart[blockIdx.x][slot] = acc;
    }
}

// ---------------------------------------------------------------------------
// Fused MLP: one CTA per 128 rows, 512 threads. BN finalize in prologue,
// H1/H2 resident in SMEM, weights from L2, A-frags via ldmatrix.
// ---------------------------------------------------------------------------
#define FM_H1HI  0            // 128*528 = 67584
#define FM_H1LO  67584        // -> 135168
#define FM_XHI   135168       // 10240 (dead after layer 1)
#define FM_XLO   145408       // 10240
#define FM_H2HI  135168       // 34816 (aliases X)
#define FM_H2LO  169984       // 34816 -> 204800
#define FM_BIAS  204800       // b1[256] b2[128] b3[64] wf[64] bf[1]
#define FM_SC    207232
#define FM_SH    207360
#define FM_RED   207488       // 8*64 floats
#define FM_SMEM  209536

__global__ void __launch_bounds__(512, 1)
fused_mlp_kernel(const float* __restrict__ gamma, const float* __restrict__ beta,
                 const float* __restrict__ b1, const float* __restrict__ b2,
                 const float* __restrict__ b3, const float* __restrict__ Wf,
                 const float* __restrict__ bf, float* __restrict__ out) {
    extern __shared__ char sm[];
    const uint32_t sbase = smem_u32(sm);
    float* sb1 = (float*)(sm + FM_BIAS);
    float* sb2 = sb1 + 256;
    float* sb3 = sb2 + 128;
    float* swv = sb3 + 64;
    float* sbf = swv + 64;
    float* sSC = (float*)(sm + FM_SC);
    float* sSH = (float*)(sm + FM_SH);
    float* sred = (float*)(sm + FM_RED);

    const int tid = threadIdx.x;
    const int r0 = blockIdx.x * 128;

    if (tid < 256) sb1[tid] = b1[tid];
    else if (tid < 384) sb2[tid - 256] = b2[tid - 256];
    else if (tid < 448) sb3[tid - 384] = b3[tid - 384];
    else if (tid < 512) swv[tid - 448] = Wf[tid - 448];
    if (tid == 0) sbf[0] = bf[0];

    // ---- BN finalize (per-CTA redundant; fixed order) ----
    {
        int slot = tid & 63, seg = tid >> 6;
        float acc = 0.f;
        for (int b = seg * 32; b < seg * 32 + 32; b++)
            acc += g_bnpart[b][slot];
        sred[seg * 64 + slot] = acc;
    }
    __syncthreads();
    if (tid < 32) {
        float s = 0.f, s2 = 0.f;
#pragma unroll
        for (int c = 0; c < 8; c++) { s += sred[c * 64 + tid]; s2 += sred[c * 64 + 32 + tid]; }
        float mean = s * (1.0f / B_ROWS);
        float var  = s2 * (1.0f / B_ROWS) - mean * mean;
        if (tid < F0) {
            float sc = gamma[tid] * rsqrtf(var + BN_EPS);
            sSC[tid] = sc;
            sSH[tid] = beta[tid] - mean * sc;
        } else { sSC[tid] = 0.f; sSH[tid] = 0.f; }
    }
    __syncthreads();

    // ---- stage X tile: BN + bf16 split ----
    {
        int r = tid >> 2, q = tid & 3;
        float4 v0 = *(const float4*)&g_xbuf[(r0 + r) * 32 + q * 8];
        float4 v1 = *(const float4*)&g_xbuf[(r0 + r) * 32 + q * 8 + 4];
        float4 sc0 = *(const float4*)&sSC[q * 8];
        float4 sc1 = *(const float4*)&sSC[q * 8 + 4];
        float4 sh0 = *(const float4*)&sSH[q * 8];
        float4 sh1 = *(const float4*)&sSH[q * 8 + 4];
        float x0 = v0.x * sc0.x + sh0.x, x1 = v0.y * sc0.y + sh0.y;
        float x2 = v0.z * sc0.z + sh0.z, x3 = v0.w * sc0.w + sh0.w;
        float x4 = v1.x * sc1.x + sh1.x, x5 = v1.y * sc1.y + sh1.y;
        float x6 = v1.z * sc1.z + sh1.z, x7 = v1.w * sc1.w + sh1.w;
        uint4 uh, ul;
        split_pack(x0, x1, uh.x, ul.x);
        split_pack(x2, x3, uh.y, ul.y);
        split_pack(x4, x5, uh.z, ul.z);
        split_pack(x6, x7, uh.w, ul.w);
        *(uint4*)(sm + FM_XHI + r * 80 + q * 16) = uh;
        *(uint4*)(sm + FM_XLO + r * 80 + q * 16) = ul;
    }
    __syncthreads();

    const int wid = tid >> 5, lane = tid & 31;
    // ldmatrix per-lane row/col selector: m = lane>>3, row = lane&7
    const int lm_m   = lane >> 3;
    const int lm_row = (lane & 7) + ((lm_m & 1) << 3);   // row within 16-row frag
    const uint32_t lm_kadd = (uint32_t)(lm_m >> 1) * 16; // k-half byte offset

    // ================= layer 1: [128x32] x [32x256] =================
    {
        const int mg = wid & 3, ng = wid >> 2;
        float acc[2][8][4];
#pragma unroll
        for (int m = 0; m < 2; m++)
#pragma unroll
            for (int n = 0; n < 8; n++)
#pragma unroll
                for (int j = 0; j < 4; j++) acc[m][n][j] = 0.f;

        // per-thread ldmatrix row offsets (stride 80)
        uint32_t ro0 = (uint32_t)(mg * 32 + lm_row) * 80 + lm_kadd;
        uint32_t ro1 = (uint32_t)(mg * 32 + 16 + lm_row) * 80 + lm_kadd;

#pragma unroll
        for (int s = 0; s < 6; s++) {
            uint32_t ab = sbase + ((s >= 4) ? FM_XLO : FM_XHI) + (uint32_t)(s & 1) * 32;
            uint32_t a[2][4];
            ldsm_x4(a[0], ab + ro0);
            ldsm_x4(a[1], ab + ro1);
#pragma unroll
            for (int n = 0; n < 8; n++) {
                uint2 w = __ldg((const uint2*)&g_wf1[((s * 32 + ng * 8 + n) * 32 + lane) * 2]);
                mma_bf16(acc[0][n], a[0][0], a[0][1], a[0][2], a[0][3], w.x, w.y);
                mma_bf16(acc[1][n], a[1][0], a[1][1], a[1][2], a[1][3], w.x, w.y);
            }
        }

#pragma unroll
        for (int mt = 0; mt < 2; mt++) {
            int rr = mg * 32 + mt * 16 + (lane >> 2);
#pragma unroll
            for (int n = 0; n < 8; n++) {
                int c0 = ng * 64 + n * 8 + (lane & 3) * 2;
                float2 bb = *(const float2*)&sb1[c0];
                uint32_t hi, lo;
                float h0 = fmaxf(acc[mt][n][0] + bb.x, 0.f);
                float h1 = fmaxf(acc[mt][n][1] + bb.y, 0.f);
                split_pack(h0, h1, hi, lo);
                *(uint32_t*)(sm + FM_H1HI + rr * 528 + c0 * 2) = hi;
                *(uint32_t*)(sm + FM_H1LO + rr * 528 + c0 * 2) = lo;
                float h2 = fmaxf(acc[mt][n][2] + bb.x, 0.f);
                float h3 = fmaxf(acc[mt][n][3] + bb.y, 0.f);
                split_pack(h2, h3, hi, lo);
                *(uint32_t*)(sm + FM_H1HI + (rr + 8) * 528 + c0 * 2) = hi;
                *(uint32_t*)(sm + FM_H1LO + (rr + 8) * 528 + c0 * 2) = lo;
            }
        }
    }
    __syncthreads();

    // ================= layer 2: [128x256] x [256x128] =================
    {
        const int mg = wid & 3, ng = wid >> 2;
        float acc[2][4][4];
#pragma unroll
        for (int m = 0; m < 2; m++)
#pragma unroll
            for (int n = 0; n < 4; n++)
#pragma unroll
                for (int j = 0; j < 4; j++) acc[m][n][j] = 0.f;

        uint32_t ro0 = (uint32_t)(mg * 32 + lm_row) * 528 + lm_kadd;
        uint32_t ro1 = (uint32_t)(mg * 32 + 16 + lm_row) * 528 + lm_kadd;

#pragma unroll 6
        for (int cs = 0; cs < 48; cs++) {
            int chunk = cs / 6, s = cs % 6;
            uint32_t ab = sbase + ((s >= 4) ? FM_H1LO : FM_H1HI)
                        + (uint32_t)chunk * 64 + (uint32_t)(s & 1) * 32;
            uint32_t a[2][4];
            ldsm_x4(a[0], ab + ro0);
            ldsm_x4(a[1], ab + ro1);
#pragma unroll
            for (int n = 0; n < 4; n++) {
                uint2 w = __ldg((const uint2*)&g_wf2[((cs * 16 + ng * 4 + n) * 32 + lane) * 2]);
                mma_bf16(acc[0][n], a[0][0], a[0][1], a[0][2], a[0][3], w.x, w.y);
                mma_bf16(acc[1][n], a[1][0], a[1][1], a[1][2], a[1][3], w.x, w.y);
            }
        }

#pragma unroll
        for (int mt = 0; mt < 2; mt++) {
            int rr = mg * 32 + mt * 16 + (lane >> 2);
#pragma unroll
            for (int n = 0; n < 4; n++) {
                int col0 = ng * 32 + n * 8 + (lane & 3) * 2;
                float2 bb = *(const float2*)&sb2[col0];
                uint32_t hi, lo;
                float h0 = fmaxf(acc[mt][n][0] + bb.x, 0.f);
                float h1 = fmaxf(acc[mt][n][1] + bb.y, 0.f);
                split_pack(h0, h1, hi, lo);
                *(uint32_t*)(sm + FM_H2HI + rr * 272 + col0 * 2) = hi;
                *(uint32_t*)(sm + FM_H2LO + rr * 272 + col0 * 2) = lo;
                float h2 = fmaxf(acc[mt][n][2] + bb.x, 0.f);
                float h3 = fmaxf(acc[mt][n][3] + bb.y, 0.f);
                split_pack(h2, h3, hi, lo);
                *(uint32_t*)(sm + FM_H2HI + (rr + 8) * 272 + col0 * 2) = hi;
                *(uint32_t*)(sm + FM_H2LO + (rr + 8) * 272 + col0 * 2) = lo;
            }
        }
    }
    __syncthreads();

    // ================= layer 3 + head: warps 0..7 =================
    if (wid < 8) {
        const int mg = wid;
        float acc[8][4];
#pragma unroll
        for (int n = 0; n < 8; n++)
#pragma unroll
            for (int j = 0; j < 4; j++) acc[n][j] = 0.f;

        uint32_t ro = (uint32_t)(mg * 16 + lm_row) * 272 + lm_kadd;

#pragma unroll
        for (int s = 0; s < 24; s++) {
            int pass = s >> 3, kt = s & 7;
            uint32_t ab = sbase + ((pass == 2) ? FM_H2LO : FM_H2HI) + (uint32_t)kt * 32;
            uint32_t a[4];
            ldsm_x4(a, ab + ro);
#pragma unroll
            for (int n = 0; n < 8; n++) {
                uint2 w = __ldg((const uint2*)&g_wf3[((s * 8 + n) * 32 + lane) * 2]);
                mma_bf16(acc[n], a[0], a[1], a[2], a[3], w.x, w.y);
            }
        }

        float sum0 = 0.f, sum1 = 0.f;
#pragma unroll
        for (int n = 0; n < 8; n++) {
            int col0 = n * 8 + (lane & 3) * 2;
            float2 bb = *(const float2*)&sb3[col0];
            float2 wv = *(const float2*)&swv[col0];
            sum0 += fmaxf(acc[n][0] + bb.x, 0.f) * wv.x
                  + fmaxf(acc[n][1] + bb.y, 0.f) * wv.y;
            sum1 += fmaxf(acc[n][2] + bb.x, 0.f) * wv.x
                  + fmaxf(acc[n][3] + bb.y, 0.f) * wv.y;
        }
        sum0 += __shfl_xor_sync(0xffffffffu, sum0, 1);
        sum0 += __shfl_xor_sync(0xffffffffu, sum0, 2);
        sum1 += __shfl_xor_sync(0xffffffffu, sum1, 1);
        sum1 += __shfl_xor_sync(0xffffffffu, sum1, 2);
        if ((lane & 3) == 0) {
            int row = r0 + mg * 16 + (lane >> 2);
            float bfv = sbf[0];
            out[row]     = 1.f / (1.f + __expf(-(sum0 + bfv)));
            out[row + 8] = 1.f / (1.f + __expf(-(sum1 + bfv)));
        }
    }
}

// ---------------------------------------------------------------------------
extern "C" void kernel_launch(void* const* d_in, const int* in_sizes, int n_in,
                              void* d_out, int out_size) {
    const float* x_dense = (const float*)d_in[0];
    const void*  x_sparse = d_in[1];
    const float* emb   = (const float*)d_in[2];
    const float* gamma = (const float*)d_in[3];
    const float* beta  = (const float*)d_in[4];
    const float* W1 = (const float*)d_in[5];
    const float* b1 = (const float*)d_in[6];
    const float* W2 = (const float*)d_in[7];
    const float* b2 = (const float*)d_in[8];
    const float* W3 = (const float*)d_in[9];
    const float* b3 = (const float*)d_in[10];
    const float* Wf = (const float*)d_in[11];
    const float* bf = (const float*)d_in[12];
    float* out = (float*)d_out;

    static bool s_attr_done = false;
    if (!s_attr_done) {
        cudaFuncSetAttribute(fused_mlp_kernel,
                             cudaFuncAttributeMaxDynamicSharedMemorySize, FM_SMEM);
        s_attr_done = true;
    }

    front_kernel<<<328, 256>>>(x_sparse, x_dense, emb, W1, W2, W3);
    fused_mlp_kernel<<<B_ROWS / 128, 512, FM_SMEM>>>(gamma, beta, b1, b2, b3,
                                                     Wf, bf, out);
}

// round 10
// speedup vs baseline: 3.5176x; 1.0117x over previous
#include <cuda_runtime.h>
#include <cuda_bf16.h>
#include <math.h>
#include <stdint.h>

#define B_ROWS 16384
#define NSP 26
#define ND 13
#define VOCAB 100000
#define EMB_D 16
#define F0 29
#define BN_EPS 1e-5f

// ---------------------------------------------------------------------------
// Device scratch
// ---------------------------------------------------------------------------
__device__ float g_xbuf[B_ROWS * 32];
__device__ float g_bnpart[256][64];     // gather-block partials

// Fragment-ordered bf16x2-packed weights
__device__ uint32_t g_wf1[12288];
__device__ uint32_t g_wf2[49152];
__device__ uint32_t g_wf3[12288];

// ---------------------------------------------------------------------------
__device__ __forceinline__ void mma_bf16(float* c, uint32_t a0, uint32_t a1,
                                         uint32_t a2, uint32_t a3,
                                         uint32_t b0, uint32_t b1) {
    asm volatile(
        "mma.sync.aligned.m16n8k16.row.col.f32.bf16.bf16.f32 "
        "{%0,%1,%2,%3}, {%4,%5,%6,%7}, {%8,%9}, {%0,%1,%2,%3};"
        : "+f"(c[0]), "+f"(c[1]), "+f"(c[2]), "+f"(c[3])
        : "r"(a0), "r"(a1), "r"(a2), "r"(a3), "r"(b0), "r"(b1));
}

__device__ __forceinline__ void ldsm_x4(uint32_t* r, uint32_t addr) {
    asm volatile("ldmatrix.sync.aligned.m8n8.x4.shared.b16 {%0,%1,%2,%3}, [%4];"
                 : "=r"(r[0]), "=r"(r[1]), "=r"(r[2]), "=r"(r[3]) : "r"(addr));
}

__device__ __forceinline__ uint32_t smem_u32(const void* p) {
    uint32_t a;
    asm("{ .reg .u64 t; cvta.to.shared.u64 t, %1; cvt.u32.u64 %0, t; }"
        : "=r"(a) : "l"(p));
    return a;
}

__device__ __forceinline__ void split_pack(float h0, float h1,
                                           uint32_t& hi, uint32_t& lo) {
    __nv_bfloat16 b0 = __float2bfloat16(h0);
    __nv_bfloat16 b1 = __float2bfloat16(h1);
    float r0 = h0 - __bfloat162float(b0);
    float r1 = h1 - __bfloat162float(b1);
    __nv_bfloat16 c0 = __float2bfloat16(r0);
    __nv_bfloat16 c1 = __float2bfloat16(r1);
    hi = ((uint32_t)__bfloat16_as_ushort(b1) << 16) | (uint32_t)__bfloat16_as_ushort(b0);
    lo = ((uint32_t)__bfloat16_as_ushort(c1) << 16) | (uint32_t)__bfloat16_as_ushort(c0);
}

__device__ __forceinline__ unsigned short wpart_bf16(float w, bool lo_part) {
    __nv_bfloat16 h = __float2bfloat16(w);
    if (!lo_part) return __bfloat16_as_ushort(h);
    return __bfloat16_as_ushort(__float2bfloat16(w - __bfloat162float(h)));
}

// ---------------------------------------------------------------------------
__device__ __forceinline__ void prep_one(int e, const float* __restrict__ W1,
                                         const float* __restrict__ W2,
                                         const float* __restrict__ W3) {
    if (e < 12288) {
        int r = e & 1, lane = (e >> 1) & 31, nt = (e >> 6) & 31, s = e >> 11;
        bool wlo = (s == 2 || s == 3);
        int kt = s & 1;
        int k = kt * 16 + (lane & 3) * 2 + r * 8;
        int n = nt * 8 + (lane >> 2);
        float w0 = (k < F0)     ? W1[k * 256 + n]       : 0.f;
        float w1 = (k + 1 < F0) ? W1[(k + 1) * 256 + n] : 0.f;
        g_wf1[e] = ((uint32_t)wpart_bf16(w1, wlo) << 16) | wpart_bf16(w0, wlo);
    } else if (e < 61440) {
        int e2 = e - 12288;
        int r = e2 & 1, lane = (e2 >> 1) & 31, nt = (e2 >> 6) & 15, cs = e2 >> 10;
        int chunk = cs / 6, s = cs % 6;
        bool wlo = (s == 2 || s == 3);
        int kt = s & 1;
        int k = chunk * 32 + kt * 16 + (lane & 3) * 2 + r * 8;
        int n = nt * 8 + (lane >> 2);
        float w0 = W2[k * 128 + n];
        float w1 = W2[(k + 1) * 128 + n];
        g_wf2[e2] = ((uint32_t)wpart_bf16(w1, wlo) << 16) | wpart_bf16(w0, wlo);
    } else {
        int e3 = e - 61440;
        int r = e3 & 1, lane = (e3 >> 1) & 31, nt = (e3 >> 6) & 7, s = e3 >> 9;
        int pass = s >> 3, kt = s & 7;
        bool wlo = (pass == 1);
        int k = kt * 16 + (lane & 3) * 2 + r * 8;
        int n = nt * 8 + (lane >> 2);
        float w0 = W3[k * 64 + n];
        float w1 = W3[(k + 1) * 64 + n];
        g_wf3[e3] = ((uint32_t)wpart_bf16(w1, wlo) << 16) | wpart_bf16(w0, wlo);
    }
}

// ---------------------------------------------------------------------------
// front: blocks 0..255 gather+cross+BN-partials; 256..327 weight prep.
// ---------------------------------------------------------------------------
__global__ void front_kernel(const void* __restrict__ xsparse,
                             const float* __restrict__ xdense,
                             const float* __restrict__ emb,
                             const float* __restrict__ W1,
                             const float* __restrict__ W2,
                             const float* __restrict__ W3) {
    if (blockIdx.x >= 256) {
        int bb = blockIdx.x - 256;
#pragma unroll
        for (int i = 0; i < 4; i++)
            prep_one(bb * 1024 + i * 256 + threadIdx.x, W1, W2, W3);
        return;
    }

    __shared__ float swarp[8][4][16];
    __shared__ int s_is64;
    const int lt = threadIdx.x;
    const int* xs_i32 = (const int*)xsparse;

    if (lt < 32) {
        unsigned m = __ballot_sync(0xffffffffu, xs_i32[2 * lt + 1] != 0);
        if (lt == 0) s_is64 = (m == 0);
    }
    __syncthreads();
    const bool is64 = (s_is64 != 0);

    int tid = blockIdx.x * blockDim.x + lt;
    int r = tid >> 2;
    int q = tid & 3;

    const long long* xs64 = (const long long*)xsparse;

    float s0 = 0.f, s1 = 0.f, s2 = 0.f, s3 = 0.f;
    float q0 = 0.f, q1 = 0.f, q2 = 0.f, q3 = 0.f;

#pragma unroll
    for (int f = 0; f < NSP; f++) {
        long long idx = is64 ? xs64[r * NSP + f] : (long long)xs_i32[r * NSP + f];
        const float4 v = *(const float4*)(emb +
            ((size_t)f * VOCAB + (size_t)idx) * EMB_D + q * 4);
        s0 += v.x; s1 += v.y; s2 += v.z; s3 += v.w;
        q0 += v.x * v.x; q1 += v.y * v.y; q2 += v.z * v.z; q3 += v.w * v.w;
    }

    float4 cr;
    cr.x = 0.5f * (s0 * s0 - q0);
    cr.y = 0.5f * (s1 * s1 - q1);
    cr.z = 0.5f * (s2 * s2 - q2);
    cr.w = 0.5f * (s3 * s3 - q3);
    *(float4*)&g_xbuf[r * 32 + q * 4] = cr;

    int base = q * 4;
    float4 dv;
    dv.x = (base + 0 < ND) ? xdense[r * ND + base + 0] : 0.f;
    dv.y = (base + 1 < ND) ? xdense[r * ND + base + 1] : 0.f;
    dv.z = (base + 2 < ND) ? xdense[r * ND + base + 2] : 0.f;
    dv.w = (base + 3 < ND) ? xdense[r * ND + base + 3] : 0.f;
    *(float4*)&g_xbuf[r * 32 + 16 + q * 4] = dv;

    float st[16];
    st[0] = cr.x; st[1] = cr.y; st[2] = cr.z; st[3] = cr.w;
    st[4] = cr.x * cr.x; st[5] = cr.y * cr.y; st[6] = cr.z * cr.z; st[7] = cr.w * cr.w;
    st[8] = dv.x; st[9] = dv.y; st[10] = dv.z; st[11] = dv.w;
    st[12] = dv.x * dv.x; st[13] = dv.y * dv.y; st[14] = dv.z * dv.z; st[15] = dv.w * dv.w;
#pragma unroll
    for (int j = 0; j < 16; j++) {
        st[j] += __shfl_xor_sync(0xffffffffu, st[j], 4);
        st[j] += __shfl_xor_sync(0xffffffffu, st[j], 8);
        st[j] += __shfl_xor_sync(0xffffffffu, st[j], 16);
    }
    int wid = lt >> 5, lane = lt & 31;
    if (lane < 4) {
#pragma unroll
        for (int j = 0; j < 16; j++) swarp[wid][lane][j] = st[j];
    }
    __syncthreads();
    if (lt < 64) {
        int qq = lt >> 4, j = lt & 15;
        float acc = 0.f;
#pragma unroll
        for (int w = 0; w < 8; w++) acc += swarp[w][qq][j];
        int col, slot;
        if (j < 4)       { col = qq * 4 + j;          slot = col; }
        else if (j < 8)  { col = qq * 4 + (j - 4);    slot = 32 + col; }
        else if (j < 12) { col = 16 + qq * 4 + (j - 8);  slot = col; }
        else             { col = 16 + qq * 4 + (j - 12); slot = 32 + col; }
        g_bnpart[blockIdx.x][slot] = acc;
    }
}

// ---------------------------------------------------------------------------
// Fused MLP: 64 rows / CTA, 256 threads, 2 CTAs per SM.
// ---------------------------------------------------------------------------
#define FM_H1HI  0            // 64*528 = 33792
#define FM_H1LO  33792        // -> 67584
#define FM_XHI   67584        // 5120 (dead after layer 1)
#define FM_XLO   72704        // 5120
#define FM_H2HI  67584        // 17408 (aliases X)
#define FM_H2LO  84992        // 17408 -> 102400
#define FM_BIAS  102400       // b1[256] b2[128] b3[64] wf[64] bf[1] = 2052B
#define FM_SC    104576
#define FM_SH    104704
#define FM_RED   104832       // 4*64 floats = 1024
#define FM_SMEM  105856

__global__ void __launch_bounds__(256, 2)
fused_mlp_kernel(const float* __restrict__ gamma, const float* __restrict__ beta,
                 const float* __restrict__ b1, const float* __restrict__ b2,
                 const float* __restrict__ b3, const float* __restrict__ Wf,
                 const float* __restrict__ bf, float* __restrict__ out) {
    extern __shared__ char sm[];
    const uint32_t sbase = smem_u32(sm);
    float* sb1 = (float*)(sm + FM_BIAS);
    float* sb2 = sb1 + 256;
    float* sb3 = sb2 + 128;
    float* swv = sb3 + 64;
    float* sbf = swv + 64;
    float* sSC = (float*)(sm + FM_SC);
    float* sSH = (float*)(sm + FM_SH);
    float* sred = (float*)(sm + FM_RED);   // [4][64]

    const int tid = threadIdx.x;
    const int r0 = blockIdx.x * 64;

    if (tid < 256) sb1[tid] = b1[tid];
    if (tid < 128) sb2[tid] = b2[tid];
    else if (tid < 192) sb3[tid - 128] = b3[tid - 128];
    else { swv[tid - 192] = Wf[tid - 192]; }
    if (tid == 0) sbf[0] = bf[0];

    // ---- BN finalize (per-CTA redundant; fixed order) ----
    {
        int slot = tid & 63, seg = tid >> 6;           // 4 segs x 64 blocks
        float acc = 0.f;
        for (int b = seg * 64; b < seg * 64 + 64; b++)
            acc += g_bnpart[b][slot];
        sred[seg * 64 + slot] = acc;
    }
    __syncthreads();
    if (tid < 32) {
        float s = 0.f, s2 = 0.f;
#pragma unroll
        for (int c = 0; c < 4; c++) { s += sred[c * 64 + tid]; s2 += sred[c * 64 + 32 + tid]; }
        float mean = s * (1.0f / B_ROWS);
        float var  = s2 * (1.0f / B_ROWS) - mean * mean;
        if (tid < F0) {
            float sc = gamma[tid] * rsqrtf(var + BN_EPS);
            sSC[tid] = sc;
            sSH[tid] = beta[tid] - mean * sc;
        } else { sSC[tid] = 0.f; sSH[tid] = 0.f; }
    }
    __syncthreads();

    // ---- stage X tile: 64 rows, 1 quad per thread ----
    {
        int r = tid >> 2, q = tid & 3;
        float4 v0 = *(const float4*)&g_xbuf[(r0 + r) * 32 + q * 8];
        float4 v1 = *(const float4*)&g_xbuf[(r0 + r) * 32 + q * 8 + 4];
        float4 sc0 = *(const float4*)&sSC[q * 8];
        float4 sc1 = *(const float4*)&sSC[q * 8 + 4];
        float4 sh0 = *(const float4*)&sSH[q * 8];
        float4 sh1 = *(const float4*)&sSH[q * 8 + 4];
        float x0 = v0.x * sc0.x + sh0.x, x1 = v0.y * sc0.y + sh0.y;
        float x2 = v0.z * sc0.z + sh0.z, x3 = v0.w * sc0.w + sh0.w;
        float x4 = v1.x * sc1.x + sh1.x, x5 = v1.y * sc1.y + sh1.y;
        float x6 = v1.z * sc1.z + sh1.z, x7 = v1.w * sc1.w + sh1.w;
        uint4 uh, ul;
        split_pack(x0, x1, uh.x, ul.x);
        split_pack(x2, x3, uh.y, ul.y);
        split_pack(x4, x5, uh.z, ul.z);
        split_pack(x6, x7, uh.w, ul.w);
        *(uint4*)(sm + FM_XHI + r * 80 + q * 16) = uh;
        *(uint4*)(sm + FM_XLO + r * 80 + q * 16) = ul;
    }
    __syncthreads();

    const int wid = tid >> 5, lane = tid & 31;
    const int lm_m   = lane >> 3;
    const int lm_row = (lane & 7) + ((lm_m & 1) << 3);
    const uint32_t lm_kadd = (uint32_t)(lm_m >> 1) * 16;

    // ================= layer 1: [64x32] x [32x256] =================
    {
        const int mg = wid & 1, ng = wid >> 1;          // 2 x 4 warp grid
        float acc[2][8][4];
#pragma unroll
        for (int m = 0; m < 2; m++)
#pragma unroll
            for (int n = 0; n < 8; n++)
#pragma unroll
                for (int j = 0; j < 4; j++) acc[m][n][j] = 0.f;

        uint32_t ro0 = (uint32_t)(mg * 32 + lm_row) * 80 + lm_kadd;
        uint32_t ro1 = (uint32_t)(mg * 32 + 16 + lm_row) * 80 + lm_kadd;

        uint2 w = __ldg((const uint2*)&g_wf1[((0 * 32 + ng * 8 + 0) * 32 + lane) * 2]);
#pragma unroll
        for (int s = 0; s < 6; s++) {
            uint32_t ab = sbase + ((s >= 4) ? FM_XLO : FM_XHI) + (uint32_t)(s & 1) * 32;
            uint32_t a[2][4];
            ldsm_x4(a[0], ab + ro0);
            ldsm_x4(a[1], ab + ro1);
#pragma unroll
            for (int n = 0; n < 8; n++) {
                uint2 wc = w;
                if (!(s == 5 && n == 7)) {
                    int sn = (n == 7) ? s + 1 : s, nn = (n == 7) ? 0 : n + 1;
                    w = __ldg((const uint2*)&g_wf1[((sn * 32 + ng * 8 + nn) * 32 + lane) * 2]);
                }
                mma_bf16(acc[0][n], a[0][0], a[0][1], a[0][2], a[0][3], wc.x, wc.y);
                mma_bf16(acc[1][n], a[1][0], a[1][1], a[1][2], a[1][3], wc.x, wc.y);
            }
        }

#pragma unroll
        for (int mt = 0; mt < 2; mt++) {
            int rr = mg * 32 + mt * 16 + (lane >> 2);
#pragma unroll
            for (int n = 0; n < 8; n++) {
                int c0 = ng * 64 + n * 8 + (lane & 3) * 2;
                float2 bb = *(const float2*)&sb1[c0];
                uint32_t hi, lo;
                float h0 = fmaxf(acc[mt][n][0] + bb.x, 0.f);
                float h1 = fmaxf(acc[mt][n][1] + bb.y, 0.f);
                split_pack(h0, h1, hi, lo);
                *(uint32_t*)(sm + FM_H1HI + rr * 528 + c0 * 2) = hi;
                *(uint32_t*)(sm + FM_H1LO + rr * 528 + c0 * 2) = lo;
                float h2 = fmaxf(acc[mt][n][2] + bb.x, 0.f);
                float h3 = fmaxf(acc[mt][n][3] + bb.y, 0.f);
                split_pack(h2, h3, hi, lo);
                *(uint32_t*)(sm + FM_H1HI + (rr + 8) * 528 + c0 * 2) = hi;
                *(uint32_t*)(sm + FM_H1LO + (rr + 8) * 528 + c0 * 2) = lo;
            }
        }
    }
    __syncthreads();

    // ================= layer 2: [64x256] x [256x128] =================
    {
        const int mg = wid & 1, ng = wid >> 1;          // 2 x 4 warp grid
        float acc[2][4][4];
#pragma unroll
        for (int m = 0; m < 2; m++)
#pragma unroll
            for (int n = 0; n < 4; n++)
#pragma unroll
                for (int j = 0; j < 4; j++) acc[m][n][j] = 0.f;

        uint32_t ro0 = (uint32_t)(mg * 32 + lm_row) * 528 + lm_kadd;
        uint32_t ro1 = (uint32_t)(mg * 32 + 16 + lm_row) * 528 + lm_kadd;

        // prefetch cs=0 weights
        uint2 w[4];
#pragma unroll
        for (int n = 0; n < 4; n++)
            w[n] = __ldg((const uint2*)&g_wf2[((0 * 16 + ng * 4 + n) * 32 + lane) * 2]);

#pragma unroll 6
        for (int cs = 0; cs < 48; cs++) {
            int chunk = cs / 6, s = cs % 6;
            uint32_t ab = sbase + ((s >= 4) ? FM_H1LO : FM_H1HI)
                        + (uint32_t)chunk * 64 + (uint32_t)(s & 1) * 32;
            uint32_t a[2][4];
            ldsm_x4(a[0], ab + ro0);
            ldsm_x4(a[1], ab + ro1);
            uint2 wn[4];
            if (cs < 47) {
#pragma unroll
                for (int n = 0; n < 4; n++)
                    wn[n] = __ldg((const uint2*)&g_wf2[(((cs + 1) * 16 + ng * 4 + n) * 32 + lane) * 2]);
            }
#pragma unroll
            for (int n = 0; n < 4; n++) {
                mma_bf16(acc[0][n], a[0][0], a[0][1], a[0][2], a[0][3], w[n].x, w[n].y);
                mma_bf16(acc[1][n], a[1][0], a[1][1], a[1][2], a[1][3], w[n].x, w[n].y);
            }
#pragma unroll
            for (int n = 0; n < 4; n++) w[n] = wn[n];
        }

#pragma unroll
        for (int mt = 0; mt < 2; mt++) {
            int rr = mg * 32 + mt * 16 + (lane >> 2);
#pragma unroll
            for (int n = 0; n < 4; n++) {
                int col0 = ng * 32 + n * 8 + (lane & 3) * 2;
                float2 bb = *(const float2*)&sb2[col0];
                uint32_t hi, lo;
                float h0 = fmaxf(acc[mt][n][0] + bb.x, 0.f);
                float h1 = fmaxf(acc[mt][n][1] + bb.y, 0.f);
                split_pack(h0, h1, hi, lo);
                *(uint32_t*)(sm + FM_H2HI + rr * 272 + col0 * 2) = hi;
                *(uint32_t*)(sm + FM_H2LO + rr * 272 + col0 * 2) = lo;
                float h2 = fmaxf(acc[mt][n][2] + bb.x, 0.f);
                float h3 = fmaxf(acc[mt][n][3] + bb.y, 0.f);
                split_pack(h2, h3, hi, lo);
                *(uint32_t*)(sm + FM_H2HI + (rr + 8) * 272 + col0 * 2) = hi;
                *(uint32_t*)(sm + FM_H2LO + (rr + 8) * 272 + col0 * 2) = lo;
            }
        }
    }
    __syncthreads();

    // ================= layer 3 + head: warps 0..3 =================
    if (wid < 4) {
        const int mg = wid;
        float acc[8][4];
#pragma unroll
        for (int n = 0; n < 8; n++)
#pragma unroll
            for (int j = 0; j < 4; j++) acc[n][j] = 0.f;

        uint32_t ro = (uint32_t)(mg * 16 + lm_row) * 272 + lm_kadd;

        uint2 w = __ldg((const uint2*)&g_wf3[((0 * 8 + 0) * 32 + lane) * 2]);
#pragma unroll
        for (int s = 0; s < 24; s++) {
            int pass = s >> 3, kt = s & 7;
            uint32_t ab = sbase + ((pass == 2) ? FM_H2LO : FM_H2HI) + (uint32_t)kt * 32;
            uint32_t a[4];
            ldsm_x4(a, ab + ro);
#pragma unroll
            for (int n = 0; n < 8; n++) {
                uint2 wc = w;
                if (!(s == 23 && n == 7)) {
                    int sn = (n == 7) ? s + 1 : s, nn = (n == 7) ? 0 : n + 1;
                    w = __ldg((const uint2*)&g_wf3[((sn * 8 + nn) * 32 + lane) * 2]);
                }
                mma_bf16(acc[n], a[0], a[1], a[2], a[3], wc.x, wc.y);
            }
        }

        float sum0 = 0.f, sum1 = 0.f;
#pragma unroll
        for (int n = 0; n < 8; n++) {
            int col0 = n * 8 + (lane & 3) * 2;
            float2 bb = *(const float2*)&sb3[col0];
            float2 wv = *(const float2*)&swv[col0];
            sum0 += fmaxf(acc[n][0] + bb.x, 0.f) * wv.x
                  + fmaxf(acc[n][1] + bb.y, 0.f) * wv.y;
            sum1 += fmaxf(acc[n][2] + bb.x, 0.f) * wv.x
                  + fmaxf(acc[n][3] + bb.y, 0.f) * wv.y;
        }
        sum0 += __shfl_xor_sync(0xffffffffu, sum0, 1);
        sum0 += __shfl_xor_sync(0xffffffffu, sum0, 2);
        sum1 += __shfl_xor_sync(0xffffffffu, sum1, 1);
        sum1 += __shfl_xor_sync(0xffffffffu, sum1, 2);
        if ((lane & 3) == 0) {
            int row = r0 + mg * 16 + (lane >> 2);
            float bfv = sbf[0];
            out[row]     = 1.f / (1.f + __expf(-(sum0 + bfv)));
            out[row + 8] = 1.f / (1.f + __expf(-(sum1 + bfv)));
        }
    }
}

// ---------------------------------------------------------------------------
extern "C" void kernel_launch(void* const* d_in, const int* in_sizes, int n_in,
                              void* d_out, int out_size) {
    const float* x_dense = (const float*)d_in[0];
    const void*  x_sparse = d_in[1];
    const float* emb   = (const float*)d_in[2];
    const float* gamma = (const float*)d_in[3];
    const float* beta  = (const float*)d_in[4];
    const float* W1 = (const float*)d_in[5];
    const float* b1 = (const float*)d_in[6];
    const float* W2 = (const float*)d_in[7];
    const float* b2 = (const float*)d_in[8];
    const float* W3 = (const float*)d_in[9];
    const float* b3 = (const float*)d_in[10];
    const float* Wf = (const float*)d_in[11];
    const float* bf = (const float*)d_in[12];
    float* out = (float*)d_out;

    static bool s_attr_done = false;
    if (!s_attr_done) {
        cudaFuncSetAttribute(fused_mlp_kernel,
                             cudaFuncAttributeMaxDynamicSharedMemorySize, FM_SMEM);
        s_attr_done = true;
    }

    front_kernel<<<328, 256>>>(x_sparse, x_dense, emb, W1, W2, W3);
    fused_mlp_kernel<<<B_ROWS / 64, 256, FM_SMEM>>>(gamma, beta, b1, b2, b3,
                                                    Wf, bf, out);
}

// round 11
// speedup vs baseline: 5.1902x; 1.4755x over previous
#include <cuda_runtime.h>
#include <cuda_fp16.h>
#include <math.h>
#include <stdint.h>

#define B_ROWS 16384
#define NSP 26
#define ND 13
#define VOCAB 100000
#define EMB_D 16
#define F0 29
#define BN_EPS 1e-5f

// ---------------------------------------------------------------------------
// Device scratch
// ---------------------------------------------------------------------------
__device__ float g_bnpart[256][64];
__device__ unsigned int g_ticket;       // never reset; cohort = ticket & ~255

// Fragment-ordered fp16x2-packed weights
__device__ uint32_t g_wf1[12288];       // layer1 3-term [s6][nt32][lane][2]
__device__ uint32_t g_wf2[16384];       // layer2 single [kt16][nt16][lane][2]
__device__ uint32_t g_wf3[4096];        // layer3 single [kt8][nt8][lane][2]

// ---------------------------------------------------------------------------
__device__ __forceinline__ void mma_f16(float* c, uint32_t a0, uint32_t a1,
                                        uint32_t a2, uint32_t a3,
                                        uint32_t b0, uint32_t b1) {
    asm volatile(
        "mma.sync.aligned.m16n8k16.row.col.f32.f16.f16.f32 "
        "{%0,%1,%2,%3}, {%4,%5,%6,%7}, {%8,%9}, {%0,%1,%2,%3};"
        : "+f"(c[0]), "+f"(c[1]), "+f"(c[2]), "+f"(c[3])
        : "r"(a0), "r"(a1), "r"(a2), "r"(a3), "r"(b0), "r"(b1));
}

__device__ __forceinline__ void ldsm_x4(uint32_t* r, uint32_t addr) {
    asm volatile("ldmatrix.sync.aligned.m8n8.x4.shared.b16 {%0,%1,%2,%3}, [%4];"
                 : "=r"(r[0]), "=r"(r[1]), "=r"(r[2]), "=r"(r[3]) : "r"(addr));
}

__device__ __forceinline__ uint32_t smem_u32(const void* p) {
    uint32_t a;
    asm("{ .reg .u64 t; cvta.to.shared.u64 t, %1; cvt.u32.u64 %0, t; }"
        : "=r"(a) : "l"(p));
    return a;
}

__device__ __forceinline__ uint32_t pack_h2(float a, float b) {
    __half2 h = __floats2half2_rn(a, b);
    return *(uint32_t*)&h;
}

__device__ __forceinline__ void split_pack_h(float h0, float h1,
                                             uint32_t& hi, uint32_t& lo) {
    __half a0 = __float2half_rn(h0);
    __half a1 = __float2half_rn(h1);
    __half c0 = __float2half_rn(h0 - __half2float(a0));
    __half c1 = __float2half_rn(h1 - __half2float(a1));
    hi = ((uint32_t)__half_as_ushort(a1) << 16) | __half_as_ushort(a0);
    lo = ((uint32_t)__half_as_ushort(c1) << 16) | __half_as_ushort(c0);
}

__device__ __forceinline__ unsigned short wpart_f16(float w, bool lo_part) {
    __half h = __float2half_rn(w);
    if (!lo_part) return __half_as_ushort(h);
    return __half_as_ushort(__float2half_rn(w - __half2float(h)));
}

// ---------------------------------------------------------------------------
// weight prep (fragment order), 32768 elements total, 128 per CTA
// ---------------------------------------------------------------------------
__device__ __forceinline__ void prep_one(int e, const float* __restrict__ W1,
                                         const float* __restrict__ W2,
                                         const float* __restrict__ W3) {
    if (e < 12288) {                       // layer1 3-term, K=32(pad), N=256
        int r = e & 1, lane = (e >> 1) & 31, nt = (e >> 6) & 31, s = e >> 11;
        bool wlo = (s == 2 || s == 3);
        int kt = s & 1;
        int k = kt * 16 + (lane & 3) * 2 + r * 8;
        int n = nt * 8 + (lane >> 2);
        float w0 = (k < F0)     ? W1[k * 256 + n]       : 0.f;
        float w1 = (k + 1 < F0) ? W1[(k + 1) * 256 + n] : 0.f;
        g_wf1[e] = ((uint32_t)wpart_f16(w1, wlo) << 16) | wpart_f16(w0, wlo);
    } else if (e < 28672) {                // layer2 single, K=256, N=128
        int e2 = e - 12288;
        int r = e2 & 1, lane = (e2 >> 1) & 31, nt = (e2 >> 6) & 15, kt = e2 >> 10;
        int k = kt * 16 + (lane & 3) * 2 + r * 8;
        int n = nt * 8 + (lane >> 2);
        float w0 = W2[k * 128 + n];
        float w1 = W2[(k + 1) * 128 + n];
        g_wf2[e2] = ((uint32_t)wpart_f16(w1, false) << 16) | wpart_f16(w0, false);
    } else {                               // layer3 single, K=128, N=64
        int e3 = e - 28672;
        int r = e3 & 1, lane = (e3 >> 1) & 31, nt = (e3 >> 6) & 7, kt = e3 >> 9;
        int k = kt * 16 + (lane & 3) * 2 + r * 8;
        int n = nt * 8 + (lane >> 2);
        float w0 = W3[k * 64 + n];
        float w1 = W3[(k + 1) * 64 + n];
        g_wf3[e3] = ((uint32_t)wpart_f16(w1, false) << 16) | wpart_f16(w0, false);
    }
}

// ---------------------------------------------------------------------------
// SMEM layout per CTA (64 rows). H2 aliases XRAW/XHI/XLO (dead after layer 1).
// ---------------------------------------------------------------------------
#define FM_H1    0            // 64*528 = 33792   (fp16, stride 528B)
#define FM_XRAW  33792        // 64*128 = 8192
#define FM_XHI   41984        // 64*80  = 5120
#define FM_XLO   47104        // 5120 -> 52224
#define FM_H2    33792        // 64*272 = 17408 -> 51200 (alias)
#define FM_BIAS  52224        // b1[256] b2[128] b3[64] wf[64] bf[1]
#define FM_SC    54288
#define FM_SH    54416
#define FM_RED   54544        // 4*64*4 = 1024
#define FM_SMEM  55568

__global__ void __launch_bounds__(256, 2)
nfm_kernel(const void* __restrict__ xsparse, const float* __restrict__ xdense,
           const float* __restrict__ emb,
           const float* __restrict__ W1, const float* __restrict__ b1,
           const float* __restrict__ W2, const float* __restrict__ b2,
           const float* __restrict__ W3, const float* __restrict__ b3,
           const float* __restrict__ Wf, const float* __restrict__ bf,
           const float* __restrict__ gamma, const float* __restrict__ beta,
           float* __restrict__ out) {
    extern __shared__ char sm[];
    const uint32_t sbase = smem_u32(sm);
    float* sb1 = (float*)(sm + FM_BIAS);
    float* sb2 = sb1 + 256;
    float* sb3 = sb2 + 128;
    float* swv = sb3 + 64;
    float* sbf = swv + 64;
    float* sSC = (float*)(sm + FM_SC);
    float* sSH = (float*)(sm + FM_SH);
    float* sred = (float*)(sm + FM_RED);
    float* swarp = (float*)(sm + FM_H1);   // reuse H1 region during gather

    __shared__ int s_is64;

    const int tid = threadIdx.x;
    const int r0 = blockIdx.x * 64;

    // ---- idx-width detect ----
    const int* xs_i32 = (const int*)xsparse;
    if (tid < 32) {
        unsigned m = __ballot_sync(0xffffffffu, xs_i32[2 * tid + 1] != 0);
        if (tid == 0) s_is64 = (m == 0);
    }
    __syncthreads();
    const bool is64 = (s_is64 != 0);

    // ---- gather + FM cross: 4 threads per row, 64 rows ----
    const long long* xs64 = (const long long*)xsparse;
    const int rloc = tid >> 2, q = tid & 3;
    const int rg = r0 + rloc;

    float s0 = 0.f, s1 = 0.f, s2 = 0.f, s3 = 0.f;
    float q0 = 0.f, q1 = 0.f, q2 = 0.f, q3 = 0.f;
#pragma unroll
    for (int f = 0; f < NSP; f++) {
        long long idx = is64 ? xs64[rg * NSP + f] : (long long)xs_i32[rg * NSP + f];
        const float4 v = *(const float4*)(emb +
            ((size_t)f * VOCAB + (size_t)idx) * EMB_D + q * 4);
        s0 += v.x; s1 += v.y; s2 += v.z; s3 += v.w;
        q0 += v.x * v.x; q1 += v.y * v.y; q2 += v.z * v.z; q3 += v.w * v.w;
    }
    float4 cr;
    cr.x = 0.5f * (s0 * s0 - q0);
    cr.y = 0.5f * (s1 * s1 - q1);
    cr.z = 0.5f * (s2 * s2 - q2);
    cr.w = 0.5f * (s3 * s3 - q3);
    int base = q * 4;
    float4 dv;
    dv.x = (base + 0 < ND) ? xdense[rg * ND + base + 0] : 0.f;
    dv.y = (base + 1 < ND) ? xdense[rg * ND + base + 1] : 0.f;
    dv.z = (base + 2 < ND) ? xdense[rg * ND + base + 2] : 0.f;
    dv.w = (base + 3 < ND) ? xdense[rg * ND + base + 3] : 0.f;

    *(float4*)(sm + FM_XRAW + rloc * 128 + q * 16) = cr;
    *(float4*)(sm + FM_XRAW + rloc * 128 + 64 + q * 16) = dv;

    // ---- BN partials (shuffle tree; swarp aliases H1 region) ----
    {
        float st[16];
        st[0] = cr.x; st[1] = cr.y; st[2] = cr.z; st[3] = cr.w;
        st[4] = cr.x * cr.x; st[5] = cr.y * cr.y; st[6] = cr.z * cr.z; st[7] = cr.w * cr.w;
        st[8] = dv.x; st[9] = dv.y; st[10] = dv.z; st[11] = dv.w;
        st[12] = dv.x * dv.x; st[13] = dv.y * dv.y; st[14] = dv.z * dv.z; st[15] = dv.w * dv.w;
#pragma unroll
        for (int j = 0; j < 16; j++) {
            st[j] += __shfl_xor_sync(0xffffffffu, st[j], 4);
            st[j] += __shfl_xor_sync(0xffffffffu, st[j], 8);
            st[j] += __shfl_xor_sync(0xffffffffu, st[j], 16);
        }
        int wd = tid >> 5, lane = tid & 31;
        if (lane < 4) {
#pragma unroll
            for (int j = 0; j < 16; j++) swarp[(wd * 4 + lane) * 16 + j] = st[j];
        }
        __syncthreads();
        if (tid < 64) {
            int qq = tid >> 4, j = tid & 15;
            float acc = 0.f;
#pragma unroll
            for (int w = 0; w < 8; w++) acc += swarp[(w * 4 + qq) * 16 + j];
            int col, slot;
            if (j < 4)       { col = qq * 4 + j;          slot = col; }
            else if (j < 8)  { col = qq * 4 + (j - 4);    slot = 32 + col; }
            else if (j < 12) { col = 16 + qq * 4 + (j - 8);  slot = col; }
            else             { col = 16 + qq * 4 + (j - 12); slot = 32 + col; }
            g_bnpart[blockIdx.x][slot] = acc;
        }
    }

    // ---- weight prep: 128 elements per CTA ----
    if (tid < 128) prep_one(blockIdx.x * 128 + tid, W1, W2, W3);

    // ---- biases (read-only inputs) ----
    if (tid < 256) sb1[tid] = b1[tid];
    if (tid < 128) sb2[tid] = b2[tid];
    else if (tid < 192) sb3[tid - 128] = b3[tid - 128];
    else swv[tid - 192] = Wf[tid - 192];
    if (tid == 0) sbf[0] = bf[0];

    // ---- device-wide ticket barrier (all 256 CTAs co-resident) ----
    __threadfence();
    __syncthreads();
    if (tid == 0) {
        unsigned t = atomicAdd(&g_ticket, 1u);
        unsigned target = (t & ~255u) + 256u;
        unsigned v;
        do {
            asm volatile("ld.acquire.gpu.global.u32 %0, [%1];"
                         : "=r"(v) : "l"(&g_ticket) : "memory");
        } while (v < target);
    }
    __syncthreads();

    // ---- BN finalize (per-CTA redundant; fixed order) ----
    {
        int slot = tid & 63, seg = tid >> 6;
        float acc = 0.f;
        for (int b = seg * 64; b < seg * 64 + 64; b++)
            acc += __ldcg(&g_bnpart[b][slot]);
        sred[seg * 64 + slot] = acc;
    }
    __syncthreads();
    if (tid < 32) {
        float s = 0.f, s2 = 0.f;
#pragma unroll
        for (int c = 0; c < 4; c++) { s += sred[c * 64 + tid]; s2 += sred[c * 64 + 32 + tid]; }
        float mean = s * (1.0f / B_ROWS);
        float var  = s2 * (1.0f / B_ROWS) - mean * mean;
        if (tid < F0) {
            float sc = gamma[tid] * rsqrtf(var + BN_EPS);
            sSC[tid] = sc;
            sSH[tid] = beta[tid] - mean * sc;
        } else { sSC[tid] = 0.f; sSH[tid] = 0.f; }
    }
    __syncthreads();

    // ---- stage X: BN + fp16 split (hi/lo) ----
    {
        float4 v0 = *(const float4*)(sm + FM_XRAW + rloc * 128 + q * 32);
        float4 v1 = *(const float4*)(sm + FM_XRAW + rloc * 128 + q * 32 + 16);
        float4 sc0 = *(const float4*)&sSC[q * 8];
        float4 sc1 = *(const float4*)&sSC[q * 8 + 4];
        float4 sh0 = *(const float4*)&sSH[q * 8];
        float4 sh1 = *(const float4*)&sSH[q * 8 + 4];
        float x0 = v0.x * sc0.x + sh0.x, x1 = v0.y * sc0.y + sh0.y;
        float x2 = v0.z * sc0.z + sh0.z, x3 = v0.w * sc0.w + sh0.w;
        float x4 = v1.x * sc1.x + sh1.x, x5 = v1.y * sc1.y + sh1.y;
        float x6 = v1.z * sc1.z + sh1.z, x7 = v1.w * sc1.w + sh1.w;
        uint4 uh, ul;
        split_pack_h(x0, x1, uh.x, ul.x);
        split_pack_h(x2, x3, uh.y, ul.y);
        split_pack_h(x4, x5, uh.z, ul.z);
        split_pack_h(x6, x7, uh.w, ul.w);
        *(uint4*)(sm + FM_XHI + rloc * 80 + q * 16) = uh;
        *(uint4*)(sm + FM_XLO + rloc * 80 + q * 16) = ul;
    }
    __syncthreads();

    const int wid = tid >> 5, lane = tid & 31;
    const int lm_m   = lane >> 3;
    const int lm_row = (lane & 7) + ((lm_m & 1) << 3);
    const uint32_t lm_kadd = (uint32_t)(lm_m >> 1) * 16;

    // ================= layer 1 (3-term fp16): [64x32] x [32x256] =========
    {
        const int mg = wid & 1, ng = wid >> 1;
        float acc[2][8][4];
#pragma unroll
        for (int m = 0; m < 2; m++)
#pragma unroll
            for (int n = 0; n < 8; n++)
#pragma unroll
                for (int j = 0; j < 4; j++) acc[m][n][j] = 0.f;

        uint32_t ro0 = (uint32_t)(mg * 32 + lm_row) * 80 + lm_kadd;
        uint32_t ro1 = (uint32_t)(mg * 32 + 16 + lm_row) * 80 + lm_kadd;

#pragma unroll
        for (int s = 0; s < 6; s++) {
            uint32_t ab = sbase + ((s >= 4) ? FM_XLO : FM_XHI) + (uint32_t)(s & 1) * 32;
            uint32_t a[2][4];
            ldsm_x4(a[0], ab + ro0);
            ldsm_x4(a[1], ab + ro1);
#pragma unroll
            for (int n = 0; n < 8; n++) {
                uint2 w = __ldcg((const uint2*)&g_wf1[((s * 32 + ng * 8 + n) * 32 + lane) * 2]);
                mma_f16(acc[0][n], a[0][0], a[0][1], a[0][2], a[0][3], w.x, w.y);
                mma_f16(acc[1][n], a[1][0], a[1][1], a[1][2], a[1][3], w.x, w.y);
            }
        }

#pragma unroll
        for (int mt = 0; mt < 2; mt++) {
            int rr = mg * 32 + mt * 16 + (lane >> 2);
#pragma unroll
            for (int n = 0; n < 8; n++) {
                int c0 = ng * 64 + n * 8 + (lane & 3) * 2;
                float2 bb = *(const float2*)&sb1[c0];
                float h0 = fmaxf(acc[mt][n][0] + bb.x, 0.f);
                float h1 = fmaxf(acc[mt][n][1] + bb.y, 0.f);
                *(uint32_t*)(sm + FM_H1 + rr * 528 + c0 * 2) = pack_h2(h0, h1);
                float h2 = fmaxf(acc[mt][n][2] + bb.x, 0.f);
                float h3 = fmaxf(acc[mt][n][3] + bb.y, 0.f);
                *(uint32_t*)(sm + FM_H1 + (rr + 8) * 528 + c0 * 2) = pack_h2(h2, h3);
            }
        }
    }
    __syncthreads();

    // ================= layer 2 (single fp16): [64x256] x [256x128] ========
    {
        const int mg = wid & 1, ng = wid >> 1;
        float acc[2][4][4];
#pragma unroll
        for (int m = 0; m < 2; m++)
#pragma unroll
            for (int n = 0; n < 4; n++)
#pragma unroll
                for (int j = 0; j < 4; j++) acc[m][n][j] = 0.f;

        uint32_t ro0 = (uint32_t)(mg * 32 + lm_row) * 528 + lm_kadd;
        uint32_t ro1 = (uint32_t)(mg * 32 + 16 + lm_row) * 528 + lm_kadd;

        uint2 w[4];
#pragma unroll
        for (int n = 0; n < 4; n++)
            w[n] = __ldcg((const uint2*)&g_wf2[((ng * 4 + n) * 32 + lane) * 2]);

#pragma unroll
        for (int kt = 0; kt < 16; kt++) {
            uint32_t ab = sbase + FM_H1 + (uint32_t)kt * 32;
            uint32_t a[2][4];
            ldsm_x4(a[0], ab + ro0);
            ldsm_x4(a[1], ab + ro1);
            uint2 wn[4];
            if (kt < 15) {
#pragma unroll
                for (int n = 0; n < 4; n++)
                    wn[n] = __ldcg((const uint2*)&g_wf2[(((kt + 1) * 16 + ng * 4 + n) * 32 + lane) * 2]);
            }
#pragma unroll
            for (int n = 0; n < 4; n++) {
                mma_f16(acc[0][n], a[0][0], a[0][1], a[0][2], a[0][3], w[n].x, w[n].y);
                mma_f16(acc[1][n], a[1][0], a[1][1], a[1][2], a[1][3], w[n].x, w[n].y);
            }
#pragma unroll
            for (int n = 0; n < 4; n++) w[n] = wn[n];
        }

        __syncthreads();   // all H1 reads done before H2 (aliased region) writes
#pragma unroll
        for (int mt = 0; mt < 2; mt++) {
            int rr = mg * 32 + mt * 16 + (lane >> 2);
#pragma unroll
            for (int n = 0; n < 4; n++) {
                int col0 = ng * 32 + n * 8 + (lane & 3) * 2;
                float2 bb = *(const float2*)&sb2[col0];
                float h0 = fmaxf(acc[mt][n][0] + bb.x, 0.f);
                float h1 = fmaxf(acc[mt][n][1] + bb.y, 0.f);
                *(uint32_t*)(sm + FM_H2 + rr * 272 + col0 * 2) = pack_h2(h0, h1);
                float h2 = fmaxf(acc[mt][n][2] + bb.x, 0.f);
                float h3 = fmaxf(acc[mt][n][3] + bb.y, 0.f);
                *(uint32_t*)(sm + FM_H2 + (rr + 8) * 272 + col0 * 2) = pack_h2(h2, h3);
            }
        }
    }
    __syncthreads();

    // ================= layer 3 + head (single fp16): warps 0..3 ===========
    if (wid < 4) {
        const int mg = wid;
        float acc[8][4];
#pragma unroll
        for (int n = 0; n < 8; n++)
#pragma unroll
            for (int j = 0; j < 4; j++) acc[n][j] = 0.f;

        uint32_t ro = (uint32_t)(mg * 16 + lm_row) * 272 + lm_kadd;

#pragma unroll
        for (int kt = 0; kt < 8; kt++) {
            uint32_t ab = sbase + FM_H2 + (uint32_t)kt * 32;
            uint32_t a[4];
            ldsm_x4(a, ab + ro);
#pragma unroll
            for (int n = 0; n < 8; n++) {
                uint2 w = __ldcg((const uint2*)&g_wf3[((kt * 8 + n) * 32 + lane) * 2]);
                mma_f16(acc[n], a[0], a[1], a[2], a[3], w.x, w.y);
            }
        }

        float sum0 = 0.f, sum1 = 0.f;
#pragma unroll
        for (int n = 0; n < 8; n++) {
            int col0 = n * 8 + (lane & 3) * 2;
            float2 bb = *(const float2*)&sb3[col0];
            float2 wv = *(const float2*)&swv[col0];
            sum0 += fmaxf(acc[n][0] + bb.x, 0.f) * wv.x
                  + fmaxf(acc[n][1] + bb.y, 0.f) * wv.y;
            sum1 += fmaxf(acc[n][2] + bb.x, 0.f) * wv.x
                  + fmaxf(acc[n][3] + bb.y, 0.f) * wv.y;
        }
        sum0 += __shfl_xor_sync(0xffffffffu, sum0, 1);
        sum0 += __shfl_xor_sync(0xffffffffu, sum0, 2);
        sum1 += __shfl_xor_sync(0xffffffffu, sum1, 1);
        sum1 += __shfl_xor_sync(0xffffffffu, sum1, 2);
        if ((lane & 3) == 0) {
            int row = r0 + mg * 16 + (lane >> 2);
            float bfv = sbf[0];
            out[row]     = 1.f / (1.f + __expf(-(sum0 + bfv)));
            out[row + 8] = 1.f / (1.f + __expf(-(sum1 + bfv)));
        }
    }
}

// ---------------------------------------------------------------------------
extern "C" void kernel_launch(void* const* d_in, const int* in_sizes, int n_in,
                              void* d_out, int out_size) {
    const float* x_dense = (const float*)d_in[0];
    const void*  x_sparse = d_in[1];
    const float* emb   = (const float*)d_in[2];
    const float* gamma = (const float*)d_in[3];
    const float* beta  = (const float*)d_in[4];
    const float* W1 = (const float*)d_in[5];
    const float* b1 = (const float*)d_in[6];
    const float* W2 = (const float*)d_in[7];
    const float* b2 = (const float*)d_in[8];
    const float* W3 = (const float*)d_in[9];
    const float* b3 = (const float*)d_in[10];
    const float* Wf = (const float*)d_in[11];
    const float* bf = (const float*)d_in[12];
    float* out = (float*)d_out;

    static bool s_attr_done = false;
    if (!s_attr_done) {
        cudaFuncSetAttribute(nfm_kernel,
                             cudaFuncAttributeMaxDynamicSharedMemorySize, FM_SMEM);
        s_attr_done = true;
    }

    nfm_kernel<<<B_ROWS / 64, 256, FM_SMEM>>>(x_sparse, x_dense, emb,
                                              W1, b1, W2, b2, W3, b3,
                                              Wf, bf, gamma, beta, out);
}

// round 12
// speedup vs baseline: 5.3761x; 1.0358x over previous
#include <cuda_runtime.h>
#include <cuda_fp16.h>
#include <math.h>
#include <stdint.h>

#define B_ROWS 16384
#define NSP 26
#define ND 13
#define VOCAB 100000
#define EMB_D 16
#define F0 29
#define BN_EPS 1e-5f

// ---------------------------------------------------------------------------
// Device scratch
// ---------------------------------------------------------------------------
__device__ float g_bnpart[256][64];
__device__ unsigned int g_ticket;       // never reset; cohort = ticket & ~255

// Fragment-ordered fp16x2-packed weights
__device__ uint32_t g_wf1[12288];       // layer1 3-term [s6][nt32][lane][2]
__device__ uint32_t g_wf2[16384];       // layer2 single [kt16][nt16][lane][2]
__device__ uint32_t g_wf3[4096];        // layer3 single [kt8][nt8][lane][2]

// ---------------------------------------------------------------------------
__device__ __forceinline__ void mma_f16(float* c, uint32_t a0, uint32_t a1,
                                        uint32_t a2, uint32_t a3,
                                        uint32_t b0, uint32_t b1) {
    asm volatile(
        "mma.sync.aligned.m16n8k16.row.col.f32.f16.f16.f32 "
        "{%0,%1,%2,%3}, {%4,%5,%6,%7}, {%8,%9}, {%0,%1,%2,%3};"
        : "+f"(c[0]), "+f"(c[1]), "+f"(c[2]), "+f"(c[3])
        : "r"(a0), "r"(a1), "r"(a2), "r"(a3), "r"(b0), "r"(b1));
}

__device__ __forceinline__ void ldsm_x4(uint32_t* r, uint32_t addr) {
    asm volatile("ldmatrix.sync.aligned.m8n8.x4.shared.b16 {%0,%1,%2,%3}, [%4];"
                 : "=r"(r[0]), "=r"(r[1]), "=r"(r[2]), "=r"(r[3]) : "r"(addr));
}

__device__ __forceinline__ uint32_t smem_u32(const void* p) {
    uint32_t a;
    asm("{ .reg .u64 t; cvta.to.shared.u64 t, %1; cvt.u32.u64 %0, t; }"
        : "=r"(a) : "l"(p));
    return a;
}

__device__ __forceinline__ uint32_t pack_h2(float a, float b) {
    __half2 h = __floats2half2_rn(a, b);
    return *(uint32_t*)&h;
}

__device__ __forceinline__ void split_pack_h(float h0, float h1,
                                             uint32_t& hi, uint32_t& lo) {
    __half a0 = __float2half_rn(h0);
    __half a1 = __float2half_rn(h1);
    __half c0 = __float2half_rn(h0 - __half2float(a0));
    __half c1 = __float2half_rn(h1 - __half2float(a1));
    hi = ((uint32_t)__half_as_ushort(a1) << 16) | __half_as_ushort(a0);
    lo = ((uint32_t)__half_as_ushort(c1) << 16) | __half_as_ushort(c0);
}

__device__ __forceinline__ unsigned short wpart_f16(float w, bool lo_part) {
    __half h = __float2half_rn(w);
    if (!lo_part) return __half_as_ushort(h);
    return __half_as_ushort(__float2half_rn(w - __half2float(h)));
}

// ---------------------------------------------------------------------------
// weight prep (fragment order), 32768 elements total, 128 per CTA
// ---------------------------------------------------------------------------
__device__ __forceinline__ void prep_one(int e, const float* __restrict__ W1,
                                         const float* __restrict__ W2,
                                         const float* __restrict__ W3) {
    if (e < 12288) {                       // layer1 3-term, K=32(pad), N=256
        int r = e & 1, lane = (e >> 1) & 31, nt = (e >> 6) & 31, s = e >> 11;
        bool wlo = (s == 2 || s == 3);
        int kt = s & 1;
        int k = kt * 16 + (lane & 3) * 2 + r * 8;
        int n = nt * 8 + (lane >> 2);
        float w0 = (k < F0)     ? W1[k * 256 + n]       : 0.f;
        float w1 = (k + 1 < F0) ? W1[(k + 1) * 256 + n] : 0.f;
        g_wf1[e] = ((uint32_t)wpart_f16(w1, wlo) << 16) | wpart_f16(w0, wlo);
    } else if (e < 28672) {                // layer2 single, K=256, N=128
        int e2 = e - 12288;
        int r = e2 & 1, lane = (e2 >> 1) & 31, nt = (e2 >> 6) & 15, kt = e2 >> 10;
        int k = kt * 16 + (lane & 3) * 2 + r * 8;
        int n = nt * 8 + (lane >> 2);
        float w0 = W2[k * 128 + n];
        float w1 = W2[(k + 1) * 128 + n];
        g_wf2[e2] = ((uint32_t)wpart_f16(w1, false) << 16) | wpart_f16(w0, false);
    } else {                               // layer3 single, K=128, N=64
        int e3 = e - 28672;
        int r = e3 & 1, lane = (e3 >> 1) & 31, nt = (e3 >> 6) & 7, kt = e3 >> 9;
        int k = kt * 16 + (lane & 3) * 2 + r * 8;
        int n = nt * 8 + (lane >> 2);
        float w0 = W3[k * 64 + n];
        float w1 = W3[(k + 1) * 64 + n];
        g_wf3[e3] = ((uint32_t)wpart_f16(w1, false) << 16) | wpart_f16(w0, false);
    }
}

// ---------------------------------------------------------------------------
// SMEM layout per CTA (64 rows). H2 aliases XRAW/XHI/XLO (dead after layer 1).
// ---------------------------------------------------------------------------
#define FM_H1    0            // 64*528 = 33792   (fp16, stride 528B)
#define FM_XRAW  33792        // 64*128 = 8192
#define FM_XHI   41984        // 64*80  = 5120
#define FM_XLO   47104        // 5120 -> 52224
#define FM_H2    33792        // 64*272 = 17408 -> 51200 (alias)
#define FM_BIAS  52224        // b1[256] b2[128] b3[64] wf[64] bf[1]
#define FM_SC    54288
#define FM_SH    54416
#define FM_RED   54544        // 4*64*4 = 1024
#define FM_SMEM  55568

__global__ void __launch_bounds__(256, 2)
nfm_kernel(const void* __restrict__ xsparse, const float* __restrict__ xdense,
           const float* __restrict__ emb,
           const float* __restrict__ W1, const float* __restrict__ b1,
           const float* __restrict__ W2, const float* __restrict__ b2,
           const float* __restrict__ W3, const float* __restrict__ b3,
           const float* __restrict__ Wf, const float* __restrict__ bf,
           const float* __restrict__ gamma, const float* __restrict__ beta,
           float* __restrict__ out) {
    extern __shared__ char sm[];
    const uint32_t sbase = smem_u32(sm);
    float* sb1 = (float*)(sm + FM_BIAS);
    float* sb2 = sb1 + 256;
    float* sb3 = sb2 + 128;
    float* swv = sb3 + 64;
    float* sbf = swv + 64;
    float* sSC = (float*)(sm + FM_SC);
    float* sSH = (float*)(sm + FM_SH);
    float* sred = (float*)(sm + FM_RED);
    float* swarp = (float*)(sm + FM_H1);   // reuse H1 region during gather

    __shared__ int s_is64;

    const int tid = threadIdx.x;
    const int r0 = blockIdx.x * 64;

    // ---- idx-width detect ----
    const int* xs_i32 = (const int*)xsparse;
    if (tid < 32) {
        unsigned m = __ballot_sync(0xffffffffu, xs_i32[2 * tid + 1] != 0);
        if (tid == 0) s_is64 = (m == 0);
    }
    __syncthreads();
    const bool is64 = (s_is64 != 0);

    // ---- gather + FM cross: 4 threads per row, 64 rows ----
    const long long* xs64 = (const long long*)xsparse;
    const int rloc = tid >> 2, q = tid & 3;
    const int rg = r0 + rloc;

    float s0 = 0.f, s1 = 0.f, s2 = 0.f, s3 = 0.f;
    float q0 = 0.f, q1 = 0.f, q2 = 0.f, q3 = 0.f;
#pragma unroll
    for (int f = 0; f < NSP; f++) {
        long long idx = is64 ? xs64[rg * NSP + f] : (long long)xs_i32[rg * NSP + f];
        const float4 v = *(const float4*)(emb +
            ((size_t)f * VOCAB + (size_t)idx) * EMB_D + q * 4);
        s0 += v.x; s1 += v.y; s2 += v.z; s3 += v.w;
        q0 += v.x * v.x; q1 += v.y * v.y; q2 += v.z * v.z; q3 += v.w * v.w;
    }
    float4 cr;
    cr.x = 0.5f * (s0 * s0 - q0);
    cr.y = 0.5f * (s1 * s1 - q1);
    cr.z = 0.5f * (s2 * s2 - q2);
    cr.w = 0.5f * (s3 * s3 - q3);
    int base = q * 4;
    float4 dv;
    dv.x = (base + 0 < ND) ? xdense[rg * ND + base + 0] : 0.f;
    dv.y = (base + 1 < ND) ? xdense[rg * ND + base + 1] : 0.f;
    dv.z = (base + 2 < ND) ? xdense[rg * ND + base + 2] : 0.f;
    dv.w = (base + 3 < ND) ? xdense[rg * ND + base + 3] : 0.f;

    *(float4*)(sm + FM_XRAW + rloc * 128 + q * 16) = cr;
    *(float4*)(sm + FM_XRAW + rloc * 128 + 64 + q * 16) = dv;

    // ---- BN partials (shuffle tree; swarp aliases H1 region) ----
    {
        float st[16];
        st[0] = cr.x; st[1] = cr.y; st[2] = cr.z; st[3] = cr.w;
        st[4] = cr.x * cr.x; st[5] = cr.y * cr.y; st[6] = cr.z * cr.z; st[7] = cr.w * cr.w;
        st[8] = dv.x; st[9] = dv.y; st[10] = dv.z; st[11] = dv.w;
        st[12] = dv.x * dv.x; st[13] = dv.y * dv.y; st[14] = dv.z * dv.z; st[15] = dv.w * dv.w;
#pragma unroll
        for (int j = 0; j < 16; j++) {
            st[j] += __shfl_xor_sync(0xffffffffu, st[j], 4);
            st[j] += __shfl_xor_sync(0xffffffffu, st[j], 8);
            st[j] += __shfl_xor_sync(0xffffffffu, st[j], 16);
        }
        int wd = tid >> 5, lane = tid & 31;
        if (lane < 4) {
#pragma unroll
            for (int j = 0; j < 16; j++) swarp[(wd * 4 + lane) * 16 + j] = st[j];
        }
        __syncthreads();
        if (tid < 64) {
            int qq = tid >> 4, j = tid & 15;
            float acc = 0.f;
#pragma unroll
            for (int w = 0; w < 8; w++) acc += swarp[(w * 4 + qq) * 16 + j];
            int col, slot;
            if (j < 4)       { col = qq * 4 + j;          slot = col; }
            else if (j < 8)  { col = qq * 4 + (j - 4);    slot = 32 + col; }
            else if (j < 12) { col = 16 + qq * 4 + (j - 8);  slot = col; }
            else             { col = 16 + qq * 4 + (j - 12); slot = 32 + col; }
            g_bnpart[blockIdx.x][slot] = acc;
        }
    }

    // ---- weight prep: 128 elements per CTA ----
    if (tid < 128) prep_one(blockIdx.x * 128 + tid, W1, W2, W3);

    // ---- biases (read-only inputs) ----
    if (tid < 256) sb1[tid] = b1[tid];
    if (tid < 128) sb2[tid] = b2[tid];
    else if (tid < 192) sb3[tid - 128] = b3[tid - 128];
    else swv[tid - 192] = Wf[tid - 192];
    if (tid == 0) sbf[0] = bf[0];

    // ---- device-wide ticket barrier (all 256 CTAs co-resident) ----
    __threadfence();
    __syncthreads();
    if (tid == 0) {
        unsigned t = atomicAdd(&g_ticket, 1u);
        unsigned target = (t & ~255u) + 256u;
        unsigned v;
        do {
            asm volatile("ld.acquire.gpu.global.u32 %0, [%1];"
                         : "=r"(v) : "l"(&g_ticket) : "memory");
        } while (v < target);
    }
    __syncthreads();

    const int wid = tid >> 5, lane = tid & 31;
    const int lm_m   = lane >> 3;
    const int lm_row = (lane & 7) + ((lm_m & 1) << 3);
    const uint32_t lm_kadd = (uint32_t)(lm_m >> 1) * 16;
    const int mg1 = wid & 1, ng1 = wid >> 1;

    // early prefetch: layer-1 s=0 weights (latency hidden by BN finalize + X staging)
    uint2 w1buf[8];
#pragma unroll
    for (int n = 0; n < 8; n++)
        w1buf[n] = __ldcg((const uint2*)&g_wf1[((ng1 * 8 + n) * 32 + lane) * 2]);

    // ---- BN finalize (per-CTA redundant; fixed order) ----
    {
        int slot = tid & 63, seg = tid >> 6;
        float acc = 0.f;
        for (int b = seg * 64; b < seg * 64 + 64; b++)
            acc += __ldcg(&g_bnpart[b][slot]);
        sred[seg * 64 + slot] = acc;
    }
    __syncthreads();
    if (tid < 32) {
        float s = 0.f, s2 = 0.f;
#pragma unroll
        for (int c = 0; c < 4; c++) { s += sred[c * 64 + tid]; s2 += sred[c * 64 + 32 + tid]; }
        float mean = s * (1.0f / B_ROWS);
        float var  = s2 * (1.0f / B_ROWS) - mean * mean;
        if (tid < F0) {
            float sc = gamma[tid] * rsqrtf(var + BN_EPS);
            sSC[tid] = sc;
            sSH[tid] = beta[tid] - mean * sc;
        } else { sSC[tid] = 0.f; sSH[tid] = 0.f; }
    }
    __syncthreads();

    // ---- stage X: BN + fp16 split (hi/lo) ----
    {
        float4 v0 = *(const float4*)(sm + FM_XRAW + rloc * 128 + q * 32);
        float4 v1 = *(const float4*)(sm + FM_XRAW + rloc * 128 + q * 32 + 16);
        float4 sc0 = *(const float4*)&sSC[q * 8];
        float4 sc1 = *(const float4*)&sSC[q * 8 + 4];
        float4 sh0 = *(const float4*)&sSH[q * 8];
        float4 sh1 = *(const float4*)&sSH[q * 8 + 4];
        float x0 = v0.x * sc0.x + sh0.x, x1 = v0.y * sc0.y + sh0.y;
        float x2 = v0.z * sc0.z + sh0.z, x3 = v0.w * sc0.w + sh0.w;
        float x4 = v1.x * sc1.x + sh1.x, x5 = v1.y * sc1.y + sh1.y;
        float x6 = v1.z * sc1.z + sh1.z, x7 = v1.w * sc1.w + sh1.w;
        uint4 uh, ul;
        split_pack_h(x0, x1, uh.x, ul.x);
        split_pack_h(x2, x3, uh.y, ul.y);
        split_pack_h(x4, x5, uh.z, ul.z);
        split_pack_h(x6, x7, uh.w, ul.w);
        *(uint4*)(sm + FM_XHI + rloc * 80 + q * 16) = uh;
        *(uint4*)(sm + FM_XLO + rloc * 80 + q * 16) = ul;
    }
    __syncthreads();

    // ================= layer 1 (3-term fp16): [64x32] x [32x256] =========
    {
        float acc[2][8][4];
#pragma unroll
        for (int m = 0; m < 2; m++)
#pragma unroll
            for (int n = 0; n < 8; n++)
#pragma unroll
                for (int j = 0; j < 4; j++) acc[m][n][j] = 0.f;

        uint32_t ro0 = (uint32_t)(mg1 * 32 + lm_row) * 80 + lm_kadd;
        uint32_t ro1 = (uint32_t)(mg1 * 32 + 16 + lm_row) * 80 + lm_kadd;

#pragma unroll
        for (int s = 0; s < 6; s++) {
            uint32_t ab = sbase + ((s >= 4) ? FM_XLO : FM_XHI) + (uint32_t)(s & 1) * 32;
            uint32_t a[2][4];
            ldsm_x4(a[0], ab + ro0);
            ldsm_x4(a[1], ab + ro1);
            uint2 wn[8];
            if (s < 5) {
#pragma unroll
                for (int n = 0; n < 8; n++)
                    wn[n] = __ldcg((const uint2*)&g_wf1[(((s + 1) * 32 + ng1 * 8 + n) * 32 + lane) * 2]);
            }
#pragma unroll
            for (int n = 0; n < 8; n++) {
                mma_f16(acc[0][n], a[0][0], a[0][1], a[0][2], a[0][3], w1buf[n].x, w1buf[n].y);
                mma_f16(acc[1][n], a[1][0], a[1][1], a[1][2], a[1][3], w1buf[n].x, w1buf[n].y);
            }
            if (s < 5) {
#pragma unroll
                for (int n = 0; n < 8; n++) w1buf[n] = wn[n];
            }
        }

#pragma unroll
        for (int mt = 0; mt < 2; mt++) {
            int rr = mg1 * 32 + mt * 16 + (lane >> 2);
#pragma unroll
            for (int n = 0; n < 8; n++) {
                int c0 = ng1 * 64 + n * 8 + (lane & 3) * 2;
                float2 bb = *(const float2*)&sb1[c0];
                float h0 = fmaxf(acc[mt][n][0] + bb.x, 0.f);
                float h1 = fmaxf(acc[mt][n][1] + bb.y, 0.f);
                *(uint32_t*)(sm + FM_H1 + rr * 528 + c0 * 2) = pack_h2(h0, h1);
                float h2 = fmaxf(acc[mt][n][2] + bb.x, 0.f);
                float h3 = fmaxf(acc[mt][n][3] + bb.y, 0.f);
                *(uint32_t*)(sm + FM_H1 + (rr + 8) * 528 + c0 * 2) = pack_h2(h2, h3);
            }
        }
    }
    __syncthreads();

    // ================= layer 2 (single fp16): [64x256] x [256x128] ========
    {
        const int mg = wid & 1, ng = wid >> 1;
        float acc[2][4][4];
#pragma unroll
        for (int m = 0; m < 2; m++)
#pragma unroll
            for (int n = 0; n < 4; n++)
#pragma unroll
                for (int j = 0; j < 4; j++) acc[m][n][j] = 0.f;

        uint32_t ro0 = (uint32_t)(mg * 32 + lm_row) * 528 + lm_kadd;
        uint32_t ro1 = (uint32_t)(mg * 32 + 16 + lm_row) * 528 + lm_kadd;

        // depth-4 rolling weight prefetch
        uint2 w[4][4];
#pragma unroll
        for (int p = 0; p < 4; p++)
#pragma unroll
            for (int n = 0; n < 4; n++)
                w[p][n] = __ldcg((const uint2*)&g_wf2[((p * 16 + ng * 4 + n) * 32 + lane) * 2]);

#pragma unroll
        for (int kt = 0; kt < 16; kt++) {
            uint32_t ab = sbase + FM_H1 + (uint32_t)kt * 32;
            uint32_t a[2][4];
            ldsm_x4(a[0], ab + ro0);
            ldsm_x4(a[1], ab + ro1);
            uint2 wn[4];
            if (kt < 12) {
#pragma unroll
                for (int n = 0; n < 4; n++)
                    wn[n] = __ldcg((const uint2*)&g_wf2[(((kt + 4) * 16 + ng * 4 + n) * 32 + lane) * 2]);
            }
            const int sl = kt & 3;
#pragma unroll
            for (int n = 0; n < 4; n++) {
                mma_f16(acc[0][n], a[0][0], a[0][1], a[0][2], a[0][3], w[sl][n].x, w[sl][n].y);
                mma_f16(acc[1][n], a[1][0], a[1][1], a[1][2], a[1][3], w[sl][n].x, w[sl][n].y);
            }
            if (kt < 12) {
#pragma unroll
                for (int n = 0; n < 4; n++) w[sl][n] = wn[n];
            }
        }

        __syncthreads();   // all H1 reads done before H2 (aliased region) writes
#pragma unroll
        for (int mt = 0; mt < 2; mt++) {
            int rr = mg * 32 + mt * 16 + (lane >> 2);
#pragma unroll
            for (int n = 0; n < 4; n++) {
                int col0 = ng * 32 + n * 8 + (lane & 3) * 2;
                float2 bb = *(const float2*)&sb2[col0];
                float h0 = fmaxf(acc[mt][n][0] + bb.x, 0.f);
                float h1 = fmaxf(acc[mt][n][1] + bb.y, 0.f);
                *(uint32_t*)(sm + FM_H2 + rr * 272 + col0 * 2) = pack_h2(h0, h1);
                float h2 = fmaxf(acc[mt][n][2] + bb.x, 0.f);
                float h3 = fmaxf(acc[mt][n][3] + bb.y, 0.f);
                *(uint32_t*)(sm + FM_H2 + (rr + 8) * 272 + col0 * 2) = pack_h2(h2, h3);
            }
        }
    }
    __syncthreads();

    // ================= layer 3 + head (single fp16): warps 0..3 ===========
    if (wid < 4) {
        const int mg = wid;
        float acc[8][4];
#pragma unroll
        for (int n = 0; n < 8; n++)
#pragma unroll
            for (int j = 0; j < 4; j++) acc[n][j] = 0.f;

        uint32_t ro = (uint32_t)(mg * 16 + lm_row) * 272 + lm_kadd;

        // depth-2 rolling weight prefetch
        uint2 w[2][8];
#pragma unroll
        for (int p = 0; p < 2; p++)
#pragma unroll
            for (int n = 0; n < 8; n++)
                w[p][n] = __ldcg((const uint2*)&g_wf3[((p * 8 + n) * 32 + lane) * 2]);

#pragma unroll
        for (int kt = 0; kt < 8; kt++) {
            uint32_t ab = sbase + FM_H2 + (uint32_t)kt * 32;
            uint32_t a[4];
            ldsm_x4(a, ab + ro);
            uint2 wn[8];
            if (kt < 6) {
#pragma unroll
                for (int n = 0; n < 8; n++)
                    wn[n] = __ldcg((const uint2*)&g_wf3[(((kt + 2) * 8 + n) * 32 + lane) * 2]);
            }
            const int sl = kt & 1;
#pragma unroll
            for (int n = 0; n < 8; n++)
                mma_f16(acc[n], a[0], a[1], a[2], a[3], w[sl][n].x, w[sl][n].y);
            if (kt < 6) {
#pragma unroll
                for (int n = 0; n < 8; n++) w[sl][n] = wn[n];
            }
        }

        float sum0 = 0.f, sum1 = 0.f;
#pragma unroll
        for (int n = 0; n < 8; n++) {
            int col0 = n * 8 + (lane & 3) * 2;
            float2 bb = *(const float2*)&sb3[col0];
            float2 wv = *(const float2*)&swv[col0];
            sum0 += fmaxf(acc[n][0] + bb.x, 0.f) * wv.x
                  + fmaxf(acc[n][1] + bb.y, 0.f) * wv.y;
            sum1 += fmaxf(acc[n][2] + bb.x, 0.f) * wv.x
                  + fmaxf(acc[n][3] + bb.y, 0.f) * wv.y;
        }
        sum0 += __shfl_xor_sync(0xffffffffu, sum0, 1);
        sum0 += __shfl_xor_sync(0xffffffffu, sum0, 2);
        sum1 += __shfl_xor_sync(0xffffffffu, sum1, 1);
        sum1 += __shfl_xor_sync(0xffffffffu, sum1, 2);
        if ((lane & 3) == 0) {
            int row = r0 + mg * 16 + (lane >> 2);
            float bfv = sbf[0];
            out[row]     = 1.f / (1.f + __expf(-(sum0 + bfv)));
            out[row + 8] = 1.f / (1.f + __expf(-(sum1 + bfv)));
        }
    }
}

// ---------------------------------------------------------------------------
extern "C" void kernel_launch(void* const* d_in, const int* in_sizes, int n_in,
                              void* d_out, int out_size) {
    const float* x_dense = (const float*)d_in[0];
    const void*  x_sparse = d_in[1];
    const float* emb   = (const float*)d_in[2];
    const float* gamma = (const float*)d_in[3];
    const float* beta  = (const float*)d_in[4];
    const float* W1 = (const float*)d_in[5];
    const float* b1 = (const float*)d_in[6];
    const float* W2 = (const float*)d_in[7];
    const float* b2 = (const float*)d_in[8];
    const float* W3 = (const float*)d_in[9];
    const float* b3 = (const float*)d_in[10];
    const float* Wf = (const float*)d_in[11];
    const float* bf = (const float*)d_in[12];
    float* out = (float*)d_out;

    static bool s_attr_done = false;
    if (!s_attr_done) {
        cudaFuncSetAttribute(nfm_kernel,
                             cudaFuncAttributeMaxDynamicSharedMemorySize, FM_SMEM);
        s_attr_done = true;
    }

    nfm_kernel<<<B_ROWS / 64, 256, FM_SMEM>>>(x_sparse, x_dense, emb,
                                              W1, b1, W2, b2, W3, b3,
                                              Wf, bf, gamma, beta, out);
}

// round 13
// speedup vs baseline: 5.4411x; 1.0121x over previous
#include <cuda_runtime.h>
#include <cuda_fp16.h>
#include <math.h>
#include <stdint.h>

#define B_ROWS 16384
#define NSP 26
#define ND 13
#define VOCAB 100000
#define EMB_D 16
#define F0 29
#define BN_EPS 1e-5f

// ---------------------------------------------------------------------------
// Device scratch
// ---------------------------------------------------------------------------
__device__ float g_bnpart[256][64];
__device__ unsigned int g_ticket;       // never reset; cohort = ticket & ~255

// Fragment-ordered fp16x2-packed weights
__device__ uint32_t g_wf1[12288];       // layer1 3-term [s6][nt32][lane][2]
__device__ uint32_t g_wf2[16384];       // layer2 single [kt16][nt16][lane][2]
__device__ uint32_t g_wf3[4096];        // layer3 single [kt8][nt8][lane][2]

// ---------------------------------------------------------------------------
__device__ __forceinline__ void mma_f16(float* c, uint32_t a0, uint32_t a1,
                                        uint32_t a2, uint32_t a3,
                                        uint32_t b0, uint32_t b1) {
    asm volatile(
        "mma.sync.aligned.m16n8k16.row.col.f32.f16.f16.f32 "
        "{%0,%1,%2,%3}, {%4,%5,%6,%7}, {%8,%9}, {%0,%1,%2,%3};"
        : "+f"(c[0]), "+f"(c[1]), "+f"(c[2]), "+f"(c[3])
        : "r"(a0), "r"(a1), "r"(a2), "r"(a3), "r"(b0), "r"(b1));
}

__device__ __forceinline__ void ldsm_x4(uint32_t* r, uint32_t addr) {
    asm volatile("ldmatrix.sync.aligned.m8n8.x4.shared.b16 {%0,%1,%2,%3}, [%4];"
                 : "=r"(r[0]), "=r"(r[1]), "=r"(r[2]), "=r"(r[3]) : "r"(addr));
}

__device__ __forceinline__ uint32_t smem_u32(const void* p) {
    uint32_t a;
    asm("{ .reg .u64 t; cvta.to.shared.u64 t, %1; cvt.u32.u64 %0, t; }"
        : "=r"(a) : "l"(p));
    return a;
}

__device__ __forceinline__ uint32_t pack_h2(float a, float b) {
    __half2 h = __floats2half2_rn(a, b);
    return *(uint32_t*)&h;
}

__device__ __forceinline__ void split_pack_h(float h0, float h1,
                                             uint32_t& hi, uint32_t& lo) {
    __half a0 = __float2half_rn(h0);
    __half a1 = __float2half_rn(h1);
    __half c0 = __float2half_rn(h0 - __half2float(a0));
    __half c1 = __float2half_rn(h1 - __half2float(a1));
    hi = ((uint32_t)__half_as_ushort(a1) << 16) | __half_as_ushort(a0);
    lo = ((uint32_t)__half_as_ushort(c1) << 16) | __half_as_ushort(c0);
}

__device__ __forceinline__ unsigned short wpart_f16(float w, bool lo_part) {
    __half h = __float2half_rn(w);
    if (!lo_part) return __half_as_ushort(h);
    return __half_as_ushort(__float2half_rn(w - __half2float(h)));
}

// ---------------------------------------------------------------------------
// weight prep (fragment order), 32768 elements total, 128 per CTA
// ---------------------------------------------------------------------------
__device__ __forceinline__ void prep_one(int e, const float* __restrict__ W1,
                                         const float* __restrict__ W2,
                                         const float* __restrict__ W3) {
    if (e < 12288) {                       // layer1 3-term, K=32(pad), N=256
        int r = e & 1, lane = (e >> 1) & 31, nt = (e >> 6) & 31, s = e >> 11;
        bool wlo = (s == 2 || s == 3);
        int kt = s & 1;
        int k = kt * 16 + (lane & 3) * 2 + r * 8;
        int n = nt * 8 + (lane >> 2);
        float w0 = (k < F0)     ? W1[k * 256 + n]       : 0.f;
        float w1 = (k + 1 < F0) ? W1[(k + 1) * 256 + n] : 0.f;
        g_wf1[e] = ((uint32_t)wpart_f16(w1, wlo) << 16) | wpart_f16(w0, wlo);
    } else if (e < 28672) {                // layer2 single, K=256, N=128
        int e2 = e - 12288;
        int r = e2 & 1, lane = (e2 >> 1) & 31, nt = (e2 >> 6) & 15, kt = e2 >> 10;
        int k = kt * 16 + (lane & 3) * 2 + r * 8;
        int n = nt * 8 + (lane >> 2);
        float w0 = W2[k * 128 + n];
        float w1 = W2[(k + 1) * 128 + n];
        g_wf2[e2] = ((uint32_t)wpart_f16(w1, false) << 16) | wpart_f16(w0, false);
    } else {                               // layer3 single, K=128, N=64
        int e3 = e - 28672;
        int r = e3 & 1, lane = (e3 >> 1) & 31, nt = (e3 >> 6) & 7, kt = e3 >> 9;
        int k = kt * 16 + (lane & 3) * 2 + r * 8;
        int n = nt * 8 + (lane >> 2);
        float w0 = W3[k * 64 + n];
        float w1 = W3[(k + 1) * 64 + n];
        g_wf3[e3] = ((uint32_t)wpart_f16(w1, false) << 16) | wpart_f16(w0, false);
    }
}

// ---------------------------------------------------------------------------
// SMEM layout per CTA (64 rows). H2 aliases XRAW/XHI/XLO (dead after layer 1).
// ---------------------------------------------------------------------------
#define FM_H1    0            // 64*528 = 33792   (fp16, stride 528B)
#define FM_XRAW  33792        // 64*128 = 8192
#define FM_XHI   41984        // 64*80  = 5120
#define FM_XLO   47104        // 5120 -> 52224
#define FM_H2    33792        // 64*272 = 17408 -> 51200 (alias)
#define FM_BIAS  52224        // b1[256] b2[128] b3[64] wf[64] bf[1]
#define FM_SC    54288
#define FM_SH    54416
#define FM_RED   54544        // 4*64*4 = 1024
#define FM_SMEM  55568

__global__ void __launch_bounds__(256, 2)
nfm_kernel(const void* __restrict__ xsparse, const float* __restrict__ xdense,
           const float* __restrict__ emb,
           const float* __restrict__ W1, const float* __restrict__ b1,
           const float* __restrict__ W2, const float* __restrict__ b2,
           const float* __restrict__ W3, const float* __restrict__ b3,
           const float* __restrict__ Wf, const float* __restrict__ bf,
           const float* __restrict__ gamma, const float* __restrict__ beta,
           float* __restrict__ out) {
    extern __shared__ char sm[];
    const uint32_t sbase = smem_u32(sm);
    float* sb1 = (float*)(sm + FM_BIAS);
    float* sb2 = sb1 + 256;
    float* sb3 = sb2 + 128;
    float* swv = sb3 + 64;
    float* sbf = swv + 64;
    float* sSC = (float*)(sm + FM_SC);
    float* sSH = (float*)(sm + FM_SH);
    float* sred = (float*)(sm + FM_RED);
    float* swarp = (float*)(sm + FM_H1);   // reuse H1 region during gather

    __shared__ int s_is64;

    const int tid = threadIdx.x;
    const int r0 = blockIdx.x * 64;

    // ---- idx-width detect ----
    const int* xs_i32 = (const int*)xsparse;
    if (tid < 32) {
        unsigned m = __ballot_sync(0xffffffffu, xs_i32[2 * tid + 1] != 0);
        if (tid == 0) s_is64 = (m == 0);
    }
    __syncthreads();
    const bool is64 = (s_is64 != 0);

    // ---- gather + FM cross: 4 threads per row, explicit MLP=13 batching ----
    const long long* xs64 = (const long long*)xsparse;
    const int rloc = tid >> 2, q = tid & 3;
    const int rg = r0 + rloc;

    int idxs[NSP];
    if (is64) {
#pragma unroll
        for (int f = 0; f < NSP; f++) idxs[f] = (int)xs64[rg * NSP + f];
    } else {
#pragma unroll
        for (int f = 0; f < NSP; f++) idxs[f] = xs_i32[rg * NSP + f];
    }

    float s0 = 0.f, s1 = 0.f, s2 = 0.f, s3 = 0.f;
    float q0 = 0.f, q1 = 0.f, q2 = 0.f, q3 = 0.f;

#pragma unroll
    for (int half = 0; half < 2; half++) {
        float4 v[13];
#pragma unroll
        for (int j = 0; j < 13; j++) {
            int f = half * 13 + j;
            v[j] = *(const float4*)(emb +
                ((size_t)f * VOCAB + (size_t)idxs[f]) * EMB_D + q * 4);
        }
#pragma unroll
        for (int j = 0; j < 13; j++) {
            s0 += v[j].x; s1 += v[j].y; s2 += v[j].z; s3 += v[j].w;
            q0 += v[j].x * v[j].x; q1 += v[j].y * v[j].y;
            q2 += v[j].z * v[j].z; q3 += v[j].w * v[j].w;
        }
    }

    float4 cr;
    cr.x = 0.5f * (s0 * s0 - q0);
    cr.y = 0.5f * (s1 * s1 - q1);
    cr.z = 0.5f * (s2 * s2 - q2);
    cr.w = 0.5f * (s3 * s3 - q3);
    int base = q * 4;
    float4 dv;
    dv.x = (base + 0 < ND) ? xdense[rg * ND + base + 0] : 0.f;
    dv.y = (base + 1 < ND) ? xdense[rg * ND + base + 1] : 0.f;
    dv.z = (base + 2 < ND) ? xdense[rg * ND + base + 2] : 0.f;
    dv.w = (base + 3 < ND) ? xdense[rg * ND + base + 3] : 0.f;

    *(float4*)(sm + FM_XRAW + rloc * 128 + q * 16) = cr;
    *(float4*)(sm + FM_XRAW + rloc * 128 + 64 + q * 16) = dv;

    // ---- BN partials (shuffle tree; swarp aliases H1 region) ----
    {
        float st[16];
        st[0] = cr.x; st[1] = cr.y; st[2] = cr.z; st[3] = cr.w;
        st[4] = cr.x * cr.x; st[5] = cr.y * cr.y; st[6] = cr.z * cr.z; st[7] = cr.w * cr.w;
        st[8] = dv.x; st[9] = dv.y; st[10] = dv.z; st[11] = dv.w;
        st[12] = dv.x * dv.x; st[13] = dv.y * dv.y; st[14] = dv.z * dv.z; st[15] = dv.w * dv.w;
#pragma unroll
        for (int j = 0; j < 16; j++) {
            st[j] += __shfl_xor_sync(0xffffffffu, st[j], 4);
            st[j] += __shfl_xor_sync(0xffffffffu, st[j], 8);
            st[j] += __shfl_xor_sync(0xffffffffu, st[j], 16);
        }
        int wd = tid >> 5, lane = tid & 31;
        if (lane < 4) {
#pragma unroll
            for (int j = 0; j < 16; j++) swarp[(wd * 4 + lane) * 16 + j] = st[j];
        }
        __syncthreads();
        if (tid < 64) {
            int qq = tid >> 4, j = tid & 15;
            float acc = 0.f;
#pragma unroll
            for (int w = 0; w < 8; w++) acc += swarp[(w * 4 + qq) * 16 + j];
            int col, slot;
            if (j < 4)       { col = qq * 4 + j;          slot = col; }
            else if (j < 8)  { col = qq * 4 + (j - 4);    slot = 32 + col; }
            else if (j < 12) { col = 16 + qq * 4 + (j - 8);  slot = col; }
            else             { col = 16 + qq * 4 + (j - 12); slot = 32 + col; }
            g_bnpart[blockIdx.x][slot] = acc;
        }
    }

    // ---- weight prep: 128 elements per CTA ----
    if (tid < 128) prep_one(blockIdx.x * 128 + tid, W1, W2, W3);

    // ---- biases (read-only inputs) ----
    if (tid < 256) sb1[tid] = b1[tid];
    if (tid < 128) sb2[tid] = b2[tid];
    else if (tid < 192) sb3[tid - 128] = b3[tid - 128];
    else swv[tid - 192] = Wf[tid - 192];
    if (tid == 0) sbf[0] = bf[0];

    // ---- device-wide ticket barrier (all 256 CTAs co-resident) ----
    __threadfence();
    __syncthreads();
    if (tid == 0) {
        unsigned t = atomicAdd(&g_ticket, 1u);
        unsigned target = (t & ~255u) + 256u;
        unsigned v;
        do {
            asm volatile("ld.acquire.gpu.global.u32 %0, [%1];"
                         : "=r"(v) : "l"(&g_ticket) : "memory");
        } while (v < target);
    }
    __syncthreads();

    const int wid = tid >> 5, lane = tid & 31;
    const int lm_m   = lane >> 3;
    const int lm_row = (lane & 7) + ((lm_m & 1) << 3);
    const uint32_t lm_kadd = (uint32_t)(lm_m >> 1) * 16;
    const int mg1 = wid & 1, ng1 = wid >> 1;

    // early prefetch: layer-1 s=0 weights (hidden by BN finalize + X staging)
    uint2 w1buf[8];
#pragma unroll
    for (int n = 0; n < 8; n++)
        w1buf[n] = __ldcg((const uint2*)&g_wf1[((ng1 * 8 + n) * 32 + lane) * 2]);

    // ---- BN finalize (per-CTA redundant; fixed order) ----
    {
        int slot = tid & 63, seg = tid >> 6;
        float acc = 0.f;
        for (int b = seg * 64; b < seg * 64 + 64; b++)
            acc += __ldcg(&g_bnpart[b][slot]);
        sred[seg * 64 + slot] = acc;
    }
    __syncthreads();
    if (tid < 32) {
        float s = 0.f, s2 = 0.f;
#pragma unroll
        for (int c = 0; c < 4; c++) { s += sred[c * 64 + tid]; s2 += sred[c * 64 + 32 + tid]; }
        float mean = s * (1.0f / B_ROWS);
        float var  = s2 * (1.0f / B_ROWS) - mean * mean;
        if (tid < F0) {
            float sc = gamma[tid] * rsqrtf(var + BN_EPS);
            sSC[tid] = sc;
            sSH[tid] = beta[tid] - mean * sc;
        } else { sSC[tid] = 0.f; sSH[tid] = 0.f; }
    }
    __syncthreads();

    // ---- stage X: BN + fp16 split (hi/lo) ----
    {
        float4 v0 = *(const float4*)(sm + FM_XRAW + rloc * 128 + q * 32);
        float4 v1 = *(const float4*)(sm + FM_XRAW + rloc * 128 + q * 32 + 16);
        float4 sc0 = *(const float4*)&sSC[q * 8];
        float4 sc1 = *(const float4*)&sSC[q * 8 + 4];
        float4 sh0 = *(const float4*)&sSH[q * 8];
        float4 sh1 = *(const float4*)&sSH[q * 8 + 4];
        float x0 = v0.x * sc0.x + sh0.x, x1 = v0.y * sc0.y + sh0.y;
        float x2 = v0.z * sc0.z + sh0.z, x3 = v0.w * sc0.w + sh0.w;
        float x4 = v1.x * sc1.x + sh1.x, x5 = v1.y * sc1.y + sh1.y;
        float x6 = v1.z * sc1.z + sh1.z, x7 = v1.w * sc1.w + sh1.w;
        uint4 uh, ul;
        split_pack_h(x0, x1, uh.x, ul.x);
        split_pack_h(x2, x3, uh.y, ul.y);
        split_pack_h(x4, x5, uh.z, ul.z);
        split_pack_h(x6, x7, uh.w, ul.w);
        *(uint4*)(sm + FM_XHI + rloc * 80 + q * 16) = uh;
        *(uint4*)(sm + FM_XLO + rloc * 80 + q * 16) = ul;
    }
    __syncthreads();

    // ================= layer 1 (3-term fp16): [64x32] x [32x256] =========
    {
        float acc[2][8][4];
#pragma unroll
        for (int m = 0; m < 2; m++)
#pragma unroll
            for (int n = 0; n < 8; n++)
#pragma unroll
                for (int j = 0; j < 4; j++) acc[m][n][j] = 0.f;

        uint32_t ro0 = (uint32_t)(mg1 * 32 + lm_row) * 80 + lm_kadd;
        uint32_t ro1 = (uint32_t)(mg1 * 32 + 16 + lm_row) * 80 + lm_kadd;

#pragma unroll
        for (int s = 0; s < 6; s++) {
            uint32_t ab = sbase + ((s >= 4) ? FM_XLO : FM_XHI) + (uint32_t)(s & 1) * 32;
            uint32_t a[2][4];
            ldsm_x4(a[0], ab + ro0);
            ldsm_x4(a[1], ab + ro1);
            uint2 wn[8];
            if (s < 5) {
#pragma unroll
                for (int n = 0; n < 8; n++)
                    wn[n] = __ldcg((const uint2*)&g_wf1[(((s + 1) * 32 + ng1 * 8 + n) * 32 + lane) * 2]);
            }
#pragma unroll
            for (int n = 0; n < 8; n++) {
                mma_f16(acc[0][n], a[0][0], a[0][1], a[0][2], a[0][3], w1buf[n].x, w1buf[n].y);
                mma_f16(acc[1][n], a[1][0], a[1][1], a[1][2], a[1][3], w1buf[n].x, w1buf[n].y);
            }
            if (s < 5) {
#pragma unroll
                for (int n = 0; n < 8; n++) w1buf[n] = wn[n];
            }
        }

#pragma unroll
        for (int mt = 0; mt < 2; mt++) {
            int rr = mg1 * 32 + mt * 16 + (lane >> 2);
#pragma unroll
            for (int n = 0; n < 8; n++) {
                int c0 = ng1 * 64 + n * 8 + (lane & 3) * 2;
                float2 bb = *(const float2*)&sb1[c0];
                float h0 = fmaxf(acc[mt][n][0] + bb.x, 0.f);
                float h1 = fmaxf(acc[mt][n][1] + bb.y, 0.f);
                *(uint32_t*)(sm + FM_H1 + rr * 528 + c0 * 2) = pack_h2(h0, h1);
                float h2 = fmaxf(acc[mt][n][2] + bb.x, 0.f);
                float h3 = fmaxf(acc[mt][n][3] + bb.y, 0.f);
                *(uint32_t*)(sm + FM_H1 + (rr + 8) * 528 + c0 * 2) = pack_h2(h2, h3);
            }
        }
    }
    __syncthreads();

    // ================= layer 2 (single fp16): [64x256] x [256x128] ========
    {
        const int mg = wid & 1, ng = wid >> 1;
        float acc[2][4][4];
#pragma unroll
        for (int m = 0; m < 2; m++)
#pragma unroll
            for (int n = 0; n < 4; n++)
#pragma unroll
                for (int j = 0; j < 4; j++) acc[m][n][j] = 0.f;

        uint32_t ro0 = (uint32_t)(mg * 32 + lm_row) * 528 + lm_kadd;
        uint32_t ro1 = (uint32_t)(mg * 32 + 16 + lm_row) * 528 + lm_kadd;

        // depth-4 rolling weight prefetch
        uint2 w[4][4];
#pragma unroll
        for (int p = 0; p < 4; p++)
#pragma unroll
            for (int n = 0; n < 4; n++)
                w[p][n] = __ldcg((const uint2*)&g_wf2[((p * 16 + ng * 4 + n) * 32 + lane) * 2]);

#pragma unroll
        for (int kt = 0; kt < 16; kt++) {
            uint32_t ab = sbase + FM_H1 + (uint32_t)kt * 32;
            uint32_t a[2][4];
            ldsm_x4(a[0], ab + ro0);
            ldsm_x4(a[1], ab + ro1);
            uint2 wn[4];
            if (kt < 12) {
#pragma unroll
                for (int n = 0; n < 4; n++)
                    wn[n] = __ldcg((const uint2*)&g_wf2[(((kt + 4) * 16 + ng * 4 + n) * 32 + lane) * 2]);
            }
            const int sl = kt & 3;
#pragma unroll
            for (int n = 0; n < 4; n++) {
                mma_f16(acc[0][n], a[0][0], a[0][1], a[0][2], a[0][3], w[sl][n].x, w[sl][n].y);
                mma_f16(acc[1][n], a[1][0], a[1][1], a[1][2], a[1][3], w[sl][n].x, w[sl][n].y);
            }
            if (kt < 12) {
#pragma unroll
                for (int n = 0; n < 4; n++) w[sl][n] = wn[n];
            }
        }

        __syncthreads();   // all H1 reads done before H2 (aliased region) writes
#pragma unroll
        for (int mt = 0; mt < 2; mt++) {
            int rr = mg * 32 + mt * 16 + (lane >> 2);
#pragma unroll
            for (int n = 0; n < 4; n++) {
                int col0 = ng * 32 + n * 8 + (lane & 3) * 2;
                float2 bb = *(const float2*)&sb2[col0];
                float h0 = fmaxf(acc[mt][n][0] + bb.x, 0.f);
                float h1 = fmaxf(acc[mt][n][1] + bb.y, 0.f);
                *(uint32_t*)(sm + FM_H2 + rr * 272 + col0 * 2) = pack_h2(h0, h1);
                float h2 = fmaxf(acc[mt][n][2] + bb.x, 0.f);
                float h3 = fmaxf(acc[mt][n][3] + bb.y, 0.f);
                *(uint32_t*)(sm + FM_H2 + (rr + 8) * 272 + col0 * 2) = pack_h2(h2, h3);
            }
        }
    }
    __syncthreads();

    // ================= layer 3 + head (single fp16): warps 0..3 ===========
    if (wid < 4) {
        const int mg = wid;
        float acc[8][4];
#pragma unroll
        for (int n = 0; n < 8; n++)
#pragma unroll
            for (int j = 0; j < 4; j++) acc[n][j] = 0.f;

        uint32_t ro = (uint32_t)(mg * 16 + lm_row) * 272 + lm_kadd;

        // depth-2 rolling weight prefetch
        uint2 w[2][8];
#pragma unroll
        for (int p = 0; p < 2; p++)
#pragma unroll
            for (int n = 0; n < 8; n++)
                w[p][n] = __ldcg((const uint2*)&g_wf3[((p * 8 + n) * 32 + lane) * 2]);

#pragma unroll
        for (int kt = 0; kt < 8; kt++) {
            uint32_t ab = sbase + FM_H2 + (uint32_t)kt * 32;
            uint32_t a[4];
            ldsm_x4(a, ab + ro);
            uint2 wn[8];
            if (kt < 6) {
#pragma unroll
                for (int n = 0; n < 8; n++)
                    wn[n] = __ldcg((const uint2*)&g_wf3[(((kt + 2) * 8 + n) * 32 + lane) * 2]);
            }
            const int sl = kt & 1;
#pragma unroll
            for (int n = 0; n < 8; n++)
                mma_f16(acc[n], a[0], a[1], a[2], a[3], w[sl][n].x, w[sl][n].y);
            if (kt < 6) {
#pragma unroll
                for (int n = 0; n < 8; n++) w[sl][n] = wn[n];
            }
        }

        float sum0 = 0.f, sum1 = 0.f;
#pragma unroll
        for (int n = 0; n < 8; n++) {
            int col0 = n * 8 + (lane & 3) * 2;
            float2 bb = *(const float2*)&sb3[col0];
            float2 wv = *(const float2*)&swv[col0];
            sum0 += fmaxf(acc[n][0] + bb.x, 0.f) * wv.x
                  + fmaxf(acc[n][1] + bb.y, 0.f) * wv.y;
            sum1 += fmaxf(acc[n][2] + bb.x, 0.f) * wv.x
                  + fmaxf(acc[n][3] + bb.y, 0.f) * wv.y;
        }
        sum0 += __shfl_xor_sync(0xffffffffu, sum0, 1);
        sum0 += __shfl_xor_sync(0xffffffffu, sum0, 2);
        sum1 += __shfl_xor_sync(0xffffffffu, sum1, 1);
        sum1 += __shfl_xor_sync(0xffffffffu, sum1, 2);
        if ((lane & 3) == 0) {
            int row = r0 + mg * 16 + (lane >> 2);
            float bfv = sbf[0];
            out[row]     = 1.f / (1.f + __expf(-(sum0 + bfv)));
            out[row + 8] = 1.f / (1.f + __expf(-(sum1 + bfv)));
        }
    }
}

// ---------------------------------------------------------------------------
extern "C" void kernel_launch(void* const* d_in, const int* in_sizes, int n_in,
                              void* d_out, int out_size) {
    const float* x_dense = (const float*)d_in[0];
    const void*  x_sparse = d_in[1];
    const float* emb   = (const float*)d_in[2];
    const float* gamma = (const float*)d_in[3];
    const float* beta  = (const float*)d_in[4];
    const float* W1 = (const float*)d_in[5];
    const float* b1 = (const float*)d_in[6];
    const float* W2 = (const float*)d_in[7];
    const float* b2 = (const float*)d_in[8];
    const float* W3 = (const float*)d_in[9];
    const float* b3 = (const float*)d_in[10];
    const float* Wf = (const float*)d_in[11];
    const float* bf = (const float*)d_in[12];
    float* out = (float*)d_out;

    static bool s_attr_done = false;
    if (!s_attr_done) {
        cudaFuncSetAttribute(nfm_kernel,
                             cudaFuncAttributeMaxDynamicSharedMemorySize, FM_SMEM);
        s_attr_done = true;
    }

    nfm_kernel<<<B_ROWS / 64, 256, FM_SMEM>>>(x_sparse, x_dense, emb,
                                              W1, b1, W2, b2, W3, b3,
                                              Wf, bf, gamma, beta, out);
}